// round 1
// baseline (speedup 1.0000x reference)
#include <cuda_runtime.h>
#include <cuda_bf16.h>
#include <math_constants.h>

// Problem constants (fixed by the reference)
#define D_MODEL   2048
#define NUM_HEADS 16
#define SEQ_LEN   2048
#define BATCH     2
#define D_HEAD    128   // D_MODEL / NUM_HEADS

// ---------------------------------------------------------------------------
// Scratch (static __device__ arrays — no allocation allowed)
// ---------------------------------------------------------------------------
__device__ float g_Q[BATCH * SEQ_LEN * D_MODEL];
__device__ float g_K[BATCH * SEQ_LEN * D_MODEL];
__device__ float g_V[BATCH * SEQ_LEN * D_MODEL];
__device__ float g_CTX[BATCH * SEQ_LEN * D_MODEL];

// ---------------------------------------------------------------------------
// SGEMM: C[M,N] = A[M,K] @ B[K,N], row-major fp32.
// 64x64 tile, BK=16, 256 threads, 4x4 per-thread micro-tile.
// All dims here are multiples of 64/16, so no bounds checks.
// ---------------------------------------------------------------------------
__global__ __launch_bounds__(256) void sgemm64(
    const float* __restrict__ A, const float* __restrict__ B,
    float* __restrict__ C, int M, int N, int K)
{
    __shared__ float As[16][64];   // transposed A tile: As[k][m]
    __shared__ float Bs[16][64];   // Bs[k][n]

    const int tid = threadIdx.x;
    const int tx = tid & 15;       // 0..15 (N direction)
    const int ty = tid >> 4;       // 0..15 (M direction)
    const int row0 = blockIdx.y * 64;
    const int col0 = blockIdx.x * 64;

    float acc[4][4];
#pragma unroll
    for (int i = 0; i < 4; i++)
#pragma unroll
        for (int j = 0; j < 4; j++) acc[i][j] = 0.0f;

    // Per-thread load coordinates (constant across k-tiles)
    const int a_lin = tid * 4;
    const int a_r = a_lin >> 4;    // 0..63
    const int a_c = a_lin & 15;    // 0,4,8,12
    const int b_lin = tid * 4;
    const int b_r = b_lin >> 6;    // 0..15
    const int b_c = b_lin & 63;

    for (int k0 = 0; k0 < K; k0 += 16) {
        // Load A tile (64x16) transposed into As
        {
            float4 a = *(const float4*)(A + (size_t)(row0 + a_r) * K + k0 + a_c);
            As[a_c + 0][a_r] = a.x;
            As[a_c + 1][a_r] = a.y;
            As[a_c + 2][a_r] = a.z;
            As[a_c + 3][a_r] = a.w;
        }
        // Load B tile (16x64)
        {
            *(float4*)(&Bs[b_r][b_c]) =
                *(const float4*)(B + (size_t)(k0 + b_r) * N + col0 + b_c);
        }
        __syncthreads();

#pragma unroll
        for (int k = 0; k < 16; k++) {
            float4 a = *(const float4*)(&As[k][ty * 4]);
            float4 b = *(const float4*)(&Bs[k][tx * 4]);
            acc[0][0] += a.x * b.x; acc[0][1] += a.x * b.y; acc[0][2] += a.x * b.z; acc[0][3] += a.x * b.w;
            acc[1][0] += a.y * b.x; acc[1][1] += a.y * b.y; acc[1][2] += a.y * b.z; acc[1][3] += a.y * b.w;
            acc[2][0] += a.z * b.x; acc[2][1] += a.z * b.y; acc[2][2] += a.z * b.z; acc[2][3] += a.z * b.w;
            acc[3][0] += a.w * b.x; acc[3][1] += a.w * b.y; acc[3][2] += a.w * b.z; acc[3][3] += a.w * b.w;
        }
        __syncthreads();
    }

#pragma unroll
    for (int i = 0; i < 4; i++) {
        float4 v = make_float4(acc[i][0], acc[i][1], acc[i][2], acc[i][3]);
        *(float4*)(C + (size_t)(row0 + ty * 4 + i) * N + col0 + tx * 4) = v;
    }
}

// ---------------------------------------------------------------------------
// Flash-style causal attention.
// Grid: (SEQ/64 q-blocks, NUM_HEADS, BATCH), 256 threads.
// Each thread owns 1 query row (r = tid/4) and a 32-wide slice of d_head
// (seg = tid%4). K and V blocks (64 x 128) share one smem buffer.
// ---------------------------------------------------------------------------
#define BM 64
#define BN 64
#define KV_PAD 4   // pad row to 132 floats (16B-aligned, bank-staggered)

__global__ __launch_bounds__(256, 1) void flash_attn(
    const float* __restrict__ Q, const float* __restrict__ K,
    const float* __restrict__ V, float* __restrict__ CTX)
{
    __shared__ float KVs[BN][D_HEAD + KV_PAD];

    const int tid = threadIdx.x;
    const int r   = tid >> 2;        // query row within block, 0..63
    const int seg = tid & 3;         // d_head slice, 0..3
    const int d0  = seg * 32;

    const int qb = blockIdx.x;       // query block
    const int h  = blockIdx.y;       // head
    const int b  = blockIdx.z;       // batch

    const int qg = qb * BM + r;      // global query index
    const size_t row_base = ((size_t)b * SEQ_LEN + qg) * D_MODEL + h * D_HEAD;

    const float inv_sqrt_dh = 0.08838834764831845f; // 1/sqrt(128)

    // Load this thread's Q slice (32 floats)
    float qreg[32];
#pragma unroll
    for (int i = 0; i < 8; i++) {
        float4 v = *(const float4*)(Q + row_base + d0 + i * 4);
        qreg[i * 4 + 0] = v.x; qreg[i * 4 + 1] = v.y;
        qreg[i * 4 + 2] = v.z; qreg[i * 4 + 3] = v.w;
    }

    float accv[32];
#pragma unroll
    for (int i = 0; i < 32; i++) accv[i] = 0.0f;
    float m = -CUDART_INF_F;
    float l = 0.0f;

    for (int kb = 0; kb <= qb; kb++) {
        const size_t kv_base = ((size_t)b * SEQ_LEN + kb * BN) * D_MODEL + h * D_HEAD;

        // ---- load K block into smem (each thread: 8 float4) ----
#pragma unroll
        for (int i = 0; i < 8; i++) {
            int lin = tid + i * 256;          // float4 index, 0..2047
            int row = lin >> 5;               // 0..63
            int c4  = lin & 31;               // 0..31
            float4 v = *(const float4*)(K + kv_base + (size_t)row * D_MODEL + c4 * 4);
            *(float4*)(&KVs[row][c4 * 4]) = v;
        }
        __syncthreads();

        // ---- scores: s[c] = dot(Q[r], K[c]) over this thread's 32-dim slice ----
        float s[BN];
#pragma unroll
        for (int c = 0; c < BN; c++) {
            float acc = 0.0f;
#pragma unroll
            for (int i = 0; i < 8; i++) {
                float4 kv = *(const float4*)(&KVs[c][d0 + i * 4]);
                acc += qreg[i * 4 + 0] * kv.x;
                acc += qreg[i * 4 + 1] * kv.y;
                acc += qreg[i * 4 + 2] * kv.z;
                acc += qreg[i * 4 + 3] * kv.w;
            }
            s[c] = acc;
        }
        // reduce across the 4 threads of the quad (lanes differ in bits 0,1)
#pragma unroll
        for (int c = 0; c < BN; c++) {
            s[c] += __shfl_xor_sync(0xffffffffu, s[c], 1);
            s[c] += __shfl_xor_sync(0xffffffffu, s[c], 2);
            s[c] *= inv_sqrt_dh;
            int kcg = kb * BN + c;
            if (kcg > qg) s[c] = -CUDART_INF_F;
        }

        // ---- online softmax update ----
        float m_new = m;
#pragma unroll
        for (int c = 0; c < BN; c++) m_new = fmaxf(m_new, s[c]);

        float corr = __expf(m - m_new);
        l *= corr;
#pragma unroll
        for (int i = 0; i < 32; i++) accv[i] *= corr;

        float psum = 0.0f;
#pragma unroll
        for (int c = 0; c < BN; c++) {
            float p = __expf(s[c] - m_new);
            s[c] = p;               // reuse s[] as probabilities
            psum += p;
        }
        l += psum;
        m = m_new;

        __syncthreads();  // done reading K from smem

        // ---- load V block into the same smem buffer ----
#pragma unroll
        for (int i = 0; i < 8; i++) {
            int lin = tid + i * 256;
            int row = lin >> 5;
            int c4  = lin & 31;
            float4 v = *(const float4*)(V + kv_base + (size_t)row * D_MODEL + c4 * 4);
            *(float4*)(&KVs[row][c4 * 4]) = v;
        }
        __syncthreads();

        // ---- accumulate ctx += P @ V (this thread's 32-dim slice) ----
#pragma unroll
        for (int c = 0; c < BN; c++) {
            float p = s[c];
#pragma unroll
            for (int i = 0; i < 8; i++) {
                float4 vv = *(const float4*)(&KVs[c][d0 + i * 4]);
                accv[i * 4 + 0] += p * vv.x;
                accv[i * 4 + 1] += p * vv.y;
                accv[i * 4 + 2] += p * vv.z;
                accv[i * 4 + 3] += p * vv.w;
            }
        }
        __syncthreads();  // before next K load overwrites smem
    }

    // ---- normalize and write ----
    float inv_l = 1.0f / l;
#pragma unroll
    for (int i = 0; i < 8; i++) {
        float4 v = make_float4(accv[i * 4 + 0] * inv_l, accv[i * 4 + 1] * inv_l,
                               accv[i * 4 + 2] * inv_l, accv[i * 4 + 3] * inv_l);
        *(float4*)(CTX + row_base + d0 + i * 4) = v;
    }
}

// ---------------------------------------------------------------------------
// Launch
// ---------------------------------------------------------------------------
extern "C" void kernel_launch(void* const* d_in, const int* in_sizes, int n_in,
                              void* d_out, int out_size)
{
    const float* x     = (const float*)d_in[0];
    const float* q_w   = (const float*)d_in[1];
    const float* k_w   = (const float*)d_in[2];
    const float* v_w   = (const float*)d_in[3];
    const float* w_out = (const float*)d_in[4];
    float* out = (float*)d_out;

    float *Q, *K, *V, *CTX;
    cudaGetSymbolAddress((void**)&Q,   g_Q);
    cudaGetSymbolAddress((void**)&K,   g_K);
    cudaGetSymbolAddress((void**)&V,   g_V);
    cudaGetSymbolAddress((void**)&CTX, g_CTX);

    const int M = BATCH * SEQ_LEN;      // 4096
    const int N = D_MODEL;              // 2048
    const int Kd = D_MODEL;             // 2048

    dim3 gemm_grid(N / 64, M / 64);     // (32, 64)
    sgemm64<<<gemm_grid, 256>>>(x, q_w, Q, M, N, Kd);
    sgemm64<<<gemm_grid, 256>>>(x, k_w, K, M, N, Kd);
    sgemm64<<<gemm_grid, 256>>>(x, v_w, V, M, N, Kd);

    dim3 attn_grid(SEQ_LEN / BM, NUM_HEADS, BATCH);  // (32, 16, 2)
    flash_attn<<<attn_grid, 256>>>(Q, K, V, CTX);

    sgemm64<<<gemm_grid, 256>>>(CTX, w_out, out, M, N, Kd);
}

// round 3
// speedup vs baseline: 1.1418x; 1.1418x over previous
#include <cuda_runtime.h>
#include <cuda_bf16.h>
#include <math_constants.h>
#include <cstdint>

// Problem constants (fixed by the reference)
#define D_MODEL   2048
#define NUM_HEADS 16
#define SEQ_LEN   2048
#define BATCH     2
#define D_HEAD    128
#define MROWS     (BATCH * SEQ_LEN)     // 4096
#define KP        (3 * D_MODEL)         // 6144  (split-tripled K)

// ---------------------------------------------------------------------------
// Scratch (static __device__ arrays — no allocation allowed)
// ---------------------------------------------------------------------------
__device__ float g_Q[MROWS * D_MODEL];
__device__ float g_K[MROWS * D_MODEL];
__device__ float g_V[MROWS * D_MODEL];
__device__ float g_CTX[MROWS * D_MODEL];
__device__ __nv_bfloat16 g_A3[(size_t)MROWS * KP];          // [hi | lo | hi]
__device__ __nv_bfloat16 g_Wq3[(size_t)D_MODEL * KP];       // transposed, [hi | hi | lo]
__device__ __nv_bfloat16 g_Wk3[(size_t)D_MODEL * KP];
__device__ __nv_bfloat16 g_Wv3[(size_t)D_MODEL * KP];
__device__ __nv_bfloat16 g_Wo3[(size_t)D_MODEL * KP];

// ---------------------------------------------------------------------------
// Split conversions (bf16 hi/lo error compensation)
// ---------------------------------------------------------------------------

// src [rows][2048] fp32 -> dst [rows][6144] bf16 laid out [hi | lo | hi]
__global__ __launch_bounds__(256) void split_act(
    const float* __restrict__ src, __nv_bfloat16* __restrict__ dst)
{
    int t = blockIdx.x * blockDim.x + threadIdx.x;
    int m = t >> 9;                 // 512 float4 per row
    int k4 = (t & 511) << 2;
    float4 v = *(const float4*)(src + (size_t)m * D_MODEL + k4);

    __nv_bfloat16 h0 = __float2bfloat16(v.x);
    __nv_bfloat16 h1 = __float2bfloat16(v.y);
    __nv_bfloat16 h2 = __float2bfloat16(v.z);
    __nv_bfloat16 h3 = __float2bfloat16(v.w);
    __nv_bfloat16 l0 = __float2bfloat16(v.x - __bfloat162float(h0));
    __nv_bfloat16 l1 = __float2bfloat16(v.y - __bfloat162float(h1));
    __nv_bfloat16 l2 = __float2bfloat16(v.z - __bfloat162float(h2));
    __nv_bfloat16 l3 = __float2bfloat16(v.w - __bfloat162float(h3));

    __nv_bfloat162 hA; hA.x = h0; hA.y = h1;
    __nv_bfloat162 hB; hB.x = h2; hB.y = h3;
    __nv_bfloat162 lA; lA.x = l0; lA.y = l1;
    __nv_bfloat162 lB; lB.x = l2; lB.y = l3;

    size_t base = (size_t)m * KP + k4;
    *(__nv_bfloat162*)(dst + base)              = hA;
    *(__nv_bfloat162*)(dst + base + 2)          = hB;
    *(__nv_bfloat162*)(dst + base + D_MODEL)    = lA;
    *(__nv_bfloat162*)(dst + base + D_MODEL + 2)= lB;
    *(__nv_bfloat162*)(dst + base + 2*D_MODEL)  = hA;
    *(__nv_bfloat162*)(dst + base + 2*D_MODEL+2)= hB;
}

// W [2048(k)][2048(n)] fp32 -> Wt [2048(n)][6144(k)] bf16 laid out [hi | hi | lo]
__global__ __launch_bounds__(256) void split_wt(
    const float* __restrict__ W, __nv_bfloat16* __restrict__ Wt)
{
    __shared__ float tile[32][33];
    int tx = threadIdx.x & 31, ty = threadIdx.x >> 5;   // 32 x 8
    int n0 = blockIdx.x * 32, k0 = blockIdx.y * 32;
#pragma unroll
    for (int j = 0; j < 4; j++)
        tile[ty + 8*j][tx] = W[(size_t)(k0 + ty + 8*j) * D_MODEL + n0 + tx];
    __syncthreads();
#pragma unroll
    for (int j = 0; j < 4; j++) {
        int n = n0 + ty + 8*j;
        float v = tile[tx][ty + 8*j];                  // = W[k0+tx][n]
        __nv_bfloat16 h = __float2bfloat16(v);
        __nv_bfloat16 l = __float2bfloat16(v - __bfloat162float(h));
        size_t base = (size_t)n * KP + k0 + tx;
        Wt[base]             = h;
        Wt[base + D_MODEL]   = h;
        Wt[base + 2*D_MODEL] = l;
    }
}

// ---------------------------------------------------------------------------
// mma.sync bf16 GEMM: C[4096,2048] fp32 = A3[4096,6144] @ Wt3[2048,6144]^T
// CTA tile 128x128, BK=32, 8 warps (2M x 4N), warp tile 64x32.
// mma.sync.aligned.m16n8k16.row.col.f32.bf16.bf16.f32
// ---------------------------------------------------------------------------
#define BKg 32
#define APAD 8                      // bf16 pad -> row stride 40 (80B, conflict-free)
#define GM_CHUNKS (KP / BKg)        // 192

__device__ __forceinline__ void mma16816(
    float* c, const uint32_t* a, const uint32_t* b)
{
    asm volatile(
        "mma.sync.aligned.m16n8k16.row.col.f32.bf16.bf16.f32 "
        "{%0,%1,%2,%3}, {%4,%5,%6,%7}, {%8,%9}, {%0,%1,%2,%3};"
        : "+f"(c[0]), "+f"(c[1]), "+f"(c[2]), "+f"(c[3])
        : "r"(a[0]), "r"(a[1]), "r"(a[2]), "r"(a[3]), "r"(b[0]), "r"(b[1]));
}

__global__ __launch_bounds__(256, 1) void gemm_mma(
    const __nv_bfloat16* __restrict__ A,   // [4096, 6144] K-major
    const __nv_bfloat16* __restrict__ B,   // [2048, 6144] K-major (= W^T tripled)
    float* __restrict__ C)                 // [4096, 2048]
{
    __shared__ __align__(16) __nv_bfloat16 As[2][128][BKg + APAD];
    __shared__ __align__(16) __nv_bfloat16 Bs[2][128][BKg + APAD];

    const int tid  = threadIdx.x;
    const int wid  = tid >> 5;
    const int lane = tid & 31;
    const int warp_m = (wid & 1) * 64;      // 2 warps along M
    const int warp_n = (wid >> 1) * 32;     // 4 warps along N
    const int row0 = blockIdx.y * 128;
    const int col0 = blockIdx.x * 128;

    // global load coords: 512 uint4 per 128x32 tile; 2 per thread
    const int ld_r0 = (tid + 0)   >> 2;     // rows 0..63
    const int ld_r1 = (tid + 256) >> 2;     // rows 64..127
    const int ld_c  = (tid & 3) * 8;        // bf16 col 0,8,16,24

    const __nv_bfloat16* Arow0 = A + (size_t)(row0 + ld_r0) * KP + ld_c;
    const __nv_bfloat16* Arow1 = A + (size_t)(row0 + ld_r1) * KP + ld_c;
    const __nv_bfloat16* Brow0 = B + (size_t)(col0 + ld_r0) * KP + ld_c;
    const __nv_bfloat16* Brow1 = B + (size_t)(col0 + ld_r1) * KP + ld_c;

    float acc[4][4][4];
#pragma unroll
    for (int mt = 0; mt < 4; mt++)
#pragma unroll
        for (int nt = 0; nt < 4; nt++)
#pragma unroll
            for (int i = 0; i < 4; i++) acc[mt][nt][i] = 0.0f;

    uint4 aReg0, aReg1, bReg0, bReg1;

    // preload chunk 0
    aReg0 = *(const uint4*)(Arow0);
    aReg1 = *(const uint4*)(Arow1);
    bReg0 = *(const uint4*)(Brow0);
    bReg1 = *(const uint4*)(Brow1);
    *(uint4*)(&As[0][ld_r0][ld_c]) = aReg0;
    *(uint4*)(&As[0][ld_r1][ld_c]) = aReg1;
    *(uint4*)(&Bs[0][ld_r0][ld_c]) = bReg0;
    *(uint4*)(&Bs[0][ld_r1][ld_c]) = bReg1;
    __syncthreads();

    const int lr  = lane >> 2;              // 0..7
    const int lc2 = (lane & 3) * 2;         // 0,2,4,6

    for (int kc = 0; kc < GM_CHUNKS; kc++) {
        const int buf = kc & 1;
        if (kc + 1 < GM_CHUNKS) {
            size_t off = (size_t)(kc + 1) * BKg;
            aReg0 = *(const uint4*)(Arow0 + off);
            aReg1 = *(const uint4*)(Arow1 + off);
            bReg0 = *(const uint4*)(Brow0 + off);
            bReg1 = *(const uint4*)(Brow1 + off);
        }

#pragma unroll
        for (int ks = 0; ks < 2; ks++) {
            const int kk = ks * 16 + lc2;
            uint32_t afrag[4][4];
            uint32_t bfrag[4][2];
#pragma unroll
            for (int mt = 0; mt < 4; mt++) {
                int r = warp_m + mt * 16 + lr;
                afrag[mt][0] = *(const uint32_t*)(&As[buf][r    ][kk    ]);
                afrag[mt][1] = *(const uint32_t*)(&As[buf][r + 8][kk    ]);
                afrag[mt][2] = *(const uint32_t*)(&As[buf][r    ][kk + 8]);
                afrag[mt][3] = *(const uint32_t*)(&As[buf][r + 8][kk + 8]);
            }
#pragma unroll
            for (int nt = 0; nt < 4; nt++) {
                int n = warp_n + nt * 8 + lr;
                bfrag[nt][0] = *(const uint32_t*)(&Bs[buf][n][kk    ]);
                bfrag[nt][1] = *(const uint32_t*)(&Bs[buf][n][kk + 8]);
            }
#pragma unroll
            for (int mt = 0; mt < 4; mt++)
#pragma unroll
                for (int nt = 0; nt < 4; nt++)
                    mma16816(acc[mt][nt], afrag[mt], bfrag[nt]);
        }

        if (kc + 1 < GM_CHUNKS) {
            const int nbuf = buf ^ 1;
            *(uint4*)(&As[nbuf][ld_r0][ld_c]) = aReg0;
            *(uint4*)(&As[nbuf][ld_r1][ld_c]) = aReg1;
            *(uint4*)(&Bs[nbuf][ld_r0][ld_c]) = bReg0;
            *(uint4*)(&Bs[nbuf][ld_r1][ld_c]) = bReg1;
            __syncthreads();
        }
    }

    // Epilogue: acc[mt][nt] frag layout -> C
#pragma unroll
    for (int mt = 0; mt < 4; mt++) {
        int r = row0 + warp_m + mt * 16 + lr;
#pragma unroll
        for (int nt = 0; nt < 4; nt++) {
            int c = col0 + warp_n + nt * 8 + lc2;
            *(float2*)(C + (size_t)r * D_MODEL + c)       = make_float2(acc[mt][nt][0], acc[mt][nt][1]);
            *(float2*)(C + (size_t)(r + 8) * D_MODEL + c) = make_float2(acc[mt][nt][2], acc[mt][nt][3]);
        }
    }
}

// ---------------------------------------------------------------------------
// Flash-style causal attention (unchanged — correct fp32 baseline).
// ---------------------------------------------------------------------------
#define BM 64
#define BN 64
#define KV_PAD 4

__global__ __launch_bounds__(256, 1) void flash_attn(
    const float* __restrict__ Q, const float* __restrict__ K,
    const float* __restrict__ V, float* __restrict__ CTX)
{
    __shared__ float KVs[BN][D_HEAD + KV_PAD];

    const int tid = threadIdx.x;
    const int r   = tid >> 2;
    const int seg = tid & 3;
    const int d0  = seg * 32;

    const int qb = blockIdx.x;
    const int h  = blockIdx.y;
    const int b  = blockIdx.z;

    const int qg = qb * BM + r;
    const size_t row_base = ((size_t)b * SEQ_LEN + qg) * D_MODEL + h * D_HEAD;

    const float inv_sqrt_dh = 0.08838834764831845f;

    float qreg[32];
#pragma unroll
    for (int i = 0; i < 8; i++) {
        float4 v = *(const float4*)(Q + row_base + d0 + i * 4);
        qreg[i*4+0] = v.x; qreg[i*4+1] = v.y; qreg[i*4+2] = v.z; qreg[i*4+3] = v.w;
    }

    float accv[32];
#pragma unroll
    for (int i = 0; i < 32; i++) accv[i] = 0.0f;
    float m = -CUDART_INF_F;
    float l = 0.0f;

    for (int kb = 0; kb <= qb; kb++) {
        const size_t kv_base = ((size_t)b * SEQ_LEN + kb * BN) * D_MODEL + h * D_HEAD;

#pragma unroll
        for (int i = 0; i < 8; i++) {
            int lin = tid + i * 256;
            int row = lin >> 5;
            int c4  = lin & 31;
            float4 v = *(const float4*)(K + kv_base + (size_t)row * D_MODEL + c4 * 4);
            *(float4*)(&KVs[row][c4 * 4]) = v;
        }
        __syncthreads();

        float s[BN];
#pragma unroll
        for (int c = 0; c < BN; c++) {
            float acc = 0.0f;
#pragma unroll
            for (int i = 0; i < 8; i++) {
                float4 kv = *(const float4*)(&KVs[c][d0 + i * 4]);
                acc += qreg[i*4+0] * kv.x;
                acc += qreg[i*4+1] * kv.y;
                acc += qreg[i*4+2] * kv.z;
                acc += qreg[i*4+3] * kv.w;
            }
            s[c] = acc;
        }
#pragma unroll
        for (int c = 0; c < BN; c++) {
            s[c] += __shfl_xor_sync(0xffffffffu, s[c], 1);
            s[c] += __shfl_xor_sync(0xffffffffu, s[c], 2);
            s[c] *= inv_sqrt_dh;
            int kcg = kb * BN + c;
            if (kcg > qg) s[c] = -CUDART_INF_F;
        }

        float m_new = m;
#pragma unroll
        for (int c = 0; c < BN; c++) m_new = fmaxf(m_new, s[c]);

        float corr = __expf(m - m_new);
        l *= corr;
#pragma unroll
        for (int i = 0; i < 32; i++) accv[i] *= corr;

        float psum = 0.0f;
#pragma unroll
        for (int c = 0; c < BN; c++) {
            float p = __expf(s[c] - m_new);
            s[c] = p;
            psum += p;
        }
        l += psum;
        m = m_new;

        __syncthreads();

#pragma unroll
        for (int i = 0; i < 8; i++) {
            int lin = tid + i * 256;
            int row = lin >> 5;
            int c4  = lin & 31;
            float4 v = *(const float4*)(V + kv_base + (size_t)row * D_MODEL + c4 * 4);
            *(float4*)(&KVs[row][c4 * 4]) = v;
        }
        __syncthreads();

#pragma unroll
        for (int c = 0; c < BN; c++) {
            float p = s[c];
#pragma unroll
            for (int i = 0; i < 8; i++) {
                float4 vv = *(const float4*)(&KVs[c][d0 + i * 4]);
                accv[i*4+0] += p * vv.x;
                accv[i*4+1] += p * vv.y;
                accv[i*4+2] += p * vv.z;
                accv[i*4+3] += p * vv.w;
            }
        }
        __syncthreads();
    }

    float inv_l = 1.0f / l;
#pragma unroll
    for (int i = 0; i < 8; i++) {
        float4 v = make_float4(accv[i*4+0] * inv_l, accv[i*4+1] * inv_l,
                               accv[i*4+2] * inv_l, accv[i*4+3] * inv_l);
        *(float4*)(CTX + row_base + d0 + i * 4) = v;
    }
}

// ---------------------------------------------------------------------------
// Launch
// ---------------------------------------------------------------------------
extern "C" void kernel_launch(void* const* d_in, const int* in_sizes, int n_in,
                              void* d_out, int out_size)
{
    const float* x     = (const float*)d_in[0];
    const float* q_w   = (const float*)d_in[1];
    const float* k_w   = (const float*)d_in[2];
    const float* v_w   = (const float*)d_in[3];
    const float* w_out = (const float*)d_in[4];
    float* out = (float*)d_out;

    float *Q, *K, *V, *CTX;
    __nv_bfloat16 *A3, *Wq3, *Wk3, *Wv3, *Wo3;
    cudaGetSymbolAddress((void**)&Q,   g_Q);
    cudaGetSymbolAddress((void**)&K,   g_K);
    cudaGetSymbolAddress((void**)&V,   g_V);
    cudaGetSymbolAddress((void**)&CTX, g_CTX);
    cudaGetSymbolAddress((void**)&A3,  g_A3);
    cudaGetSymbolAddress((void**)&Wq3, g_Wq3);
    cudaGetSymbolAddress((void**)&Wk3, g_Wk3);
    cudaGetSymbolAddress((void**)&Wv3, g_Wv3);
    cudaGetSymbolAddress((void**)&Wo3, g_Wo3);

    // 1. Weight splits (transpose + hi/lo bf16)
    dim3 wgrid(D_MODEL / 32, D_MODEL / 32);
    split_wt<<<wgrid, 256>>>(q_w,   Wq3);
    split_wt<<<wgrid, 256>>>(k_w,   Wk3);
    split_wt<<<wgrid, 256>>>(v_w,   Wv3);
    split_wt<<<wgrid, 256>>>(w_out, Wo3);

    // 2. Activation split
    int act_blocks = (MROWS * (D_MODEL / 4)) / 256;
    split_act<<<act_blocks, 256>>>(x, A3);

    // 3. Q/K/V projections on tensor cores (mma.sync bf16, split-K3)
    dim3 ggrid(D_MODEL / 128, MROWS / 128);   // (16, 32)
    gemm_mma<<<ggrid, 256>>>(A3, Wq3, Q);
    gemm_mma<<<ggrid, 256>>>(A3, Wk3, K);
    gemm_mma<<<ggrid, 256>>>(A3, Wv3, V);

    // 4. Attention
    dim3 attn_grid(SEQ_LEN / BM, NUM_HEADS, BATCH);
    flash_attn<<<attn_grid, 256>>>(Q, K, V, CTX);

    // 5. Output projection
    split_act<<<act_blocks, 256>>>(CTX, A3);
    gemm_mma<<<ggrid, 256>>>(A3, Wo3, out);
}

// round 4
// speedup vs baseline: 1.2715x; 1.1136x over previous
#include <cuda_runtime.h>
#include <cuda_bf16.h>
#include <math_constants.h>
#include <cstdint>

// Problem constants (fixed by the reference)
#define D_MODEL   2048
#define NUM_HEADS 16
#define SEQ_LEN   2048
#define BATCH     2
#define D_HEAD    128
#define MROWS     (BATCH * SEQ_LEN)     // 4096
#define KP        (3 * D_MODEL)         // 6144  (split-tripled K)

// ---------------------------------------------------------------------------
// Scratch (static __device__ arrays — no allocation allowed)
// ---------------------------------------------------------------------------
__device__ float g_Q[MROWS * D_MODEL];
__device__ float g_K[MROWS * D_MODEL];
__device__ float g_V[MROWS * D_MODEL];
__device__ float g_CTX[MROWS * D_MODEL];
__device__ __nv_bfloat16 g_A3[(size_t)MROWS * KP];          // [hi | lo | hi]
__device__ __nv_bfloat16 g_Wq3[(size_t)D_MODEL * KP];       // transposed, [hi | hi | lo]
__device__ __nv_bfloat16 g_Wk3[(size_t)D_MODEL * KP];
__device__ __nv_bfloat16 g_Wv3[(size_t)D_MODEL * KP];
__device__ __nv_bfloat16 g_Wo3[(size_t)D_MODEL * KP];

__device__ __forceinline__ uint32_t smem_to_u32(const void* p) {
    uint32_t a;
    asm("{ .reg .u64 t; cvta.to.shared.u64 t, %1; cvt.u32.u64 %0, t; }" : "=r"(a) : "l"(p));
    return a;
}

// ---------------------------------------------------------------------------
// Split conversions (bf16 hi/lo error compensation)
// ---------------------------------------------------------------------------
__global__ __launch_bounds__(256) void split_act(
    const float* __restrict__ src, __nv_bfloat16* __restrict__ dst)
{
    int t = blockIdx.x * blockDim.x + threadIdx.x;
    int m = t >> 9;
    int k4 = (t & 511) << 2;
    float4 v = *(const float4*)(src + (size_t)m * D_MODEL + k4);

    __nv_bfloat16 h0 = __float2bfloat16(v.x);
    __nv_bfloat16 h1 = __float2bfloat16(v.y);
    __nv_bfloat16 h2 = __float2bfloat16(v.z);
    __nv_bfloat16 h3 = __float2bfloat16(v.w);
    __nv_bfloat16 l0 = __float2bfloat16(v.x - __bfloat162float(h0));
    __nv_bfloat16 l1 = __float2bfloat16(v.y - __bfloat162float(h1));
    __nv_bfloat16 l2 = __float2bfloat16(v.z - __bfloat162float(h2));
    __nv_bfloat16 l3 = __float2bfloat16(v.w - __bfloat162float(h3));

    __nv_bfloat162 hA; hA.x = h0; hA.y = h1;
    __nv_bfloat162 hB; hB.x = h2; hB.y = h3;
    __nv_bfloat162 lA; lA.x = l0; lA.y = l1;
    __nv_bfloat162 lB; lB.x = l2; lB.y = l3;

    size_t base = (size_t)m * KP + k4;
    *(__nv_bfloat162*)(dst + base)              = hA;
    *(__nv_bfloat162*)(dst + base + 2)          = hB;
    *(__nv_bfloat162*)(dst + base + D_MODEL)    = lA;
    *(__nv_bfloat162*)(dst + base + D_MODEL + 2)= lB;
    *(__nv_bfloat162*)(dst + base + 2*D_MODEL)  = hA;
    *(__nv_bfloat162*)(dst + base + 2*D_MODEL+2)= hB;
}

__global__ __launch_bounds__(256) void split_wt(
    const float* __restrict__ W, __nv_bfloat16* __restrict__ Wt)
{
    __shared__ float tile[32][33];
    int tx = threadIdx.x & 31, ty = threadIdx.x >> 5;
    int n0 = blockIdx.x * 32, k0 = blockIdx.y * 32;
#pragma unroll
    for (int j = 0; j < 4; j++)
        tile[ty + 8*j][tx] = W[(size_t)(k0 + ty + 8*j) * D_MODEL + n0 + tx];
    __syncthreads();
#pragma unroll
    for (int j = 0; j < 4; j++) {
        int n = n0 + ty + 8*j;
        float v = tile[tx][ty + 8*j];
        __nv_bfloat16 h = __float2bfloat16(v);
        __nv_bfloat16 l = __float2bfloat16(v - __bfloat162float(h));
        size_t base = (size_t)n * KP + k0 + tx;
        Wt[base]             = h;
        Wt[base + D_MODEL]   = h;
        Wt[base + 2*D_MODEL] = l;
    }
}

// ---------------------------------------------------------------------------
// Pipelined mma.sync bf16 GEMM: C[4096,2048] = A3[4096,6144] @ Wt3[2048,6144]^T
// CTA 128x128, BK=64, 4 warps (2x2) of 64x64 warp tiles, 128 threads.
// cp.async 3-stage pipeline + ldmatrix.x4 fragments, XOR-swizzled smem.
// ---------------------------------------------------------------------------
#define BKg 64
#define NCH (KP / BKg)                 // 96
#define STAGE_BYTES 32768              // A tile 16KB + B tile 16KB
#define GEMM_SMEM (3 * STAGE_BYTES)    // 98304

__device__ __forceinline__ void mma16816(
    float* c, const uint32_t* a, const uint32_t* b)
{
    asm volatile(
        "mma.sync.aligned.m16n8k16.row.col.f32.bf16.bf16.f32 "
        "{%0,%1,%2,%3}, {%4,%5,%6,%7}, {%8,%9}, {%0,%1,%2,%3};"
        : "+f"(c[0]), "+f"(c[1]), "+f"(c[2]), "+f"(c[3])
        : "r"(a[0]), "r"(a[1]), "r"(a[2]), "r"(a[3]), "r"(b[0]), "r"(b[1]));
}
__device__ __forceinline__ void ldsm_x4(uint32_t* r, uint32_t addr)
{
    asm volatile("ldmatrix.sync.aligned.m8n8.x4.shared.b16 {%0,%1,%2,%3}, [%4];"
                 : "=r"(r[0]), "=r"(r[1]), "=r"(r[2]), "=r"(r[3]) : "r"(addr));
}
__device__ __forceinline__ void cp_async16(uint32_t dst, const void* src)
{
    asm volatile("cp.async.cg.shared.global [%0], [%1], 16;" :: "r"(dst), "l"(src));
}

__global__ __launch_bounds__(128) void gemm_mma(
    const __nv_bfloat16* __restrict__ A,   // [4096, 6144] K-major
    const __nv_bfloat16* __restrict__ B,   // [2048, 6144] K-major
    float* __restrict__ C)                 // [4096, 2048]
{
    extern __shared__ char gsm[];
    const uint32_t smem_base = smem_to_u32(gsm);

    const int tid  = threadIdx.x;
    const int wid  = tid >> 5;
    const int lane = tid & 31;
    const int warp_m = (wid & 1) * 64;
    const int warp_n = (wid >> 1) * 64;
    const int row0 = blockIdx.y * 128;
    const int col0 = blockIdx.x * 128;

    // cp.async coords: per tile 128 rows x 8 chunks(16B); 8 chunks per thread.
    // id = tid + i*128 -> row = id>>3, c = id&7; smem col swizzled c ^ (row&7).
    float acc[4][8][4];
#pragma unroll
    for (int mt = 0; mt < 4; mt++)
#pragma unroll
        for (int nt = 0; nt < 8; nt++)
#pragma unroll
            for (int i = 0; i < 4; i++) acc[mt][nt][i] = 0.0f;

    const __nv_bfloat16* Abase = A + (size_t)row0 * KP;
    const __nv_bfloat16* Bbase = B + (size_t)col0 * KP;

    auto issue_stage = [&](int kc, int s) {
        const uint32_t stA = smem_base + s * STAGE_BYTES;
        const uint32_t stB = stA + 16384;
        const __nv_bfloat16* gA = Abase + (size_t)kc * BKg;
        const __nv_bfloat16* gB = Bbase + (size_t)kc * BKg;
#pragma unroll
        for (int i = 0; i < 8; i++) {
            int id = tid + i * 128;
            int r = id >> 3, c = id & 7;
            uint32_t soff = r * 128 + ((c ^ (r & 7)) << 4);
            cp_async16(stA + soff, gA + (size_t)r * KP + c * 8);
            cp_async16(stB + soff, gB + (size_t)r * KP + c * 8);
        }
        asm volatile("cp.async.commit_group;" ::: "memory");
    };

    issue_stage(0, 0);
    issue_stage(1, 1);

    const int l16   = lane & 15;
    const int aCsel = lane >> 4;                       // 0/1 -> k half
    const int bRow  = (lane & 7) + ((lane & 16) >> 1); // 0..15
    const int bCsel = (lane >> 3) & 1;

    for (int kc = 0; kc < NCH; kc++) {
        if (kc + 2 < NCH) { asm volatile("cp.async.wait_group 1;" ::: "memory"); }
        else              { asm volatile("cp.async.wait_group 0;" ::: "memory"); }
        __syncthreads();
        if (kc + 2 < NCH) issue_stage(kc + 2, (kc + 2) % 3);

        const int s = kc % 3;
        const uint32_t stA = smem_base + s * STAGE_BYTES;
        const uint32_t stB = stA + 16384;

#pragma unroll
        for (int ks = 0; ks < 4; ks++) {
            uint32_t afrag[4][4], bfrag[8][2];
#pragma unroll
            for (int mt = 0; mt < 4; mt++) {
                int r = warp_m + mt * 16 + l16;
                int c = 2 * ks + aCsel;
                ldsm_x4(afrag[mt], stA + r * 128 + ((c ^ (r & 7)) << 4));
            }
#pragma unroll
            for (int ntp = 0; ntp < 4; ntp++) {
                int n = warp_n + ntp * 16 + bRow;
                int c = 2 * ks + bCsel;
                uint32_t q[4];
                ldsm_x4(q, stB + n * 128 + ((c ^ (n & 7)) << 4));
                bfrag[2*ntp][0] = q[0]; bfrag[2*ntp][1] = q[1];
                bfrag[2*ntp+1][0] = q[2]; bfrag[2*ntp+1][1] = q[3];
            }
#pragma unroll
            for (int mt = 0; mt < 4; mt++)
#pragma unroll
                for (int nt = 0; nt < 8; nt++)
                    mma16816(acc[mt][nt], afrag[mt], bfrag[nt]);
        }
    }

    // Epilogue
    const int lr  = lane >> 2;
    const int lc2 = (lane & 3) * 2;
#pragma unroll
    for (int mt = 0; mt < 4; mt++) {
        int r = row0 + warp_m + mt * 16 + lr;
#pragma unroll
        for (int nt = 0; nt < 8; nt++) {
            int c = col0 + warp_n + nt * 8 + lc2;
            *(float2*)(C + (size_t)r * D_MODEL + c)       = make_float2(acc[mt][nt][0], acc[mt][nt][1]);
            *(float2*)(C + (size_t)(r + 8) * D_MODEL + c) = make_float2(acc[mt][nt][2], acc[mt][nt][3]);
        }
    }
}

// ---------------------------------------------------------------------------
// Flash-style causal attention (unchanged — correct fp32 baseline).
// ---------------------------------------------------------------------------
#define BM 64
#define BN 64
#define KV_PAD 4

__global__ __launch_bounds__(256, 1) void flash_attn(
    const float* __restrict__ Q, const float* __restrict__ K,
    const float* __restrict__ V, float* __restrict__ CTX)
{
    __shared__ float KVs[BN][D_HEAD + KV_PAD];

    const int tid = threadIdx.x;
    const int r   = tid >> 2;
    const int seg = tid & 3;
    const int d0  = seg * 32;

    const int qb = blockIdx.x;
    const int h  = blockIdx.y;
    const int b  = blockIdx.z;

    const int qg = qb * BM + r;
    const size_t row_base = ((size_t)b * SEQ_LEN + qg) * D_MODEL + h * D_HEAD;

    const float inv_sqrt_dh = 0.08838834764831845f;

    float qreg[32];
#pragma unroll
    for (int i = 0; i < 8; i++) {
        float4 v = *(const float4*)(Q + row_base + d0 + i * 4);
        qreg[i*4+0] = v.x; qreg[i*4+1] = v.y; qreg[i*4+2] = v.z; qreg[i*4+3] = v.w;
    }

    float accv[32];
#pragma unroll
    for (int i = 0; i < 32; i++) accv[i] = 0.0f;
    float m = -CUDART_INF_F;
    float l = 0.0f;

    for (int kb = 0; kb <= qb; kb++) {
        const size_t kv_base = ((size_t)b * SEQ_LEN + kb * BN) * D_MODEL + h * D_HEAD;

#pragma unroll
        for (int i = 0; i < 8; i++) {
            int lin = tid + i * 256;
            int row = lin >> 5;
            int c4  = lin & 31;
            float4 v = *(const float4*)(K + kv_base + (size_t)row * D_MODEL + c4 * 4);
            *(float4*)(&KVs[row][c4 * 4]) = v;
        }
        __syncthreads();

        float s[BN];
#pragma unroll
        for (int c = 0; c < BN; c++) {
            float acc = 0.0f;
#pragma unroll
            for (int i = 0; i < 8; i++) {
                float4 kv = *(const float4*)(&KVs[c][d0 + i * 4]);
                acc += qreg[i*4+0] * kv.x;
                acc += qreg[i*4+1] * kv.y;
                acc += qreg[i*4+2] * kv.z;
                acc += qreg[i*4+3] * kv.w;
            }
            s[c] = acc;
        }
#pragma unroll
        for (int c = 0; c < BN; c++) {
            s[c] += __shfl_xor_sync(0xffffffffu, s[c], 1);
            s[c] += __shfl_xor_sync(0xffffffffu, s[c], 2);
            s[c] *= inv_sqrt_dh;
            int kcg = kb * BN + c;
            if (kcg > qg) s[c] = -CUDART_INF_F;
        }

        float m_new = m;
#pragma unroll
        for (int c = 0; c < BN; c++) m_new = fmaxf(m_new, s[c]);

        float corr = __expf(m - m_new);
        l *= corr;
#pragma unroll
        for (int i = 0; i < 32; i++) accv[i] *= corr;

        float psum = 0.0f;
#pragma unroll
        for (int c = 0; c < BN; c++) {
            float p = __expf(s[c] - m_new);
            s[c] = p;
            psum += p;
        }
        l += psum;
        m = m_new;

        __syncthreads();

#pragma unroll
        for (int i = 0; i < 8; i++) {
            int lin = tid + i * 256;
            int row = lin >> 5;
            int c4  = lin & 31;
            float4 v = *(const float4*)(V + kv_base + (size_t)row * D_MODEL + c4 * 4);
            *(float4*)(&KVs[row][c4 * 4]) = v;
        }
        __syncthreads();

#pragma unroll
        for (int c = 0; c < BN; c++) {
            float p = s[c];
#pragma unroll
            for (int i = 0; i < 8; i++) {
                float4 vv = *(const float4*)(&KVs[c][d0 + i * 4]);
                accv[i*4+0] += p * vv.x;
                accv[i*4+1] += p * vv.y;
                accv[i*4+2] += p * vv.z;
                accv[i*4+3] += p * vv.w;
            }
        }
        __syncthreads();
    }

    float inv_l = 1.0f / l;
#pragma unroll
    for (int i = 0; i < 8; i++) {
        float4 v = make_float4(accv[i*4+0] * inv_l, accv[i*4+1] * inv_l,
                               accv[i*4+2] * inv_l, accv[i*4+3] * inv_l);
        *(float4*)(CTX + row_base + d0 + i * 4) = v;
    }
}

// ---------------------------------------------------------------------------
// Launch
// ---------------------------------------------------------------------------
extern "C" void kernel_launch(void* const* d_in, const int* in_sizes, int n_in,
                              void* d_out, int out_size)
{
    const float* x     = (const float*)d_in[0];
    const float* q_w   = (const float*)d_in[1];
    const float* k_w   = (const float*)d_in[2];
    const float* v_w   = (const float*)d_in[3];
    const float* w_out = (const float*)d_in[4];
    float* out = (float*)d_out;

    float *Q, *K, *V, *CTX;
    __nv_bfloat16 *A3, *Wq3, *Wk3, *Wv3, *Wo3;
    cudaGetSymbolAddress((void**)&Q,   g_Q);
    cudaGetSymbolAddress((void**)&K,   g_K);
    cudaGetSymbolAddress((void**)&V,   g_V);
    cudaGetSymbolAddress((void**)&CTX, g_CTX);
    cudaGetSymbolAddress((void**)&A3,  g_A3);
    cudaGetSymbolAddress((void**)&Wq3, g_Wq3);
    cudaGetSymbolAddress((void**)&Wk3, g_Wk3);
    cudaGetSymbolAddress((void**)&Wv3, g_Wv3);
    cudaGetSymbolAddress((void**)&Wo3, g_Wo3);

    cudaFuncSetAttribute(gemm_mma,
                         cudaFuncAttributeMaxDynamicSharedMemorySize, GEMM_SMEM);

    // 1. Weight splits (transpose + hi/lo bf16)
    dim3 wgrid(D_MODEL / 32, D_MODEL / 32);
    split_wt<<<wgrid, 256>>>(q_w,   Wq3);
    split_wt<<<wgrid, 256>>>(k_w,   Wk3);
    split_wt<<<wgrid, 256>>>(v_w,   Wv3);
    split_wt<<<wgrid, 256>>>(w_out, Wo3);

    // 2. Activation split
    int act_blocks = (MROWS * (D_MODEL / 4)) / 256;
    split_act<<<act_blocks, 256>>>(x, A3);

    // 3. Q/K/V projections on tensor cores
    dim3 ggrid(D_MODEL / 128, MROWS / 128);   // (16, 32)
    gemm_mma<<<ggrid, 128, GEMM_SMEM>>>(A3, Wq3, Q);
    gemm_mma<<<ggrid, 128, GEMM_SMEM>>>(A3, Wk3, K);
    gemm_mma<<<ggrid, 128, GEMM_SMEM>>>(A3, Wv3, V);

    // 4. Attention
    dim3 attn_grid(SEQ_LEN / BM, NUM_HEADS, BATCH);
    flash_attn<<<attn_grid, 256>>>(Q, K, V, CTX);

    // 5. Output projection
    split_act<<<act_blocks, 256>>>(CTX, A3);
    gemm_mma<<<ggrid, 128, GEMM_SMEM>>>(A3, Wo3, out);
}

// round 5
// speedup vs baseline: 8.4346x; 6.6338x over previous
#include <cuda_runtime.h>
#include <cuda_bf16.h>
#include <math_constants.h>
#include <cstdint>

#define D_MODEL   2048
#define NUM_HEADS 16
#define SEQ_LEN   2048
#define BATCH     2
#define D_HEAD    128
#define MROWS     (BATCH * SEQ_LEN)     // 4096
#define KP        (3 * D_MODEL)         // 6144

// ---------------------------------------------------------------------------
// Scratch
// ---------------------------------------------------------------------------
__device__ float g_Q[MROWS * D_MODEL];
__device__ float g_K[MROWS * D_MODEL];
__device__ float g_V[MROWS * D_MODEL];
__device__ float g_CTX[MROWS * D_MODEL];
__device__ __nv_bfloat16 g_A3[(size_t)MROWS * KP];
__device__ __nv_bfloat16 g_Wq3[(size_t)D_MODEL * KP];
__device__ __nv_bfloat16 g_Wk3[(size_t)D_MODEL * KP];
__device__ __nv_bfloat16 g_Wv3[(size_t)D_MODEL * KP];
__device__ __nv_bfloat16 g_Wo3[(size_t)D_MODEL * KP];
// attention operands, per-head layout [b][h][t][128]
#define HSZ ((size_t)BATCH * NUM_HEADS * SEQ_LEN * D_HEAD)
__device__ __nv_bfloat16 g_Qhi[HSZ];
__device__ __nv_bfloat16 g_Qlo[HSZ];
__device__ __nv_bfloat16 g_Khi[HSZ];
__device__ __nv_bfloat16 g_Klo[HSZ];
__device__ __nv_bfloat16 g_Vhi[HSZ];
__device__ __nv_bfloat16 g_Vlo[HSZ];

__device__ __forceinline__ uint32_t smem_to_u32(const void* p) {
    uint32_t a;
    asm("{ .reg .u64 t; cvta.to.shared.u64 t, %1; cvt.u32.u64 %0, t; }" : "=r"(a) : "l"(p));
    return a;
}
__device__ __forceinline__ void mma16816(
    float* c, const uint32_t* a, const uint32_t* b)
{
    asm volatile(
        "mma.sync.aligned.m16n8k16.row.col.f32.bf16.bf16.f32 "
        "{%0,%1,%2,%3}, {%4,%5,%6,%7}, {%8,%9}, {%0,%1,%2,%3};"
        : "+f"(c[0]), "+f"(c[1]), "+f"(c[2]), "+f"(c[3])
        : "r"(a[0]), "r"(a[1]), "r"(a[2]), "r"(a[3]), "r"(b[0]), "r"(b[1]));
}
__device__ __forceinline__ void ldsm_x4(uint32_t* r, uint32_t addr)
{
    asm volatile("ldmatrix.sync.aligned.m8n8.x4.shared.b16 {%0,%1,%2,%3}, [%4];"
                 : "=r"(r[0]), "=r"(r[1]), "=r"(r[2]), "=r"(r[3]) : "r"(addr));
}
__device__ __forceinline__ void ldsm_x4_t(uint32_t* r, uint32_t addr)
{
    asm volatile("ldmatrix.sync.aligned.m8n8.x4.trans.shared.b16 {%0,%1,%2,%3}, [%4];"
                 : "=r"(r[0]), "=r"(r[1]), "=r"(r[2]), "=r"(r[3]) : "r"(addr));
}
__device__ __forceinline__ void cp_async16(uint32_t dst, const void* src)
{
    asm volatile("cp.async.cg.shared.global [%0], [%1], 16;" :: "r"(dst), "l"(src));
}

// ---------------------------------------------------------------------------
// Split conversions
// ---------------------------------------------------------------------------
__global__ __launch_bounds__(256) void split_act(
    const float* __restrict__ src, __nv_bfloat16* __restrict__ dst)
{
    int t = blockIdx.x * blockDim.x + threadIdx.x;
    int m = t >> 9;
    int k4 = (t & 511) << 2;
    float4 v = *(const float4*)(src + (size_t)m * D_MODEL + k4);

    __nv_bfloat16 h0 = __float2bfloat16(v.x);
    __nv_bfloat16 h1 = __float2bfloat16(v.y);
    __nv_bfloat16 h2 = __float2bfloat16(v.z);
    __nv_bfloat16 h3 = __float2bfloat16(v.w);
    __nv_bfloat162 hA; hA.x = h0; hA.y = h1;
    __nv_bfloat162 hB; hB.x = h2; hB.y = h3;
    __nv_bfloat162 lA = __floats2bfloat162_rn(v.x - __bfloat162float(h0),
                                              v.y - __bfloat162float(h1));
    __nv_bfloat162 lB = __floats2bfloat162_rn(v.z - __bfloat162float(h2),
                                              v.w - __bfloat162float(h3));
    size_t base = (size_t)m * KP + k4;
    *(__nv_bfloat162*)(dst + base)              = hA;
    *(__nv_bfloat162*)(dst + base + 2)          = hB;
    *(__nv_bfloat162*)(dst + base + D_MODEL)    = lA;
    *(__nv_bfloat162*)(dst + base + D_MODEL + 2)= lB;
    *(__nv_bfloat162*)(dst + base + 2*D_MODEL)  = hA;
    *(__nv_bfloat162*)(dst + base + 2*D_MODEL+2)= hB;
}

__global__ __launch_bounds__(256) void split_wt(
    const float* __restrict__ W, __nv_bfloat16* __restrict__ Wt)
{
    __shared__ float tile[32][33];
    int tx = threadIdx.x & 31, ty = threadIdx.x >> 5;
    int n0 = blockIdx.x * 32, k0 = blockIdx.y * 32;
#pragma unroll
    for (int j = 0; j < 4; j++)
        tile[ty + 8*j][tx] = W[(size_t)(k0 + ty + 8*j) * D_MODEL + n0 + tx];
    __syncthreads();
#pragma unroll
    for (int j = 0; j < 4; j++) {
        int n = n0 + ty + 8*j;
        float v = tile[tx][ty + 8*j];
        __nv_bfloat16 h = __float2bfloat16(v);
        __nv_bfloat16 l = __float2bfloat16(v - __bfloat162float(h));
        size_t base = (size_t)n * KP + k0 + tx;
        Wt[base]             = h;
        Wt[base + D_MODEL]   = h;
        Wt[base + 2*D_MODEL] = l;
    }
}

// fp32 [m=b*T+t][2048] -> per-head hi/lo bf16 [b][h][t][128], optional scale
__global__ __launch_bounds__(256) void split_qkv(
    const float* __restrict__ src, __nv_bfloat16* __restrict__ hi,
    __nv_bfloat16* __restrict__ lo, float scale)
{
    int t = blockIdx.x * blockDim.x + threadIdx.x;
    int m = t >> 9;
    int k4 = (t & 511) << 2;
    float4 v = *(const float4*)(src + (size_t)m * D_MODEL + k4);
    v.x *= scale; v.y *= scale; v.z *= scale; v.w *= scale;

    int b = m >> 11, tt = m & (SEQ_LEN - 1);
    int hh = k4 >> 7, d = k4 & 127;
    size_t o = ((size_t)(b * NUM_HEADS + hh) * SEQ_LEN + tt) * D_HEAD + d;

    __nv_bfloat16 h0 = __float2bfloat16(v.x);
    __nv_bfloat16 h1 = __float2bfloat16(v.y);
    __nv_bfloat16 h2 = __float2bfloat16(v.z);
    __nv_bfloat16 h3 = __float2bfloat16(v.w);
    __nv_bfloat162 H0; H0.x = h0; H0.y = h1;
    __nv_bfloat162 H1; H1.x = h2; H1.y = h3;
    __nv_bfloat162 L0 = __floats2bfloat162_rn(v.x - __bfloat162float(h0),
                                              v.y - __bfloat162float(h1));
    __nv_bfloat162 L1 = __floats2bfloat162_rn(v.z - __bfloat162float(h2),
                                              v.w - __bfloat162float(h3));
    *(__nv_bfloat162*)(hi + o)     = H0;
    *(__nv_bfloat162*)(hi + o + 2) = H1;
    *(__nv_bfloat162*)(lo + o)     = L0;
    *(__nv_bfloat162*)(lo + o + 2) = L1;
}

// ---------------------------------------------------------------------------
// Pipelined mma.sync bf16 GEMM (unchanged from R4)
// ---------------------------------------------------------------------------
#define BKg 64
#define NCH (KP / BKg)
#define STAGE_BYTES 32768
#define GEMM_SMEM (3 * STAGE_BYTES)

__global__ __launch_bounds__(128) void gemm_mma(
    const __nv_bfloat16* __restrict__ A,
    const __nv_bfloat16* __restrict__ B,
    float* __restrict__ C)
{
    extern __shared__ char gsm[];
    const uint32_t smem_base = smem_to_u32(gsm);

    const int tid  = threadIdx.x;
    const int wid  = tid >> 5;
    const int lane = tid & 31;
    const int warp_m = (wid & 1) * 64;
    const int warp_n = (wid >> 1) * 64;
    const int row0 = blockIdx.y * 128;
    const int col0 = blockIdx.x * 128;

    float acc[4][8][4];
#pragma unroll
    for (int mt = 0; mt < 4; mt++)
#pragma unroll
        for (int nt = 0; nt < 8; nt++)
#pragma unroll
            for (int i = 0; i < 4; i++) acc[mt][nt][i] = 0.0f;

    const __nv_bfloat16* Abase = A + (size_t)row0 * KP;
    const __nv_bfloat16* Bbase = B + (size_t)col0 * KP;

    auto issue_stage = [&](int kc, int s) {
        const uint32_t stA = smem_base + s * STAGE_BYTES;
        const uint32_t stB = stA + 16384;
        const __nv_bfloat16* gA = Abase + (size_t)kc * BKg;
        const __nv_bfloat16* gB = Bbase + (size_t)kc * BKg;
#pragma unroll
        for (int i = 0; i < 8; i++) {
            int id = tid + i * 128;
            int r = id >> 3, c = id & 7;
            uint32_t soff = r * 128 + ((c ^ (r & 7)) << 4);
            cp_async16(stA + soff, gA + (size_t)r * KP + c * 8);
            cp_async16(stB + soff, gB + (size_t)r * KP + c * 8);
        }
        asm volatile("cp.async.commit_group;" ::: "memory");
    };

    issue_stage(0, 0);
    issue_stage(1, 1);

    const int l16   = lane & 15;
    const int aCsel = lane >> 4;
    const int bRow  = (lane & 7) + ((lane & 16) >> 1);
    const int bCsel = (lane >> 3) & 1;

    for (int kc = 0; kc < NCH; kc++) {
        if (kc + 2 < NCH) { asm volatile("cp.async.wait_group 1;" ::: "memory"); }
        else              { asm volatile("cp.async.wait_group 0;" ::: "memory"); }
        __syncthreads();
        if (kc + 2 < NCH) issue_stage(kc + 2, (kc + 2) % 3);

        const int s = kc % 3;
        const uint32_t stA = smem_base + s * STAGE_BYTES;
        const uint32_t stB = stA + 16384;

#pragma unroll
        for (int ks = 0; ks < 4; ks++) {
            uint32_t afrag[4][4], bfrag[8][2];
#pragma unroll
            for (int mt = 0; mt < 4; mt++) {
                int r = warp_m + mt * 16 + l16;
                int c = 2 * ks + aCsel;
                ldsm_x4(afrag[mt], stA + r * 128 + ((c ^ (r & 7)) << 4));
            }
#pragma unroll
            for (int ntp = 0; ntp < 4; ntp++) {
                int n = warp_n + ntp * 16 + bRow;
                int c = 2 * ks + bCsel;
                uint32_t q[4];
                ldsm_x4(q, stB + n * 128 + ((c ^ (n & 7)) << 4));
                bfrag[2*ntp][0] = q[0]; bfrag[2*ntp][1] = q[1];
                bfrag[2*ntp+1][0] = q[2]; bfrag[2*ntp+1][1] = q[3];
            }
#pragma unroll
            for (int mt = 0; mt < 4; mt++)
#pragma unroll
                for (int nt = 0; nt < 8; nt++)
                    mma16816(acc[mt][nt], afrag[mt], bfrag[nt]);
        }
    }

    const int lr  = lane >> 2;
    const int lc2 = (lane & 3) * 2;
#pragma unroll
    for (int mt = 0; mt < 4; mt++) {
        int r = row0 + warp_m + mt * 16 + lr;
#pragma unroll
        for (int nt = 0; nt < 8; nt++) {
            int c = col0 + warp_n + nt * 8 + lc2;
            *(float2*)(C + (size_t)r * D_MODEL + c)       = make_float2(acc[mt][nt][0], acc[mt][nt][1]);
            *(float2*)(C + (size_t)(r + 8) * D_MODEL + c) = make_float2(acc[mt][nt][2], acc[mt][nt][3]);
        }
    }
}

// ---------------------------------------------------------------------------
// Tensor-core causal flash attention with hi/lo split compensation.
// CTA: 128 queries x (64-key blocks), 8 warps, 192KB smem, cp.async prefetch.
// ---------------------------------------------------------------------------
#define BMa 128
#define BNa 64
#define ATT_SMEM (3 * 65536)   // Qhi+Qlo 64KB, 2 KV stages 64KB each

__global__ __launch_bounds__(256, 1) void attn_mma(
    const __nv_bfloat16* __restrict__ Qhi, const __nv_bfloat16* __restrict__ Qlo,
    const __nv_bfloat16* __restrict__ Khi, const __nv_bfloat16* __restrict__ Klo,
    const __nv_bfloat16* __restrict__ Vhi, const __nv_bfloat16* __restrict__ Vlo,
    float* __restrict__ CTX)
{
    extern __shared__ char smemraw[];
    const uint32_t sb = smem_to_u32(smemraw);
    const int tid = threadIdx.x, wid = tid >> 5, lane = tid & 31;
    const int qb = gridDim.x - 1 - blockIdx.x;   // heavy blocks first
    const int h = blockIdx.y, b = blockIdx.z;
    const int warp_m = wid * 16;

    const size_t head_off = (size_t)(b * NUM_HEADS + h) * SEQ_LEN * D_HEAD;
    const uint32_t sQhi = sb, sQlo = sb + 32768;

    // load Q tiles (hi & lo), swizzled; rows of 128 bf16 = 16 chunks of 16B
    {
        const __nv_bfloat16* qhg = Qhi + head_off + (size_t)qb * BMa * D_HEAD;
        const __nv_bfloat16* qlg = Qlo + head_off + (size_t)qb * BMa * D_HEAD;
#pragma unroll
        for (int i = 0; i < 8; i++) {
            int id = tid + i * 256;
            int r = id >> 4, c = id & 15;
            uint32_t sw = (uint32_t)((c & 8) | ((c & 7) ^ (r & 7))) << 4;
            cp_async16(sQhi + r * 256 + sw, qhg + r * 128 + c * 8);
            cp_async16(sQlo + r * 256 + sw, qlg + r * 128 + c * 8);
        }
        asm volatile("cp.async.commit_group;" ::: "memory");
    }

    const int nkb = 2 * qb + 2;
    auto issue_kv = [&](int kb, int s) {
        uint32_t st = sb + 65536 + s * 65536;
        const __nv_bfloat16* kh = Khi + head_off + (size_t)kb * BNa * D_HEAD;
        const __nv_bfloat16* kl = Klo + head_off + (size_t)kb * BNa * D_HEAD;
        const __nv_bfloat16* vh = Vhi + head_off + (size_t)kb * BNa * D_HEAD;
        const __nv_bfloat16* vl = Vlo + head_off + (size_t)kb * BNa * D_HEAD;
#pragma unroll
        for (int i = 0; i < 4; i++) {
            int id = tid + i * 256;
            int r = id >> 4, c = id & 15;
            uint32_t sw = (uint32_t)((c & 8) | ((c & 7) ^ (r & 7))) << 4;
            uint32_t so = r * 256 + sw;
            int go = r * 128 + c * 8;
            cp_async16(st +         so, kh + go);
            cp_async16(st + 16384 + so, kl + go);
            cp_async16(st + 32768 + so, vh + go);
            cp_async16(st + 49152 + so, vl + go);
        }
        asm volatile("cp.async.commit_group;" ::: "memory");
    };
    issue_kv(0, 0);

    float oacc[16][4];
#pragma unroll
    for (int j = 0; j < 16; j++)
#pragma unroll
        for (int i = 0; i < 4; i++) oacc[j][i] = 0.0f;
    float m0 = -1e30f, m1 = -1e30f, l0 = 0.0f, l1 = 0.0f;
    const int lr = lane >> 2, lc2 = (lane & 3) * 2;

    for (int kb = 0; kb < nkb; kb++) {
        asm volatile("cp.async.wait_group 0;" ::: "memory");
        __syncthreads();
        if (kb + 1 < nkb) issue_kv(kb + 1, (kb + 1) & 1);

        const uint32_t st = sb + 65536 + (kb & 1) * 65536;
        float sacc[8][4];
#pragma unroll
        for (int j = 0; j < 8; j++)
#pragma unroll
            for (int i = 0; i < 4; i++) sacc[j][i] = 0.0f;

        // 3 score passes: (Qhi,Khi), (Qlo,Khi), (Qhi,Klo)
#pragma unroll
        for (int pass = 0; pass < 3; pass++) {
            const uint32_t sQ = (pass == 1) ? sQlo : sQhi;
            const uint32_t sK = (pass == 2) ? (st + 16384) : st;
#pragma unroll
            for (int ks = 0; ks < 8; ks++) {
                uint32_t a[4];
                {
                    int r = warp_m + (lane & 15);
                    int c = 2 * ks + (lane >> 4);
                    uint32_t sw = (uint32_t)((c & 8) | ((c & 7) ^ (r & 7))) << 4;
                    ldsm_x4(a, sQ + r * 256 + sw);
                }
                uint32_t bf[8][2];
#pragma unroll
                for (int g4 = 0; g4 < 4; g4++) {
                    int n = g4 * 16 + (lane & 7) + ((lane & 16) >> 1);
                    int c = 2 * ks + ((lane >> 3) & 1);
                    uint32_t sw = (uint32_t)((c & 8) | ((c & 7) ^ (n & 7))) << 4;
                    uint32_t q[4];
                    ldsm_x4(q, sK + n * 256 + sw);
                    bf[2*g4][0] = q[0]; bf[2*g4][1] = q[1];
                    bf[2*g4+1][0] = q[2]; bf[2*g4+1][1] = q[3];
                }
#pragma unroll
                for (int j = 0; j < 8; j++) mma16816(sacc[j], a, bf[j]);
            }
        }

        // causal mask (only blocks overlapping the diagonal)
        if (kb >= 2 * qb) {
            const int diag = kb * BNa - qb * BMa;   // 0 or 64
            const int ra = warp_m + lr, rb = ra + 8;
#pragma unroll
            for (int j = 0; j < 8; j++) {
                int colb = diag + 8 * j + lc2;
                if (colb     > ra) sacc[j][0] = -1e30f;
                if (colb + 1 > ra) sacc[j][1] = -1e30f;
                if (colb     > rb) sacc[j][2] = -1e30f;
                if (colb + 1 > rb) sacc[j][3] = -1e30f;
            }
        }

        // online softmax
        float rmx0 = -1e30f, rmx1 = -1e30f;
#pragma unroll
        for (int j = 0; j < 8; j++) {
            rmx0 = fmaxf(rmx0, fmaxf(sacc[j][0], sacc[j][1]));
            rmx1 = fmaxf(rmx1, fmaxf(sacc[j][2], sacc[j][3]));
        }
        rmx0 = fmaxf(rmx0, __shfl_xor_sync(0xffffffffu, rmx0, 1));
        rmx0 = fmaxf(rmx0, __shfl_xor_sync(0xffffffffu, rmx0, 2));
        rmx1 = fmaxf(rmx1, __shfl_xor_sync(0xffffffffu, rmx1, 1));
        rmx1 = fmaxf(rmx1, __shfl_xor_sync(0xffffffffu, rmx1, 2));
        float mn0 = fmaxf(m0, rmx0), mn1 = fmaxf(m1, rmx1);
        float c0 = __expf(m0 - mn0), c1 = __expf(m1 - mn1);
        m0 = mn0; m1 = mn1;
        float ps0 = 0.0f, ps1 = 0.0f;
#pragma unroll
        for (int j = 0; j < 8; j++) {
            sacc[j][0] = __expf(sacc[j][0] - mn0); ps0 += sacc[j][0];
            sacc[j][1] = __expf(sacc[j][1] - mn0); ps0 += sacc[j][1];
            sacc[j][2] = __expf(sacc[j][2] - mn1); ps1 += sacc[j][2];
            sacc[j][3] = __expf(sacc[j][3] - mn1); ps1 += sacc[j][3];
        }
        l0 = l0 * c0 + ps0;
        l1 = l1 * c1 + ps1;
#pragma unroll
        for (int j = 0; j < 16; j++) {
            oacc[j][0] *= c0; oacc[j][1] *= c0;
            oacc[j][2] *= c1; oacc[j][3] *= c1;
        }

        // PV: O += Phi*Vhi + Plo*Vhi + Phi*Vlo
        const uint32_t sVhi = st + 32768, sVlo = st + 49152;
#pragma unroll
        for (int s = 0; s < 4; s++) {
            uint32_t phi[4], plo[4];
            {
                const float* pa = sacc[2*s];
                const float* pb = sacc[2*s + 1];
#pragma unroll
                for (int u = 0; u < 2; u++) {
                    float x0 = pa[2*u], x1 = pa[2*u+1];
                    __nv_bfloat16 hx = __float2bfloat16(x0), hy = __float2bfloat16(x1);
                    __nv_bfloat162 H; H.x = hx; H.y = hy;
                    __nv_bfloat162 L = __floats2bfloat162_rn(
                        x0 - __bfloat162float(hx), x1 - __bfloat162float(hy));
                    phi[u] = *(uint32_t*)&H; plo[u] = *(uint32_t*)&L;
                }
#pragma unroll
                for (int u = 0; u < 2; u++) {
                    float x0 = pb[2*u], x1 = pb[2*u+1];
                    __nv_bfloat16 hx = __float2bfloat16(x0), hy = __float2bfloat16(x1);
                    __nv_bfloat162 H; H.x = hx; H.y = hy;
                    __nv_bfloat162 L = __floats2bfloat162_rn(
                        x0 - __bfloat162float(hx), x1 - __bfloat162float(hy));
                    phi[2+u] = *(uint32_t*)&H; plo[2+u] = *(uint32_t*)&L;
                }
            }
            uint32_t bv[16][2];
            const int mid = lane >> 3;
#pragma unroll
            for (int g = 0; g < 8; g++) {
                int r = s * 16 + 8 * (mid & 1) + (lane & 7);
                int c = 2 * g + (mid >> 1);
                uint32_t sw = (uint32_t)((c & 8) | ((c & 7) ^ (r & 7))) << 4;
                uint32_t q[4];
                ldsm_x4_t(q, sVhi + r * 256 + sw);
                bv[2*g][0] = q[0]; bv[2*g][1] = q[1];
                bv[2*g+1][0] = q[2]; bv[2*g+1][1] = q[3];
            }
#pragma unroll
            for (int j = 0; j < 16; j++) mma16816(oacc[j], phi, bv[j]);
#pragma unroll
            for (int j = 0; j < 16; j++) mma16816(oacc[j], plo, bv[j]);
#pragma unroll
            for (int g = 0; g < 8; g++) {
                int r = s * 16 + 8 * (mid & 1) + (lane & 7);
                int c = 2 * g + (mid >> 1);
                uint32_t sw = (uint32_t)((c & 8) | ((c & 7) ^ (r & 7))) << 4;
                uint32_t q[4];
                ldsm_x4_t(q, sVlo + r * 256 + sw);
                bv[2*g][0] = q[0]; bv[2*g][1] = q[1];
                bv[2*g+1][0] = q[2]; bv[2*g+1][1] = q[3];
            }
#pragma unroll
            for (int j = 0; j < 16; j++) mma16816(oacc[j], phi, bv[j]);
        }
    }

    // finalize
    l0 += __shfl_xor_sync(0xffffffffu, l0, 1);
    l0 += __shfl_xor_sync(0xffffffffu, l0, 2);
    l1 += __shfl_xor_sync(0xffffffffu, l1, 1);
    l1 += __shfl_xor_sync(0xffffffffu, l1, 2);
    const float il0 = 1.0f / l0, il1 = 1.0f / l1;

    const int ra = qb * BMa + warp_m + lr;
    float* d0 = CTX + ((size_t)b * SEQ_LEN + ra) * D_MODEL + h * D_HEAD;
    float* d1 = d0 + 8 * D_MODEL;
#pragma unroll
    for (int j = 0; j < 16; j++) {
        *(float2*)(d0 + 8*j + lc2) = make_float2(oacc[j][0] * il0, oacc[j][1] * il0);
        *(float2*)(d1 + 8*j + lc2) = make_float2(oacc[j][2] * il1, oacc[j][3] * il1);
    }
}

// ---------------------------------------------------------------------------
// Launch
// ---------------------------------------------------------------------------
extern "C" void kernel_launch(void* const* d_in, const int* in_sizes, int n_in,
                              void* d_out, int out_size)
{
    const float* x     = (const float*)d_in[0];
    const float* q_w   = (const float*)d_in[1];
    const float* k_w   = (const float*)d_in[2];
    const float* v_w   = (const float*)d_in[3];
    const float* w_out = (const float*)d_in[4];
    float* out = (float*)d_out;

    float *Q, *K, *V, *CTX;
    __nv_bfloat16 *A3, *Wq3, *Wk3, *Wv3, *Wo3;
    __nv_bfloat16 *Qhi, *Qlo, *Khi, *Klo, *Vhi, *Vlo;
    cudaGetSymbolAddress((void**)&Q,   g_Q);
    cudaGetSymbolAddress((void**)&K,   g_K);
    cudaGetSymbolAddress((void**)&V,   g_V);
    cudaGetSymbolAddress((void**)&CTX, g_CTX);
    cudaGetSymbolAddress((void**)&A3,  g_A3);
    cudaGetSymbolAddress((void**)&Wq3, g_Wq3);
    cudaGetSymbolAddress((void**)&Wk3, g_Wk3);
    cudaGetSymbolAddress((void**)&Wv3, g_Wv3);
    cudaGetSymbolAddress((void**)&Wo3, g_Wo3);
    cudaGetSymbolAddress((void**)&Qhi, g_Qhi);
    cudaGetSymbolAddress((void**)&Qlo, g_Qlo);
    cudaGetSymbolAddress((void**)&Khi, g_Khi);
    cudaGetSymbolAddress((void**)&Klo, g_Klo);
    cudaGetSymbolAddress((void**)&Vhi, g_Vhi);
    cudaGetSymbolAddress((void**)&Vlo, g_Vlo);

    cudaFuncSetAttribute(gemm_mma,
                         cudaFuncAttributeMaxDynamicSharedMemorySize, GEMM_SMEM);
    cudaFuncSetAttribute(attn_mma,
                         cudaFuncAttributeMaxDynamicSharedMemorySize, ATT_SMEM);

    // 1. weight + activation splits
    dim3 wgrid(D_MODEL / 32, D_MODEL / 32);
    split_wt<<<wgrid, 256>>>(q_w,   Wq3);
    split_wt<<<wgrid, 256>>>(k_w,   Wk3);
    split_wt<<<wgrid, 256>>>(v_w,   Wv3);
    split_wt<<<wgrid, 256>>>(w_out, Wo3);
    int act_blocks = (MROWS * (D_MODEL / 4)) / 256;
    split_act<<<act_blocks, 256>>>(x, A3);

    // 2. Q/K/V projections
    dim3 ggrid(D_MODEL / 128, MROWS / 128);
    gemm_mma<<<ggrid, 128, GEMM_SMEM>>>(A3, Wq3, Q);
    gemm_mma<<<ggrid, 128, GEMM_SMEM>>>(A3, Wk3, K);
    gemm_mma<<<ggrid, 128, GEMM_SMEM>>>(A3, Wv3, V);

    // 3. hi/lo split into per-head layout (scale folded into Q)
    const float inv_sqrt_dh = 0.08838834764831845f;
    split_qkv<<<act_blocks, 256>>>(Q, Qhi, Qlo, inv_sqrt_dh);
    split_qkv<<<act_blocks, 256>>>(K, Khi, Klo, 1.0f);
    split_qkv<<<act_blocks, 256>>>(V, Vhi, Vlo, 1.0f);

    // 4. tensor-core causal attention
    dim3 agrid(SEQ_LEN / BMa, NUM_HEADS, BATCH);   // (16,16,2)
    attn_mma<<<agrid, 256, ATT_SMEM>>>(Qhi, Qlo, Khi, Klo, Vhi, Vlo, CTX);

    // 5. output projection
    split_act<<<act_blocks, 256>>>(CTX, A3);
    gemm_mma<<<ggrid, 128, GEMM_SMEM>>>(A3, Wo3, out);
}

// round 6
// speedup vs baseline: 9.1390x; 1.0835x over previous
#include <cuda_runtime.h>
#include <cuda_bf16.h>
#include <math_constants.h>
#include <cstdint>

#define D_MODEL   2048
#define NUM_HEADS 16
#define SEQ_LEN   2048
#define BATCH     2
#define D_HEAD    128
#define MROWS     (BATCH * SEQ_LEN)     // 4096
#define KP        (3 * D_MODEL)         // 6144
#define NQKV      (3 * D_MODEL)         // fused QKV output width

// ---------------------------------------------------------------------------
// Scratch
// ---------------------------------------------------------------------------
__device__ __nv_bfloat16 g_A3[(size_t)MROWS * KP];           // x / ctx, [hi|lo|hi]
__device__ __nv_bfloat16 g_Wqkv3[(size_t)NQKV * KP];         // packed Wq|Wk|Wv, [n][k]
__device__ __nv_bfloat16 g_Wo3[(size_t)D_MODEL * KP];
#define HSZ ((size_t)BATCH * NUM_HEADS * SEQ_LEN * D_HEAD)
__device__ __nv_bfloat16 g_Qhi[HSZ];
__device__ __nv_bfloat16 g_Qlo[HSZ];
__device__ __nv_bfloat16 g_Khi[HSZ];
__device__ __nv_bfloat16 g_Klo[HSZ];
__device__ __nv_bfloat16 g_Vhi[HSZ];
__device__ __nv_bfloat16 g_Vlo[HSZ];

__device__ __forceinline__ uint32_t smem_to_u32(const void* p) {
    uint32_t a;
    asm("{ .reg .u64 t; cvta.to.shared.u64 t, %1; cvt.u32.u64 %0, t; }" : "=r"(a) : "l"(p));
    return a;
}
__device__ __forceinline__ void mma16816(
    float* c, const uint32_t* a, const uint32_t* b)
{
    asm volatile(
        "mma.sync.aligned.m16n8k16.row.col.f32.bf16.bf16.f32 "
        "{%0,%1,%2,%3}, {%4,%5,%6,%7}, {%8,%9}, {%0,%1,%2,%3};"
        : "+f"(c[0]), "+f"(c[1]), "+f"(c[2]), "+f"(c[3])
        : "r"(a[0]), "r"(a[1]), "r"(a[2]), "r"(a[3]), "r"(b[0]), "r"(b[1]));
}
__device__ __forceinline__ void ldsm_x4(uint32_t* r, uint32_t addr)
{
    asm volatile("ldmatrix.sync.aligned.m8n8.x4.shared.b16 {%0,%1,%2,%3}, [%4];"
                 : "=r"(r[0]), "=r"(r[1]), "=r"(r[2]), "=r"(r[3]) : "r"(addr));
}
__device__ __forceinline__ void ldsm_x4_t(uint32_t* r, uint32_t addr)
{
    asm volatile("ldmatrix.sync.aligned.m8n8.x4.trans.shared.b16 {%0,%1,%2,%3}, [%4];"
                 : "=r"(r[0]), "=r"(r[1]), "=r"(r[2]), "=r"(r[3]) : "r"(addr));
}
__device__ __forceinline__ void cp_async16(uint32_t dst, const void* src)
{
    asm volatile("cp.async.cg.shared.global [%0], [%1], 16;" :: "r"(dst), "l"(src));
}
__device__ __forceinline__ void hilo_pack(float x0, float x1, uint32_t& h, uint32_t& l)
{
    __nv_bfloat16 h0 = __float2bfloat16(x0), h1 = __float2bfloat16(x1);
    __nv_bfloat162 H; H.x = h0; H.y = h1;
    __nv_bfloat162 L = __floats2bfloat162_rn(x0 - __bfloat162float(h0),
                                             x1 - __bfloat162float(h1));
    h = *(uint32_t*)&H; l = *(uint32_t*)&L;
}

// ---------------------------------------------------------------------------
// Split conversions
// ---------------------------------------------------------------------------
__global__ __launch_bounds__(256) void split_act(
    const float* __restrict__ src, __nv_bfloat16* __restrict__ dst)
{
    int t = blockIdx.x * blockDim.x + threadIdx.x;
    int m = t >> 9;
    int k4 = (t & 511) << 2;
    float4 v = *(const float4*)(src + (size_t)m * D_MODEL + k4);

    uint32_t hA, lA, hB, lB;
    hilo_pack(v.x, v.y, hA, lA);
    hilo_pack(v.z, v.w, hB, lB);

    size_t base = (size_t)m * KP + k4;
    *(uint32_t*)(dst + base)               = hA;
    *(uint32_t*)(dst + base + 2)           = hB;
    *(uint32_t*)(dst + base + D_MODEL)     = lA;
    *(uint32_t*)(dst + base + D_MODEL + 2) = lB;
    *(uint32_t*)(dst + base + 2*D_MODEL)   = hA;
    *(uint32_t*)(dst + base + 2*D_MODEL+2) = hB;
}

__global__ __launch_bounds__(256) void split_wt(
    const float* __restrict__ W, __nv_bfloat16* __restrict__ Wt)
{
    __shared__ float tile[32][33];
    int tx = threadIdx.x & 31, ty = threadIdx.x >> 5;
    int n0 = blockIdx.x * 32, k0 = blockIdx.y * 32;
#pragma unroll
    for (int j = 0; j < 4; j++)
        tile[ty + 8*j][tx] = W[(size_t)(k0 + ty + 8*j) * D_MODEL + n0 + tx];
    __syncthreads();
#pragma unroll
    for (int j = 0; j < 4; j++) {
        int n = n0 + ty + 8*j;
        float v = tile[tx][ty + 8*j];
        __nv_bfloat16 h = __float2bfloat16(v);
        __nv_bfloat16 l = __float2bfloat16(v - __bfloat162float(h));
        size_t base = (size_t)n * KP + k0 + tx;
        Wt[base]             = h;
        Wt[base + D_MODEL]   = h;
        Wt[base + 2*D_MODEL] = l;
    }
}

// ---------------------------------------------------------------------------
// Pipelined mma.sync bf16 GEMM core (mainloop shared by both epilogues)
// CTA 128x128, BK=64, 4 warps 64x64, 3-stage cp.async.
// ---------------------------------------------------------------------------
#define BKg 64
#define NCH (KP / BKg)
#define STAGE_BYTES 32768
#define GEMM_SMEM (3 * STAGE_BYTES)

struct GemmAcc { float a[4][8][4]; };

__device__ __forceinline__ void gemm_mainloop(
    const __nv_bfloat16* __restrict__ A, const __nv_bfloat16* __restrict__ B,
    int row0, int col0, int ldb, GemmAcc& acc)
{
    extern __shared__ char gsm[];
    const uint32_t smem_base = smem_to_u32(gsm);
    const int tid  = threadIdx.x;
    const int wid  = tid >> 5;
    const int lane = tid & 31;
    const int warp_m = (wid & 1) * 64;
    const int warp_n = (wid >> 1) * 64;

#pragma unroll
    for (int mt = 0; mt < 4; mt++)
#pragma unroll
        for (int nt = 0; nt < 8; nt++)
#pragma unroll
            for (int i = 0; i < 4; i++) acc.a[mt][nt][i] = 0.0f;

    const __nv_bfloat16* Abase = A + (size_t)row0 * KP;
    const __nv_bfloat16* Bbase = B + (size_t)col0 * ldb;

    auto issue_stage = [&](int kc, int s) {
        const uint32_t stA = smem_base + s * STAGE_BYTES;
        const uint32_t stB = stA + 16384;
        const __nv_bfloat16* gA = Abase + (size_t)kc * BKg;
        const __nv_bfloat16* gB = Bbase + (size_t)kc * BKg;
#pragma unroll
        for (int i = 0; i < 8; i++) {
            int id = tid + i * 128;
            int r = id >> 3, c = id & 7;
            uint32_t soff = r * 128 + ((c ^ (r & 7)) << 4);
            cp_async16(stA + soff, gA + (size_t)r * KP + c * 8);
            cp_async16(stB + soff, gB + (size_t)r * ldb + c * 8);
        }
        asm volatile("cp.async.commit_group;" ::: "memory");
    };

    issue_stage(0, 0);
    issue_stage(1, 1);

    const int l16   = lane & 15;
    const int aCsel = lane >> 4;
    const int bRow  = (lane & 7) + ((lane & 16) >> 1);
    const int bCsel = (lane >> 3) & 1;

    for (int kc = 0; kc < NCH; kc++) {
        if (kc + 2 < NCH) { asm volatile("cp.async.wait_group 1;" ::: "memory"); }
        else              { asm volatile("cp.async.wait_group 0;" ::: "memory"); }
        __syncthreads();
        if (kc + 2 < NCH) issue_stage(kc + 2, (kc + 2) % 3);

        const int s = kc % 3;
        const uint32_t stA = smem_base + s * STAGE_BYTES;
        const uint32_t stB = stA + 16384;

#pragma unroll
        for (int ks = 0; ks < 4; ks++) {
            uint32_t afrag[4][4], bfrag[8][2];
#pragma unroll
            for (int mt = 0; mt < 4; mt++) {
                int r = warp_m + mt * 16 + l16;
                int c = 2 * ks + aCsel;
                ldsm_x4(afrag[mt], stA + r * 128 + ((c ^ (r & 7)) << 4));
            }
#pragma unroll
            for (int ntp = 0; ntp < 4; ntp++) {
                int n = warp_n + ntp * 16 + bRow;
                int c = 2 * ks + bCsel;
                uint32_t q[4];
                ldsm_x4(q, stB + n * 128 + ((c ^ (n & 7)) << 4));
                bfrag[2*ntp][0] = q[0]; bfrag[2*ntp][1] = q[1];
                bfrag[2*ntp+1][0] = q[2]; bfrag[2*ntp+1][1] = q[3];
            }
#pragma unroll
            for (int mt = 0; mt < 4; mt++)
#pragma unroll
                for (int nt = 0; nt < 8; nt++)
                    mma16816(acc.a[mt][nt], afrag[mt], bfrag[nt]);
        }
    }
}

// Fused QKV projection: C tile -> direct hi/lo per-head layout.
__global__ __launch_bounds__(128) void gemm_qkv(
    const __nv_bfloat16* __restrict__ A,        // [4096, 6144]
    const __nv_bfloat16* __restrict__ Wqkv,     // [6144, 6144]
    __nv_bfloat16* __restrict__ Qhi, __nv_bfloat16* __restrict__ Qlo,
    __nv_bfloat16* __restrict__ Khi, __nv_bfloat16* __restrict__ Klo,
    __nv_bfloat16* __restrict__ Vhi, __nv_bfloat16* __restrict__ Vlo)
{
    const int row0 = blockIdx.y * 128;
    const int col0 = blockIdx.x * 128;
    GemmAcc acc;
    gemm_mainloop(A, Wqkv, row0, col0, KP, acc);

    const int wid  = threadIdx.x >> 5;
    const int lane = threadIdx.x & 31;
    const int warp_m = (wid & 1) * 64;
    const int warp_n = (wid >> 1) * 64;
    const int lr  = lane >> 2;
    const int lc2 = (lane & 3) * 2;

    const int proj = col0 >> 11;                // 0=Q 1=K 2=V
    const int hh   = (col0 & 2047) >> 7;
    __nv_bfloat16* hiP = (proj == 0) ? Qhi : (proj == 1) ? Khi : Vhi;
    __nv_bfloat16* loP = (proj == 0) ? Qlo : (proj == 1) ? Klo : Vlo;
    const float scale = (proj == 0) ? 0.08838834764831845f : 1.0f;

#pragma unroll
    for (int mt = 0; mt < 4; mt++) {
        int r = row0 + warp_m + mt * 16 + lr;
        int b = r >> 11, t = r & (SEQ_LEN - 1);
        size_t base0 = ((size_t)(b * NUM_HEADS + hh) * SEQ_LEN + t) * D_HEAD;
        size_t base1 = base0 + 8 * D_HEAD;      // row r+8 (same batch block)
#pragma unroll
        for (int nt = 0; nt < 8; nt++) {
            int d = warp_n + nt * 8 + lc2;
            uint32_t h0, l0, h1, l1;
            hilo_pack(acc.a[mt][nt][0] * scale, acc.a[mt][nt][1] * scale, h0, l0);
            hilo_pack(acc.a[mt][nt][2] * scale, acc.a[mt][nt][3] * scale, h1, l1);
            *(uint32_t*)(hiP + base0 + d) = h0;
            *(uint32_t*)(loP + base0 + d) = l0;
            *(uint32_t*)(hiP + base1 + d) = h1;
            *(uint32_t*)(loP + base1 + d) = l1;
        }
    }
}

// Output projection: plain fp32 epilogue to d_out.
__global__ __launch_bounds__(128) void gemm_out(
    const __nv_bfloat16* __restrict__ A,
    const __nv_bfloat16* __restrict__ B,
    float* __restrict__ C)
{
    const int row0 = blockIdx.y * 128;
    const int col0 = blockIdx.x * 128;
    GemmAcc acc;
    gemm_mainloop(A, B, row0, col0, KP, acc);

    const int wid  = threadIdx.x >> 5;
    const int lane = threadIdx.x & 31;
    const int warp_m = (wid & 1) * 64;
    const int warp_n = (wid >> 1) * 64;
    const int lr  = lane >> 2;
    const int lc2 = (lane & 3) * 2;
#pragma unroll
    for (int mt = 0; mt < 4; mt++) {
        int r = row0 + warp_m + mt * 16 + lr;
#pragma unroll
        for (int nt = 0; nt < 8; nt++) {
            int c = col0 + warp_n + nt * 8 + lc2;
            *(float2*)(C + (size_t)r * D_MODEL + c)       = make_float2(acc.a[mt][nt][0], acc.a[mt][nt][1]);
            *(float2*)(C + (size_t)(r + 8) * D_MODEL + c) = make_float2(acc.a[mt][nt][2], acc.a[mt][nt][3]);
        }
    }
}

// ---------------------------------------------------------------------------
// Tensor-core causal flash attention with hi/lo split; writes A3 layout.
// ---------------------------------------------------------------------------
#define BMa 128
#define BNa 64
#define ATT_SMEM (3 * 65536)

__global__ __launch_bounds__(256, 1) void attn_mma(
    const __nv_bfloat16* __restrict__ Qhi, const __nv_bfloat16* __restrict__ Qlo,
    const __nv_bfloat16* __restrict__ Khi, const __nv_bfloat16* __restrict__ Klo,
    const __nv_bfloat16* __restrict__ Vhi, const __nv_bfloat16* __restrict__ Vlo,
    __nv_bfloat16* __restrict__ CTX3)
{
    extern __shared__ char smemraw[];
    const uint32_t sb = smem_to_u32(smemraw);
    const int tid = threadIdx.x, wid = tid >> 5, lane = tid & 31;
    const int qb = gridDim.x - 1 - blockIdx.x;
    const int h = blockIdx.y, b = blockIdx.z;
    const int warp_m = wid * 16;

    const size_t head_off = (size_t)(b * NUM_HEADS + h) * SEQ_LEN * D_HEAD;
    const uint32_t sQhi = sb, sQlo = sb + 32768;

    {
        const __nv_bfloat16* qhg = Qhi + head_off + (size_t)qb * BMa * D_HEAD;
        const __nv_bfloat16* qlg = Qlo + head_off + (size_t)qb * BMa * D_HEAD;
#pragma unroll
        for (int i = 0; i < 8; i++) {
            int id = tid + i * 256;
            int r = id >> 4, c = id & 15;
            uint32_t sw = (uint32_t)((c & 8) | ((c & 7) ^ (r & 7))) << 4;
            cp_async16(sQhi + r * 256 + sw, qhg + r * 128 + c * 8);
            cp_async16(sQlo + r * 256 + sw, qlg + r * 128 + c * 8);
        }
        asm volatile("cp.async.commit_group;" ::: "memory");
    }

    const int nkb = 2 * qb + 2;
    auto issue_kv = [&](int kb, int s) {
        uint32_t st = sb + 65536 + s * 65536;
        const __nv_bfloat16* kh = Khi + head_off + (size_t)kb * BNa * D_HEAD;
        const __nv_bfloat16* kl = Klo + head_off + (size_t)kb * BNa * D_HEAD;
        const __nv_bfloat16* vh = Vhi + head_off + (size_t)kb * BNa * D_HEAD;
        const __nv_bfloat16* vl = Vlo + head_off + (size_t)kb * BNa * D_HEAD;
#pragma unroll
        for (int i = 0; i < 4; i++) {
            int id = tid + i * 256;
            int r = id >> 4, c = id & 15;
            uint32_t sw = (uint32_t)((c & 8) | ((c & 7) ^ (r & 7))) << 4;
            uint32_t so = r * 256 + sw;
            int go = r * 128 + c * 8;
            cp_async16(st +         so, kh + go);
            cp_async16(st + 16384 + so, kl + go);
            cp_async16(st + 32768 + so, vh + go);
            cp_async16(st + 49152 + so, vl + go);
        }
        asm volatile("cp.async.commit_group;" ::: "memory");
    };
    issue_kv(0, 0);

    float oacc[16][4];
#pragma unroll
    for (int j = 0; j < 16; j++)
#pragma unroll
        for (int i = 0; i < 4; i++) oacc[j][i] = 0.0f;
    float m0 = -1e30f, m1 = -1e30f, l0 = 0.0f, l1 = 0.0f;
    const int lr = lane >> 2, lc2 = (lane & 3) * 2;

    for (int kb = 0; kb < nkb; kb++) {
        asm volatile("cp.async.wait_group 0;" ::: "memory");
        __syncthreads();
        if (kb + 1 < nkb) issue_kv(kb + 1, (kb + 1) & 1);

        const uint32_t st = sb + 65536 + (kb & 1) * 65536;
        float sacc[8][4];
#pragma unroll
        for (int j = 0; j < 8; j++)
#pragma unroll
            for (int i = 0; i < 4; i++) sacc[j][i] = 0.0f;

#pragma unroll
        for (int pass = 0; pass < 3; pass++) {
            const uint32_t sQ = (pass == 1) ? sQlo : sQhi;
            const uint32_t sK = (pass == 2) ? (st + 16384) : st;
#pragma unroll
            for (int ks = 0; ks < 8; ks++) {
                uint32_t a[4];
                {
                    int r = warp_m + (lane & 15);
                    int c = 2 * ks + (lane >> 4);
                    uint32_t sw = (uint32_t)((c & 8) | ((c & 7) ^ (r & 7))) << 4;
                    ldsm_x4(a, sQ + r * 256 + sw);
                }
                uint32_t bf[8][2];
#pragma unroll
                for (int g4 = 0; g4 < 4; g4++) {
                    int n = g4 * 16 + (lane & 7) + ((lane & 16) >> 1);
                    int c = 2 * ks + ((lane >> 3) & 1);
                    uint32_t sw = (uint32_t)((c & 8) | ((c & 7) ^ (n & 7))) << 4;
                    uint32_t q[4];
                    ldsm_x4(q, sK + n * 256 + sw);
                    bf[2*g4][0] = q[0]; bf[2*g4][1] = q[1];
                    bf[2*g4+1][0] = q[2]; bf[2*g4+1][1] = q[3];
                }
#pragma unroll
                for (int j = 0; j < 8; j++) mma16816(sacc[j], a, bf[j]);
            }
        }

        if (kb >= 2 * qb) {
            const int diag = kb * BNa - qb * BMa;
            const int ra = warp_m + lr, rb = ra + 8;
#pragma unroll
            for (int j = 0; j < 8; j++) {
                int colb = diag + 8 * j + lc2;
                if (colb     > ra) sacc[j][0] = -1e30f;
                if (colb + 1 > ra) sacc[j][1] = -1e30f;
                if (colb     > rb) sacc[j][2] = -1e30f;
                if (colb + 1 > rb) sacc[j][3] = -1e30f;
            }
        }

        float rmx0 = -1e30f, rmx1 = -1e30f;
#pragma unroll
        for (int j = 0; j < 8; j++) {
            rmx0 = fmaxf(rmx0, fmaxf(sacc[j][0], sacc[j][1]));
            rmx1 = fmaxf(rmx1, fmaxf(sacc[j][2], sacc[j][3]));
        }
        rmx0 = fmaxf(rmx0, __shfl_xor_sync(0xffffffffu, rmx0, 1));
        rmx0 = fmaxf(rmx0, __shfl_xor_sync(0xffffffffu, rmx0, 2));
        rmx1 = fmaxf(rmx1, __shfl_xor_sync(0xffffffffu, rmx1, 1));
        rmx1 = fmaxf(rmx1, __shfl_xor_sync(0xffffffffu, rmx1, 2));
        float mn0 = fmaxf(m0, rmx0), mn1 = fmaxf(m1, rmx1);
        float c0 = __expf(m0 - mn0), c1 = __expf(m1 - mn1);
        m0 = mn0; m1 = mn1;
        float ps0 = 0.0f, ps1 = 0.0f;
#pragma unroll
        for (int j = 0; j < 8; j++) {
            sacc[j][0] = __expf(sacc[j][0] - mn0); ps0 += sacc[j][0];
            sacc[j][1] = __expf(sacc[j][1] - mn0); ps0 += sacc[j][1];
            sacc[j][2] = __expf(sacc[j][2] - mn1); ps1 += sacc[j][2];
            sacc[j][3] = __expf(sacc[j][3] - mn1); ps1 += sacc[j][3];
        }
        l0 = l0 * c0 + ps0;
        l1 = l1 * c1 + ps1;
#pragma unroll
        for (int j = 0; j < 16; j++) {
            oacc[j][0] *= c0; oacc[j][1] *= c0;
            oacc[j][2] *= c1; oacc[j][3] *= c1;
        }

        const uint32_t sVhi = st + 32768, sVlo = st + 49152;
#pragma unroll
        for (int s = 0; s < 4; s++) {
            uint32_t phi[4], plo[4];
            hilo_pack(sacc[2*s][0],   sacc[2*s][1],   phi[0], plo[0]);
            hilo_pack(sacc[2*s][2],   sacc[2*s][3],   phi[1], plo[1]);
            hilo_pack(sacc[2*s+1][0], sacc[2*s+1][1], phi[2], plo[2]);
            hilo_pack(sacc[2*s+1][2], sacc[2*s+1][3], phi[3], plo[3]);

            uint32_t bv[16][2];
            const int mid = lane >> 3;
#pragma unroll
            for (int g = 0; g < 8; g++) {
                int r = s * 16 + 8 * (mid & 1) + (lane & 7);
                int c = 2 * g + (mid >> 1);
                uint32_t sw = (uint32_t)((c & 8) | ((c & 7) ^ (r & 7))) << 4;
                uint32_t q[4];
                ldsm_x4_t(q, sVhi + r * 256 + sw);
                bv[2*g][0] = q[0]; bv[2*g][1] = q[1];
                bv[2*g+1][0] = q[2]; bv[2*g+1][1] = q[3];
            }
#pragma unroll
            for (int j = 0; j < 16; j++) mma16816(oacc[j], phi, bv[j]);
#pragma unroll
            for (int j = 0; j < 16; j++) mma16816(oacc[j], plo, bv[j]);
#pragma unroll
            for (int g = 0; g < 8; g++) {
                int r = s * 16 + 8 * (mid & 1) + (lane & 7);
                int c = 2 * g + (mid >> 1);
                uint32_t sw = (uint32_t)((c & 8) | ((c & 7) ^ (r & 7))) << 4;
                uint32_t q[4];
                ldsm_x4_t(q, sVlo + r * 256 + sw);
                bv[2*g][0] = q[0]; bv[2*g][1] = q[1];
                bv[2*g+1][0] = q[2]; bv[2*g+1][1] = q[3];
            }
#pragma unroll
            for (int j = 0; j < 16; j++) mma16816(oacc[j], phi, bv[j]);
        }
    }

    l0 += __shfl_xor_sync(0xffffffffu, l0, 1);
    l0 += __shfl_xor_sync(0xffffffffu, l0, 2);
    l1 += __shfl_xor_sync(0xffffffffu, l1, 1);
    l1 += __shfl_xor_sync(0xffffffffu, l1, 2);
    const float il0 = 1.0f / l0, il1 = 1.0f / l1;

    // write hi/lo/hi A3 layout directly (m = b*SEQ + token, col = h*128 + d)
    const int ra = qb * BMa + warp_m + lr;
    size_t base0 = ((size_t)(b * SEQ_LEN) + ra) * KP + h * D_HEAD;
    size_t base1 = base0 + (size_t)8 * KP;
#pragma unroll
    for (int j = 0; j < 16; j++) {
        int d = 8 * j + lc2;
        uint32_t h2, l2;
        hilo_pack(oacc[j][0] * il0, oacc[j][1] * il0, h2, l2);
        *(uint32_t*)(CTX3 + base0 + d)             = h2;
        *(uint32_t*)(CTX3 + base0 + D_MODEL + d)   = l2;
        *(uint32_t*)(CTX3 + base0 + 2*D_MODEL + d) = h2;
        hilo_pack(oacc[j][2] * il1, oacc[j][3] * il1, h2, l2);
        *(uint32_t*)(CTX3 + base1 + d)             = h2;
        *(uint32_t*)(CTX3 + base1 + D_MODEL + d)   = l2;
        *(uint32_t*)(CTX3 + base1 + 2*D_MODEL + d) = h2;
    }
}

// ---------------------------------------------------------------------------
// Launch
// ---------------------------------------------------------------------------
extern "C" void kernel_launch(void* const* d_in, const int* in_sizes, int n_in,
                              void* d_out, int out_size)
{
    const float* x     = (const float*)d_in[0];
    const float* q_w   = (const float*)d_in[1];
    const float* k_w   = (const float*)d_in[2];
    const float* v_w   = (const float*)d_in[3];
    const float* w_out = (const float*)d_in[4];
    float* out = (float*)d_out;

    __nv_bfloat16 *A3, *Wqkv3, *Wo3;
    __nv_bfloat16 *Qhi, *Qlo, *Khi, *Klo, *Vhi, *Vlo;
    cudaGetSymbolAddress((void**)&A3,    g_A3);
    cudaGetSymbolAddress((void**)&Wqkv3, g_Wqkv3);
    cudaGetSymbolAddress((void**)&Wo3,   g_Wo3);
    cudaGetSymbolAddress((void**)&Qhi, g_Qhi);
    cudaGetSymbolAddress((void**)&Qlo, g_Qlo);
    cudaGetSymbolAddress((void**)&Khi, g_Khi);
    cudaGetSymbolAddress((void**)&Klo, g_Klo);
    cudaGetSymbolAddress((void**)&Vhi, g_Vhi);
    cudaGetSymbolAddress((void**)&Vlo, g_Vlo);

    cudaFuncSetAttribute(gemm_qkv, cudaFuncAttributeMaxDynamicSharedMemorySize, GEMM_SMEM);
    cudaFuncSetAttribute(gemm_out, cudaFuncAttributeMaxDynamicSharedMemorySize, GEMM_SMEM);
    cudaFuncSetAttribute(attn_mma, cudaFuncAttributeMaxDynamicSharedMemorySize, ATT_SMEM);

    // 1. weight + activation splits
    dim3 wgrid(D_MODEL / 32, D_MODEL / 32);
    split_wt<<<wgrid, 256>>>(q_w,   Wqkv3);
    split_wt<<<wgrid, 256>>>(k_w,   Wqkv3 + (size_t)D_MODEL * KP);
    split_wt<<<wgrid, 256>>>(v_w,   Wqkv3 + (size_t)2 * D_MODEL * KP);
    split_wt<<<wgrid, 256>>>(w_out, Wo3);
    int act_blocks = (MROWS * (D_MODEL / 4)) / 256;
    split_act<<<act_blocks, 256>>>(x, A3);

    // 2. fused QKV projection -> direct hi/lo per-head outputs
    dim3 qkvgrid(NQKV / 128, MROWS / 128);        // (48, 32)
    gemm_qkv<<<qkvgrid, 128, GEMM_SMEM>>>(A3, Wqkv3,
                                          Qhi, Qlo, Khi, Klo, Vhi, Vlo);

    // 3. tensor-core causal attention -> writes A3 [hi|lo|hi] directly
    dim3 agrid(SEQ_LEN / BMa, NUM_HEADS, BATCH);
    attn_mma<<<agrid, 256, ATT_SMEM>>>(Qhi, Qlo, Khi, Klo, Vhi, Vlo, A3);

    // 4. output projection
    dim3 ogrid(D_MODEL / 128, MROWS / 128);       // (16, 32)
    gemm_out<<<ogrid, 128, GEMM_SMEM>>>(A3, Wo3, out);
}

// round 8
// speedup vs baseline: 12.0699x; 1.3207x over previous
#include <cuda_runtime.h>
#include <cuda_fp16.h>
#include <math_constants.h>
#include <cstdint>

#define D_MODEL   2048
#define NUM_HEADS 16
#define SEQ_LEN   2048
#define BATCH     2
#define D_HEAD    128
#define MROWS     (BATCH * SEQ_LEN)     // 4096
#define KP2       (2 * D_MODEL)         // 4096  ([hi|lo] K)
#define NQKV      (3 * D_MODEL)

// ---------------------------------------------------------------------------
// Scratch
// ---------------------------------------------------------------------------
__device__ __half g_A2[(size_t)MROWS * KP2];            // x / ctx, [hi|lo] fp16
__device__ __half g_Wqkv2[(size_t)NQKV * D_MODEL];      // Wq|Wk|Wv transposed [n][k] fp16
__device__ __half g_Wo2[(size_t)D_MODEL * D_MODEL];     // W_out transposed [n][k] fp16
#define HSZ ((size_t)BATCH * NUM_HEADS * SEQ_LEN * D_HEAD)
__device__ __half g_Qhi[HSZ];
__device__ __half g_Qlo[HSZ];
__device__ __half g_Khi[HSZ];
__device__ __half g_Klo[HSZ];
__device__ __half g_Vhi[HSZ];
__device__ __half g_Vlo[HSZ];

__device__ __forceinline__ uint32_t smem_to_u32(const void* p) {
    uint32_t a;
    asm("{ .reg .u64 t; cvta.to.shared.u64 t, %1; cvt.u32.u64 %0, t; }" : "=r"(a) : "l"(p));
    return a;
}
__device__ __forceinline__ void mma16816(
    float* c, const uint32_t* a, const uint32_t* b)
{
    asm volatile(
        "mma.sync.aligned.m16n8k16.row.col.f32.f16.f16.f32 "
        "{%0,%1,%2,%3}, {%4,%5,%6,%7}, {%8,%9}, {%0,%1,%2,%3};"
        : "+f"(c[0]), "+f"(c[1]), "+f"(c[2]), "+f"(c[3])
        : "r"(a[0]), "r"(a[1]), "r"(a[2]), "r"(a[3]), "r"(b[0]), "r"(b[1]));
}
__device__ __forceinline__ void ldsm_x4(uint32_t* r, uint32_t addr)
{
    asm volatile("ldmatrix.sync.aligned.m8n8.x4.shared.b16 {%0,%1,%2,%3}, [%4];"
                 : "=r"(r[0]), "=r"(r[1]), "=r"(r[2]), "=r"(r[3]) : "r"(addr));
}
__device__ __forceinline__ void ldsm_x4_t(uint32_t* r, uint32_t addr)
{
    asm volatile("ldmatrix.sync.aligned.m8n8.x4.trans.shared.b16 {%0,%1,%2,%3}, [%4];"
                 : "=r"(r[0]), "=r"(r[1]), "=r"(r[2]), "=r"(r[3]) : "r"(addr));
}
__device__ __forceinline__ void cp_async16(uint32_t dst, const void* src)
{
    asm volatile("cp.async.cg.shared.global [%0], [%1], 16;" :: "r"(dst), "l"(src));
}
__device__ __forceinline__ void hilo_pack(float x0, float x1, uint32_t& h, uint32_t& l)
{
    __half h0 = __float2half_rn(x0), h1 = __float2half_rn(x1);
    __half l0 = __float2half_rn(x0 - __half2float(h0));
    __half l1 = __float2half_rn(x1 - __half2float(h1));
    __half2 H = __halves2half2(h0, h1);
    __half2 L = __halves2half2(l0, l1);
    h = *(uint32_t*)&H; l = *(uint32_t*)&L;
}

// ---------------------------------------------------------------------------
// Split conversions
// ---------------------------------------------------------------------------
// x [m][2048] fp32 -> A2 [m][4096] fp16 [hi|lo]
__global__ __launch_bounds__(256) void split_act(
    const float* __restrict__ src, __half* __restrict__ dst)
{
    int t = blockIdx.x * blockDim.x + threadIdx.x;
    int m = t >> 9;
    int k4 = (t & 511) << 2;
    float4 v = *(const float4*)(src + (size_t)m * D_MODEL + k4);

    uint32_t hA, lA, hB, lB;
    hilo_pack(v.x, v.y, hA, lA);
    hilo_pack(v.z, v.w, hB, lB);

    size_t base = (size_t)m * KP2 + k4;
    *(uint32_t*)(dst + base)               = hA;
    *(uint32_t*)(dst + base + 2)           = hB;
    *(uint32_t*)(dst + base + D_MODEL)     = lA;
    *(uint32_t*)(dst + base + D_MODEL + 2) = lB;
}

// all 4 weights: transpose [k][n] -> [n][k] fp16 (hi only; 2-term scheme)
__global__ __launch_bounds__(256) void split_wt_all(
    const float* __restrict__ Wq, const float* __restrict__ Wk,
    const float* __restrict__ Wv, const float* __restrict__ Wo,
    __half* __restrict__ Wqkv, __half* __restrict__ Wout)
{
    __shared__ float tile[32][33];
    const int z = blockIdx.z;
    const float* W = (z == 0) ? Wq : (z == 1) ? Wk : (z == 2) ? Wv : Wo;
    __half* dst = (z < 3) ? (Wqkv + (size_t)z * D_MODEL * D_MODEL) : Wout;

    int tx = threadIdx.x & 31, ty = threadIdx.x >> 5;
    int n0 = blockIdx.x * 32, k0 = blockIdx.y * 32;
#pragma unroll
    for (int j = 0; j < 4; j++)
        tile[ty + 8*j][tx] = W[(size_t)(k0 + ty + 8*j) * D_MODEL + n0 + tx];
    __syncthreads();
#pragma unroll
    for (int j = 0; j < 4; j++) {
        int n = n0 + ty + 8*j;
        dst[(size_t)n * D_MODEL + k0 + tx] = __float2half_rn(tile[tx][ty + 8*j]);
    }
}

// ---------------------------------------------------------------------------
// Pipelined mma.sync fp16 GEMM core.
// CTA 128x128, BK=64, 4 warps 64x64, 3-stage cp.async.
// A [m][4096] = [hi|lo]; B [n][2048]; B chunk index wraps (kc & 31).
// ---------------------------------------------------------------------------
#define BKg 64
#define NCH2 64                         // 4096 / 64
#define BMASK 31
#define STAGE_BYTES 32768
#define GEMM_SMEM (3 * STAGE_BYTES)

struct GemmAcc { float a[4][8][4]; };

__device__ __forceinline__ void gemm_mainloop(
    const __half* __restrict__ A, const __half* __restrict__ B,
    int row0, int col0, GemmAcc& acc)
{
    extern __shared__ char gsm[];
    const uint32_t smem_base = smem_to_u32(gsm);
    const int tid  = threadIdx.x;
    const int wid  = tid >> 5;
    const int lane = tid & 31;
    const int warp_m = (wid & 1) * 64;
    const int warp_n = (wid >> 1) * 64;

#pragma unroll
    for (int mt = 0; mt < 4; mt++)
#pragma unroll
        for (int nt = 0; nt < 8; nt++)
#pragma unroll
            for (int i = 0; i < 4; i++) acc.a[mt][nt][i] = 0.0f;

    const __half* Abase = A + (size_t)row0 * KP2;
    const __half* Bbase = B + (size_t)col0 * D_MODEL;

    auto issue_stage = [&](int kc, int s) {
        const uint32_t stA = smem_base + s * STAGE_BYTES;
        const uint32_t stB = stA + 16384;
        const __half* gA = Abase + (size_t)kc * BKg;
        const __half* gB = Bbase + (size_t)(kc & BMASK) * BKg;
#pragma unroll
        for (int i = 0; i < 8; i++) {
            int id = tid + i * 128;
            int r = id >> 3, c = id & 7;
            uint32_t soff = r * 128 + ((c ^ (r & 7)) << 4);
            cp_async16(stA + soff, gA + (size_t)r * KP2 + c * 8);
            cp_async16(stB + soff, gB + (size_t)r * D_MODEL + c * 8);
        }
        asm volatile("cp.async.commit_group;" ::: "memory");
    };

    issue_stage(0, 0);
    issue_stage(1, 1);

    const int l16   = lane & 15;
    const int aCsel = lane >> 4;
    const int bRow  = (lane & 7) + ((lane & 16) >> 1);
    const int bCsel = (lane >> 3) & 1;

    for (int kc = 0; kc < NCH2; kc++) {
        if (kc + 2 < NCH2) { asm volatile("cp.async.wait_group 1;" ::: "memory"); }
        else               { asm volatile("cp.async.wait_group 0;" ::: "memory"); }
        __syncthreads();
        if (kc + 2 < NCH2) issue_stage(kc + 2, (kc + 2) % 3);

        const int s = kc % 3;
        const uint32_t stA = smem_base + s * STAGE_BYTES;
        const uint32_t stB = stA + 16384;

#pragma unroll
        for (int ks = 0; ks < 4; ks++) {
            uint32_t afrag[4][4], bfrag[8][2];
#pragma unroll
            for (int mt = 0; mt < 4; mt++) {
                int r = warp_m + mt * 16 + l16;
                int c = 2 * ks + aCsel;
                ldsm_x4(afrag[mt], stA + r * 128 + ((c ^ (r & 7)) << 4));
            }
#pragma unroll
            for (int ntp = 0; ntp < 4; ntp++) {
                int n = warp_n + ntp * 16 + bRow;
                int c = 2 * ks + bCsel;
                uint32_t q[4];
                ldsm_x4(q, stB + n * 128 + ((c ^ (n & 7)) << 4));
                bfrag[2*ntp][0] = q[0]; bfrag[2*ntp][1] = q[1];
                bfrag[2*ntp+1][0] = q[2]; bfrag[2*ntp+1][1] = q[3];
            }
#pragma unroll
            for (int mt = 0; mt < 4; mt++)
#pragma unroll
                for (int nt = 0; nt < 8; nt++)
                    mma16816(acc.a[mt][nt], afrag[mt], bfrag[nt]);
        }
    }
}

// Fused QKV projection -> hi/lo per-head fp16 outputs.
__global__ __launch_bounds__(128) void gemm_qkv(
    const __half* __restrict__ A, const __half* __restrict__ Wqkv,
    __half* __restrict__ Qhi, __half* __restrict__ Qlo,
    __half* __restrict__ Khi, __half* __restrict__ Klo,
    __half* __restrict__ Vhi, __half* __restrict__ Vlo)
{
    const int row0 = blockIdx.y * 128;
    const int col0 = blockIdx.x * 128;
    GemmAcc acc;
    gemm_mainloop(A, Wqkv, row0, col0, acc);

    const int wid  = threadIdx.x >> 5;
    const int lane = threadIdx.x & 31;
    const int warp_m = (wid & 1) * 64;
    const int warp_n = (wid >> 1) * 64;
    const int lr  = lane >> 2;
    const int lc2 = (lane & 3) * 2;

    const int proj = col0 >> 11;                // 0=Q 1=K 2=V
    const int hh   = (col0 & 2047) >> 7;
    __half* hiP = (proj == 0) ? Qhi : (proj == 1) ? Khi : Vhi;
    __half* loP = (proj == 0) ? Qlo : (proj == 1) ? Klo : Vlo;
    const float scale = (proj == 0) ? 0.08838834764831845f : 1.0f;

#pragma unroll
    for (int mt = 0; mt < 4; mt++) {
        int r = row0 + warp_m + mt * 16 + lr;
        int b = r >> 11, t = r & (SEQ_LEN - 1);
        size_t base0 = ((size_t)(b * NUM_HEADS + hh) * SEQ_LEN + t) * D_HEAD;
        size_t base1 = base0 + 8 * D_HEAD;
#pragma unroll
        for (int nt = 0; nt < 8; nt++) {
            int d = warp_n + nt * 8 + lc2;
            uint32_t h0, l0, h1, l1;
            hilo_pack(acc.a[mt][nt][0] * scale, acc.a[mt][nt][1] * scale, h0, l0);
            hilo_pack(acc.a[mt][nt][2] * scale, acc.a[mt][nt][3] * scale, h1, l1);
            *(uint32_t*)(hiP + base0 + d) = h0;
            *(uint32_t*)(loP + base0 + d) = l0;
            *(uint32_t*)(hiP + base1 + d) = h1;
            *(uint32_t*)(loP + base1 + d) = l1;
        }
    }
}

// Output projection -> fp32 d_out.
__global__ __launch_bounds__(128) void gemm_out(
    const __half* __restrict__ A, const __half* __restrict__ B,
    float* __restrict__ C)
{
    const int row0 = blockIdx.y * 128;
    const int col0 = blockIdx.x * 128;
    GemmAcc acc;
    gemm_mainloop(A, B, row0, col0, acc);

    const int wid  = threadIdx.x >> 5;
    const int lane = threadIdx.x & 31;
    const int warp_m = (wid & 1) * 64;
    const int warp_n = (wid >> 1) * 64;
    const int lr  = lane >> 2;
    const int lc2 = (lane & 3) * 2;
#pragma unroll
    for (int mt = 0; mt < 4; mt++) {
        int r = row0 + warp_m + mt * 16 + lr;
#pragma unroll
        for (int nt = 0; nt < 8; nt++) {
            int c = col0 + warp_n + nt * 8 + lc2;
            *(float2*)(C + (size_t)r * D_MODEL + c)       = make_float2(acc.a[mt][nt][0], acc.a[mt][nt][1]);
            *(float2*)(C + (size_t)(r + 8) * D_MODEL + c) = make_float2(acc.a[mt][nt][2], acc.a[mt][nt][3]);
        }
    }
}

// ---------------------------------------------------------------------------
// Tensor-core causal flash attention, fp16 hi/lo; writes A2 [hi|lo] layout.
// ---------------------------------------------------------------------------
#define BMa 128
#define BNa 64
#define ATT_SMEM (3 * 65536)

__global__ __launch_bounds__(256, 1) void attn_mma(
    const __half* __restrict__ Qhi, const __half* __restrict__ Qlo,
    const __half* __restrict__ Khi, const __half* __restrict__ Klo,
    const __half* __restrict__ Vhi, const __half* __restrict__ Vlo,
    __half* __restrict__ CTX2)
{
    extern __shared__ char smemraw[];
    const uint32_t sb = smem_to_u32(smemraw);
    const int tid = threadIdx.x, wid = tid >> 5, lane = tid & 31;
    const int qb = gridDim.x - 1 - blockIdx.x;
    const int h = blockIdx.y, b = blockIdx.z;
    const int warp_m = wid * 16;

    const size_t head_off = (size_t)(b * NUM_HEADS + h) * SEQ_LEN * D_HEAD;
    const uint32_t sQhi = sb, sQlo = sb + 32768;

    {
        const __half* qhg = Qhi + head_off + (size_t)qb * BMa * D_HEAD;
        const __half* qlg = Qlo + head_off + (size_t)qb * BMa * D_HEAD;
#pragma unroll
        for (int i = 0; i < 8; i++) {
            int id = tid + i * 256;
            int r = id >> 4, c = id & 15;
            uint32_t sw = (uint32_t)((c & 8) | ((c & 7) ^ (r & 7))) << 4;
            cp_async16(sQhi + r * 256 + sw, qhg + r * 128 + c * 8);
            cp_async16(sQlo + r * 256 + sw, qlg + r * 128 + c * 8);
        }
        asm volatile("cp.async.commit_group;" ::: "memory");
    }

    const int nkb = 2 * qb + 2;
    auto issue_kv = [&](int kb, int s) {
        uint32_t st = sb + 65536 + s * 65536;
        const __half* kh = Khi + head_off + (size_t)kb * BNa * D_HEAD;
        const __half* kl = Klo + head_off + (size_t)kb * BNa * D_HEAD;
        const __half* vh = Vhi + head_off + (size_t)kb * BNa * D_HEAD;
        const __half* vl = Vlo + head_off + (size_t)kb * BNa * D_HEAD;
#pragma unroll
        for (int i = 0; i < 4; i++) {
            int id = tid + i * 256;
            int r = id >> 4, c = id & 15;
            uint32_t sw = (uint32_t)((c & 8) | ((c & 7) ^ (r & 7))) << 4;
            uint32_t so = r * 256 + sw;
            int go = r * 128 + c * 8;
            cp_async16(st +         so, kh + go);
            cp_async16(st + 16384 + so, kl + go);
            cp_async16(st + 32768 + so, vh + go);
            cp_async16(st + 49152 + so, vl + go);
        }
        asm volatile("cp.async.commit_group;" ::: "memory");
    };
    issue_kv(0, 0);

    float oacc[16][4];
#pragma unroll
    for (int j = 0; j < 16; j++)
#pragma unroll
        for (int i = 0; i < 4; i++) oacc[j][i] = 0.0f;
    float m0 = -1e30f, m1 = -1e30f, l0 = 0.0f, l1 = 0.0f;
    const int lr = lane >> 2, lc2 = (lane & 3) * 2;

    for (int kb = 0; kb < nkb; kb++) {
        asm volatile("cp.async.wait_group 0;" ::: "memory");
        __syncthreads();
        if (kb + 1 < nkb) issue_kv(kb + 1, (kb + 1) & 1);

        const uint32_t st = sb + 65536 + (kb & 1) * 65536;
        float sacc[8][4];
#pragma unroll
        for (int j = 0; j < 8; j++)
#pragma unroll
            for (int i = 0; i < 4; i++) sacc[j][i] = 0.0f;

#pragma unroll
        for (int pass = 0; pass < 3; pass++) {
            const uint32_t sQ = (pass == 1) ? sQlo : sQhi;
            const uint32_t sK = (pass == 2) ? (st + 16384) : st;
#pragma unroll
            for (int ks = 0; ks < 8; ks++) {
                uint32_t a[4];
                {
                    int r = warp_m + (lane & 15);
                    int c = 2 * ks + (lane >> 4);
                    uint32_t sw = (uint32_t)((c & 8) | ((c & 7) ^ (r & 7))) << 4;
                    ldsm_x4(a, sQ + r * 256 + sw);
                }
                uint32_t bf[8][2];
#pragma unroll
                for (int g4 = 0; g4 < 4; g4++) {
                    int n = g4 * 16 + (lane & 7) + ((lane & 16) >> 1);
                    int c = 2 * ks + ((lane >> 3) & 1);
                    uint32_t sw = (uint32_t)((c & 8) | ((c & 7) ^ (n & 7))) << 4;
                    uint32_t q[4];
                    ldsm_x4(q, sK + n * 256 + sw);
                    bf[2*g4][0] = q[0]; bf[2*g4][1] = q[1];
                    bf[2*g4+1][0] = q[2]; bf[2*g4+1][1] = q[3];
                }
#pragma unroll
                for (int j = 0; j < 8; j++) mma16816(sacc[j], a, bf[j]);
            }
        }

        if (kb >= 2 * qb) {
            const int diag = kb * BNa - qb * BMa;
            const int ra = warp_m + lr, rb = ra + 8;
#pragma unroll
            for (int j = 0; j < 8; j++) {
                int colb = diag + 8 * j + lc2;
                if (colb     > ra) sacc[j][0] = -1e30f;
                if (colb + 1 > ra) sacc[j][1] = -1e30f;
                if (colb     > rb) sacc[j][2] = -1e30f;
                if (colb + 1 > rb) sacc[j][3] = -1e30f;
            }
        }

        float rmx0 = -1e30f, rmx1 = -1e30f;
#pragma unroll
        for (int j = 0; j < 8; j++) {
            rmx0 = fmaxf(rmx0, fmaxf(sacc[j][0], sacc[j][1]));
            rmx1 = fmaxf(rmx1, fmaxf(sacc[j][2], sacc[j][3]));
        }
        rmx0 = fmaxf(rmx0, __shfl_xor_sync(0xffffffffu, rmx0, 1));
        rmx0 = fmaxf(rmx0, __shfl_xor_sync(0xffffffffu, rmx0, 2));
        rmx1 = fmaxf(rmx1, __shfl_xor_sync(0xffffffffu, rmx1, 1));
        rmx1 = fmaxf(rmx1, __shfl_xor_sync(0xffffffffu, rmx1, 2));
        float mn0 = fmaxf(m0, rmx0), mn1 = fmaxf(m1, rmx1);
        float c0 = __expf(m0 - mn0), c1 = __expf(m1 - mn1);
        m0 = mn0; m1 = mn1;
        float ps0 = 0.0f, ps1 = 0.0f;
#pragma unroll
        for (int j = 0; j < 8; j++) {
            sacc[j][0] = __expf(sacc[j][0] - mn0); ps0 += sacc[j][0];
            sacc[j][1] = __expf(sacc[j][1] - mn0); ps0 += sacc[j][1];
            sacc[j][2] = __expf(sacc[j][2] - mn1); ps1 += sacc[j][2];
            sacc[j][3] = __expf(sacc[j][3] - mn1); ps1 += sacc[j][3];
        }
        l0 = l0 * c0 + ps0;
        l1 = l1 * c1 + ps1;
#pragma unroll
        for (int j = 0; j < 16; j++) {
            oacc[j][0] *= c0; oacc[j][1] *= c0;
            oacc[j][2] *= c1; oacc[j][3] *= c1;
        }

        const uint32_t sVhi = st + 32768, sVlo = st + 49152;
#pragma unroll
        for (int s = 0; s < 4; s++) {
            uint32_t phi[4], plo[4];
            hilo_pack(sacc[2*s][0],   sacc[2*s][1],   phi[0], plo[0]);
            hilo_pack(sacc[2*s][2],   sacc[2*s][3],   phi[1], plo[1]);
            hilo_pack(sacc[2*s+1][0], sacc[2*s+1][1], phi[2], plo[2]);
            hilo_pack(sacc[2*s+1][2], sacc[2*s+1][3], phi[3], plo[3]);

            uint32_t bv[16][2];
            const int mid = lane >> 3;
#pragma unroll
            for (int g = 0; g < 8; g++) {
                int r = s * 16 + 8 * (mid & 1) + (lane & 7);
                int c = 2 * g + (mid >> 1);
                uint32_t sw = (uint32_t)((c & 8) | ((c & 7) ^ (r & 7))) << 4;
                uint32_t q[4];
                ldsm_x4_t(q, sVhi + r * 256 + sw);
                bv[2*g][0] = q[0]; bv[2*g][1] = q[1];
                bv[2*g+1][0] = q[2]; bv[2*g+1][1] = q[3];
            }
#pragma unroll
            for (int j = 0; j < 16; j++) mma16816(oacc[j], phi, bv[j]);
#pragma unroll
            for (int j = 0; j < 16; j++) mma16816(oacc[j], plo, bv[j]);
#pragma unroll
            for (int g = 0; g < 8; g++) {
                int r = s * 16 + 8 * (mid & 1) + (lane & 7);
                int c = 2 * g + (mid >> 1);
                uint32_t sw = (uint32_t)((c & 8) | ((c & 7) ^ (r & 7))) << 4;
                uint32_t q[4];
                ldsm_x4_t(q, sVlo + r * 256 + sw);
                bv[2*g][0] = q[0]; bv[2*g][1] = q[1];
                bv[2*g+1][0] = q[2]; bv[2*g+1][1] = q[3];
            }
#pragma unroll
            for (int j = 0; j < 16; j++) mma16816(oacc[j], phi, bv[j]);
        }
    }

    l0 += __shfl_xor_sync(0xffffffffu, l0, 1);
    l0 += __shfl_xor_sync(0xffffffffu, l0, 2);
    l1 += __shfl_xor_sync(0xffffffffu, l1, 1);
    l1 += __shfl_xor_sync(0xffffffffu, l1, 2);
    const float il0 = 1.0f / l0, il1 = 1.0f / l1;

    // write [hi|lo] A2 layout (row = b*SEQ + token, col = h*128 + d)
    const int ra = qb * BMa + warp_m + lr;
    size_t base0 = ((size_t)(b * SEQ_LEN) + ra) * KP2 + h * D_HEAD;
    size_t base1 = base0 + (size_t)8 * KP2;
#pragma unroll
    for (int j = 0; j < 16; j++) {
        int d = 8 * j + lc2;
        uint32_t h2, l2;
        hilo_pack(oacc[j][0] * il0, oacc[j][1] * il0, h2, l2);
        *(uint32_t*)(CTX2 + base0 + d)           = h2;
        *(uint32_t*)(CTX2 + base0 + D_MODEL + d) = l2;
        hilo_pack(oacc[j][2] * il1, oacc[j][3] * il1, h2, l2);
        *(uint32_t*)(CTX2 + base1 + d)           = h2;
        *(uint32_t*)(CTX2 + base1 + D_MODEL + d) = l2;
    }
}

// ---------------------------------------------------------------------------
// Launch
// ---------------------------------------------------------------------------
extern "C" void kernel_launch(void* const* d_in, const int* in_sizes, int n_in,
                              void* d_out, int out_size)
{
    const float* x     = (const float*)d_in[0];
    const float* q_w   = (const float*)d_in[1];
    const float* k_w   = (const float*)d_in[2];
    const float* v_w   = (const float*)d_in[3];
    const float* w_out = (const float*)d_in[4];
    float* out = (float*)d_out;

    __half *A2, *Wqkv2, *Wo2;
    __half *Qhi, *Qlo, *Khi, *Klo, *Vhi, *Vlo;
    cudaGetSymbolAddress((void**)&A2,    g_A2);
    cudaGetSymbolAddress((void**)&Wqkv2, g_Wqkv2);
    cudaGetSymbolAddress((void**)&Wo2,   g_Wo2);
    cudaGetSymbolAddress((void**)&Qhi, g_Qhi);
    cudaGetSymbolAddress((void**)&Qlo, g_Qlo);
    cudaGetSymbolAddress((void**)&Khi, g_Khi);
    cudaGetSymbolAddress((void**)&Klo, g_Klo);
    cudaGetSymbolAddress((void**)&Vhi, g_Vhi);
    cudaGetSymbolAddress((void**)&Vlo, g_Vlo);

    cudaFuncSetAttribute(gemm_qkv, cudaFuncAttributeMaxDynamicSharedMemorySize, GEMM_SMEM);
    cudaFuncSetAttribute(gemm_out, cudaFuncAttributeMaxDynamicSharedMemorySize, GEMM_SMEM);
    cudaFuncSetAttribute(attn_mma, cudaFuncAttributeMaxDynamicSharedMemorySize, ATT_SMEM);

    // 1. weight transpose/convert (one launch) + activation split
    dim3 wgrid(D_MODEL / 32, D_MODEL / 32, 4);
    split_wt_all<<<wgrid, 256>>>(q_w, k_w, v_w, w_out, Wqkv2, Wo2);
    int act_blocks = (MROWS * (D_MODEL / 4)) / 256;
    split_act<<<act_blocks, 256>>>(x, A2);

    // 2. fused QKV projection (2-term fp16, K=4096)
    dim3 qkvgrid(NQKV / 128, MROWS / 128);        // (48, 32)
    gemm_qkv<<<qkvgrid, 128, GEMM_SMEM>>>(A2, Wqkv2,
                                          Qhi, Qlo, Khi, Klo, Vhi, Vlo);

    // 3. tensor-core causal attention -> writes A2 [hi|lo]
    dim3 agrid(SEQ_LEN / BMa, NUM_HEADS, BATCH);
    attn_mma<<<agrid, 256, ATT_SMEM>>>(Qhi, Qlo, Khi, Klo, Vhi, Vlo, A2);

    // 4. output projection (2-term fp16)
    dim3 ogrid(D_MODEL / 128, MROWS / 128);       // (16, 32)
    gemm_out<<<ogrid, 128, GEMM_SMEM>>>(A2, Wo2, out);
}

// round 12
// speedup vs baseline: 19.5559x; 1.6202x over previous
#include <cuda_runtime.h>
#include <cuda_fp16.h>
#include <math_constants.h>
#include <cstdint>

#define D_MODEL   2048
#define NUM_HEADS 16
#define SEQ_LEN   2048
#define BATCH     2
#define D_HEAD    128
#define MROWS     (BATCH * SEQ_LEN)     // 4096
#define NQKV      (3 * D_MODEL)

// ---------------------------------------------------------------------------
// Scratch
// ---------------------------------------------------------------------------
__device__ __half g_A[(size_t)MROWS * D_MODEL];         // x / ctx, fp16
__device__ __half g_Wqkv[(size_t)NQKV * D_MODEL];       // Wq|Wk|Wv transposed [n][k]
__device__ __half g_Wo[(size_t)D_MODEL * D_MODEL];      // W_out transposed [n][k]
#define HSZ ((size_t)BATCH * NUM_HEADS * SEQ_LEN * D_HEAD)
__device__ __half g_Qhi[HSZ];
__device__ __half g_Qlo[HSZ];
__device__ __half g_Khi[HSZ];
__device__ __half g_Klo[HSZ];
__device__ __half g_Vhi[HSZ];
__device__ __half g_Vlo[HSZ];

__device__ __forceinline__ uint32_t smem_to_u32(const void* p) {
    uint32_t a;
    asm("{ .reg .u64 t; cvta.to.shared.u64 t, %1; cvt.u32.u64 %0, t; }" : "=r"(a) : "l"(p));
    return a;
}
__device__ __forceinline__ void mma16816(
    float* c, const uint32_t* a, const uint32_t* b)
{
    asm volatile(
        "mma.sync.aligned.m16n8k16.row.col.f32.f16.f16.f32 "
        "{%0,%1,%2,%3}, {%4,%5,%6,%7}, {%8,%9}, {%0,%1,%2,%3};"
        : "+f"(c[0]), "+f"(c[1]), "+f"(c[2]), "+f"(c[3])
        : "r"(a[0]), "r"(a[1]), "r"(a[2]), "r"(a[3]), "r"(b[0]), "r"(b[1]));
}
__device__ __forceinline__ void ldsm_x4(uint32_t* r, uint32_t addr)
{
    asm volatile("ldmatrix.sync.aligned.m8n8.x4.shared.b16 {%0,%1,%2,%3}, [%4];"
                 : "=r"(r[0]), "=r"(r[1]), "=r"(r[2]), "=r"(r[3]) : "r"(addr));
}
__device__ __forceinline__ void ldsm_x4_t(uint32_t* r, uint32_t addr)
{
    asm volatile("ldmatrix.sync.aligned.m8n8.x4.trans.shared.b16 {%0,%1,%2,%3}, [%4];"
                 : "=r"(r[0]), "=r"(r[1]), "=r"(r[2]), "=r"(r[3]) : "r"(addr));
}
__device__ __forceinline__ void cp_async16(uint32_t dst, const void* src)
{
    asm volatile("cp.async.cg.shared.global [%0], [%1], 16;" :: "r"(dst), "l"(src));
}
__device__ __forceinline__ void hilo_pack(float x0, float x1, uint32_t& h, uint32_t& l)
{
    __half h0 = __float2half_rn(x0), h1 = __float2half_rn(x1);
    __half l0 = __float2half_rn(x0 - __half2float(h0));
    __half l1 = __float2half_rn(x1 - __half2float(h1));
    __half2 H = __halves2half2(h0, h1);
    __half2 L = __halves2half2(l0, l1);
    h = *(uint32_t*)&H; l = *(uint32_t*)&L;
}

// ---------------------------------------------------------------------------
// Conversions
// ---------------------------------------------------------------------------
// x [m][2048] fp32 -> fp16
__global__ __launch_bounds__(256) void conv_act(
    const float* __restrict__ src, __half* __restrict__ dst)
{
    int t = blockIdx.x * blockDim.x + threadIdx.x;
    float4 v = *(const float4*)(src + (size_t)t * 4);
    __half2 a = __floats2half2_rn(v.x, v.y);
    __half2 b = __floats2half2_rn(v.z, v.w);
    *(uint32_t*)(dst + (size_t)t * 4)     = *(uint32_t*)&a;
    *(uint32_t*)(dst + (size_t)t * 4 + 2) = *(uint32_t*)&b;
}

// all 4 weights: transpose [k][n] -> [n][k] fp16
__global__ __launch_bounds__(256) void conv_wt_all(
    const float* __restrict__ Wq, const float* __restrict__ Wk,
    const float* __restrict__ Wv, const float* __restrict__ Wo,
    __half* __restrict__ Wqkv, __half* __restrict__ Wout)
{
    __shared__ float tile[32][33];
    const int z = blockIdx.z;
    const float* W = (z == 0) ? Wq : (z == 1) ? Wk : (z == 2) ? Wv : Wo;
    __half* dst = (z < 3) ? (Wqkv + (size_t)z * D_MODEL * D_MODEL) : Wout;

    int tx = threadIdx.x & 31, ty = threadIdx.x >> 5;
    int n0 = blockIdx.x * 32, k0 = blockIdx.y * 32;
#pragma unroll
    for (int j = 0; j < 4; j++)
        tile[ty + 8*j][tx] = W[(size_t)(k0 + ty + 8*j) * D_MODEL + n0 + tx];
    __syncthreads();
#pragma unroll
    for (int j = 0; j < 4; j++) {
        int n = n0 + ty + 8*j;
        dst[(size_t)n * D_MODEL + k0 + tx] = __float2half_rn(tile[tx][ty + 8*j]);
    }
}

// ---------------------------------------------------------------------------
// Pipelined mma.sync fp16 GEMM core. K=2048 (1-term).
// CTA 128x128, BK=64, 4 warps 64x64, 3-stage cp.async.
// ---------------------------------------------------------------------------
#define BKg 64
#define NCH1 (D_MODEL / BKg)            // 32
#define STAGE_BYTES 32768
#define GEMM_SMEM (3 * STAGE_BYTES)

struct GemmAcc { float a[4][8][4]; };

__device__ __forceinline__ void gemm_mainloop(
    const __half* __restrict__ A, const __half* __restrict__ B,
    int row0, int col0, GemmAcc& acc)
{
    extern __shared__ char gsm[];
    const uint32_t smem_base = smem_to_u32(gsm);
    const int tid  = threadIdx.x;
    const int wid  = tid >> 5;
    const int lane = tid & 31;
    const int warp_m = (wid & 1) * 64;
    const int warp_n = (wid >> 1) * 64;

#pragma unroll
    for (int mt = 0; mt < 4; mt++)
#pragma unroll
        for (int nt = 0; nt < 8; nt++)
#pragma unroll
            for (int i = 0; i < 4; i++) acc.a[mt][nt][i] = 0.0f;

    const __half* Abase = A + (size_t)row0 * D_MODEL;
    const __half* Bbase = B + (size_t)col0 * D_MODEL;

    auto issue_stage = [&](int kc, int s) {
        const uint32_t stA = smem_base + s * STAGE_BYTES;
        const uint32_t stB = stA + 16384;
        const __half* gA = Abase + (size_t)kc * BKg;
        const __half* gB = Bbase + (size_t)kc * BKg;
#pragma unroll
        for (int i = 0; i < 8; i++) {
            int id = tid + i * 128;
            int r = id >> 3, c = id & 7;
            uint32_t soff = r * 128 + ((c ^ (r & 7)) << 4);
            cp_async16(stA + soff, gA + (size_t)r * D_MODEL + c * 8);
            cp_async16(stB + soff, gB + (size_t)r * D_MODEL + c * 8);
        }
        asm volatile("cp.async.commit_group;" ::: "memory");
    };

    issue_stage(0, 0);
    issue_stage(1, 1);

    const int l16   = lane & 15;
    const int aCsel = lane >> 4;
    const int bRow  = (lane & 7) + ((lane & 16) >> 1);
    const int bCsel = (lane >> 3) & 1;

    for (int kc = 0; kc < NCH1; kc++) {
        if (kc + 2 < NCH1) { asm volatile("cp.async.wait_group 1;" ::: "memory"); }
        else               { asm volatile("cp.async.wait_group 0;" ::: "memory"); }
        __syncthreads();
        if (kc + 2 < NCH1) issue_stage(kc + 2, (kc + 2) % 3);

        const int s = kc % 3;
        const uint32_t stA = smem_base + s * STAGE_BYTES;
        const uint32_t stB = stA + 16384;

#pragma unroll
        for (int ks = 0; ks < 4; ks++) {
            uint32_t afrag[4][4], bfrag[8][2];
#pragma unroll
            for (int mt = 0; mt < 4; mt++) {
                int r = warp_m + mt * 16 + l16;
                int c = 2 * ks + aCsel;
                ldsm_x4(afrag[mt], stA + r * 128 + ((c ^ (r & 7)) << 4));
            }
#pragma unroll
            for (int ntp = 0; ntp < 4; ntp++) {
                int n = warp_n + ntp * 16 + bRow;
                int c = 2 * ks + bCsel;
                uint32_t q[4];
                ldsm_x4(q, stB + n * 128 + ((c ^ (n & 7)) << 4));
                bfrag[2*ntp][0] = q[0]; bfrag[2*ntp][1] = q[1];
                bfrag[2*ntp+1][0] = q[2]; bfrag[2*ntp+1][1] = q[3];
            }
#pragma unroll
            for (int mt = 0; mt < 4; mt++)
#pragma unroll
                for (int nt = 0; nt < 8; nt++)
                    mma16816(acc.a[mt][nt], afrag[mt], bfrag[nt]);
        }
    }
}

// Fused QKV projection -> hi/lo per-head fp16 outputs (exact split of fp32 acc).
__global__ __launch_bounds__(128) void gemm_qkv(
    const __half* __restrict__ A, const __half* __restrict__ Wqkv,
    __half* __restrict__ Qhi, __half* __restrict__ Qlo,
    __half* __restrict__ Khi, __half* __restrict__ Klo,
    __half* __restrict__ Vhi, __half* __restrict__ Vlo)
{
    const int row0 = blockIdx.y * 128;
    const int col0 = blockIdx.x * 128;
    GemmAcc acc;
    gemm_mainloop(A, Wqkv, row0, col0, acc);

    const int wid  = threadIdx.x >> 5;
    const int lane = threadIdx.x & 31;
    const int warp_m = (wid & 1) * 64;
    const int warp_n = (wid >> 1) * 64;
    const int lr  = lane >> 2;
    const int lc2 = (lane & 3) * 2;

    const int proj = col0 >> 11;                // 0=Q 1=K 2=V
    const int hh   = (col0 & 2047) >> 7;
    __half* hiP = (proj == 0) ? Qhi : (proj == 1) ? Khi : Vhi;
    __half* loP = (proj == 0) ? Qlo : (proj == 1) ? Klo : Vlo;
    const float scale = (proj == 0) ? 0.08838834764831845f : 1.0f;

#pragma unroll
    for (int mt = 0; mt < 4; mt++) {
        int r = row0 + warp_m + mt * 16 + lr;
        int b = r >> 11, t = r & (SEQ_LEN - 1);
        size_t base0 = ((size_t)(b * NUM_HEADS + hh) * SEQ_LEN + t) * D_HEAD;
        size_t base1 = base0 + 8 * D_HEAD;
#pragma unroll
        for (int nt = 0; nt < 8; nt++) {
            int d = warp_n + nt * 8 + lc2;
            uint32_t h0, l0, h1, l1;
            hilo_pack(acc.a[mt][nt][0] * scale, acc.a[mt][nt][1] * scale, h0, l0);
            hilo_pack(acc.a[mt][nt][2] * scale, acc.a[mt][nt][3] * scale, h1, l1);
            *(uint32_t*)(hiP + base0 + d) = h0;
            *(uint32_t*)(loP + base0 + d) = l0;
            *(uint32_t*)(hiP + base1 + d) = h1;
            *(uint32_t*)(loP + base1 + d) = l1;
        }
    }
}

// Output projection -> fp32 d_out.
__global__ __launch_bounds__(128) void gemm_out(
    const __half* __restrict__ A, const __half* __restrict__ B,
    float* __restrict__ C)
{
    const int row0 = blockIdx.y * 128;
    const int col0 = blockIdx.x * 128;
    GemmAcc acc;
    gemm_mainloop(A, B, row0, col0, acc);

    const int wid  = threadIdx.x >> 5;
    const int lane = threadIdx.x & 31;
    const int warp_m = (wid & 1) * 64;
    const int warp_n = (wid >> 1) * 64;
    const int lr  = lane >> 2;
    const int lc2 = (lane & 3) * 2;
#pragma unroll
    for (int mt = 0; mt < 4; mt++) {
        int r = row0 + warp_m + mt * 16 + lr;
#pragma unroll
        for (int nt = 0; nt < 8; nt++) {
            int c = col0 + warp_n + nt * 8 + lc2;
            *(float2*)(C + (size_t)r * D_MODEL + c)       = make_float2(acc.a[mt][nt][0], acc.a[mt][nt][1]);
            *(float2*)(C + (size_t)(r + 8) * D_MODEL + c) = make_float2(acc.a[mt][nt][2], acc.a[mt][nt][3]);
        }
    }
}

// ---------------------------------------------------------------------------
// Tensor-core causal flash attention, fp16 hi/lo 3-pass; writes fp16 ctx.
// Grid: (NUM_HEADS, SEQ/BMa, BATCH) with qb reversed on y (heavy first).
// ---------------------------------------------------------------------------
#define BMa 128
#define BNa 64
#define ATT_SMEM (3 * 65536)

__global__ __launch_bounds__(256, 1) void attn_mma(
    const __half* __restrict__ Qhi, const __half* __restrict__ Qlo,
    const __half* __restrict__ Khi, const __half* __restrict__ Klo,
    const __half* __restrict__ Vhi, const __half* __restrict__ Vlo,
    __half* __restrict__ CTX)
{
    extern __shared__ char smemraw[];
    const uint32_t sb = smem_to_u32(smemraw);
    const int tid = threadIdx.x, wid = tid >> 5, lane = tid & 31;
    const int h  = blockIdx.x;
    const int qb = gridDim.y - 1 - blockIdx.y;   // heavy blocks first chip-wide
    const int b  = blockIdx.z;
    const int warp_m = wid * 16;

    const size_t head_off = (size_t)(b * NUM_HEADS + h) * SEQ_LEN * D_HEAD;
    const uint32_t sQhi = sb, sQlo = sb + 32768;

    {
        const __half* qhg = Qhi + head_off + (size_t)qb * BMa * D_HEAD;
        const __half* qlg = Qlo + head_off + (size_t)qb * BMa * D_HEAD;
#pragma unroll
        for (int i = 0; i < 8; i++) {
            int id = tid + i * 256;
            int r = id >> 4, c = id & 15;
            uint32_t sw = (uint32_t)((c & 8) | ((c & 7) ^ (r & 7))) << 4;
            cp_async16(sQhi + r * 256 + sw, qhg + r * 128 + c * 8);
            cp_async16(sQlo + r * 256 + sw, qlg + r * 128 + c * 8);
        }
        asm volatile("cp.async.commit_group;" ::: "memory");
    }

    const int nkb = 2 * qb + 2;
    auto issue_kv = [&](int kb, int s) {
        uint32_t st = sb + 65536 + s * 65536;
        const __half* kh = Khi + head_off + (size_t)kb * BNa * D_HEAD;
        const __half* kl = Klo + head_off + (size_t)kb * BNa * D_HEAD;
        const __half* vh = Vhi + head_off + (size_t)kb * BNa * D_HEAD;
        const __half* vl = Vlo + head_off + (size_t)kb * BNa * D_HEAD;
#pragma unroll
        for (int i = 0; i < 4; i++) {
            int id = tid + i * 256;
            int r = id >> 4, c = id & 15;
            uint32_t sw = (uint32_t)((c & 8) | ((c & 7) ^ (r & 7))) << 4;
            uint32_t so = r * 256 + sw;
            int go = r * 128 + c * 8;
            cp_async16(st +         so, kh + go);
            cp_async16(st + 16384 + so, kl + go);
            cp_async16(st + 32768 + so, vh + go);
            cp_async16(st + 49152 + so, vl + go);
        }
        asm volatile("cp.async.commit_group;" ::: "memory");
    };
    issue_kv(0, 0);

    float oacc[16][4];
#pragma unroll
    for (int j = 0; j < 16; j++)
#pragma unroll
        for (int i = 0; i < 4; i++) oacc[j][i] = 0.0f;
    float m0 = -1e30f, m1 = -1e30f, l0 = 0.0f, l1 = 0.0f;
    const int lr = lane >> 2, lc2 = (lane & 3) * 2;

    for (int kb = 0; kb < nkb; kb++) {
        asm volatile("cp.async.wait_group 0;" ::: "memory");
        __syncthreads();
        if (kb + 1 < nkb) issue_kv(kb + 1, (kb + 1) & 1);

        const uint32_t st = sb + 65536 + (kb & 1) * 65536;
        float sacc[8][4];
#pragma unroll
        for (int j = 0; j < 8; j++)
#pragma unroll
            for (int i = 0; i < 4; i++) sacc[j][i] = 0.0f;

#pragma unroll
        for (int pass = 0; pass < 3; pass++) {
            const uint32_t sQ = (pass == 1) ? sQlo : sQhi;
            const uint32_t sK = (pass == 2) ? (st + 16384) : st;
#pragma unroll
            for (int ks = 0; ks < 8; ks++) {
                uint32_t a[4];
                {
                    int r = warp_m + (lane & 15);
                    int c = 2 * ks + (lane >> 4);
                    uint32_t sw = (uint32_t)((c & 8) | ((c & 7) ^ (r & 7))) << 4;
                    ldsm_x4(a, sQ + r * 256 + sw);
                }
                uint32_t bf[8][2];
#pragma unroll
                for (int g4 = 0; g4 < 4; g4++) {
                    int n = g4 * 16 + (lane & 7) + ((lane & 16) >> 1);
                    int c = 2 * ks + ((lane >> 3) & 1);
                    uint32_t sw = (uint32_t)((c & 8) | ((c & 7) ^ (n & 7))) << 4;
                    uint32_t q[4];
                    ldsm_x4(q, sK + n * 256 + sw);
                    bf[2*g4][0] = q[0]; bf[2*g4][1] = q[1];
                    bf[2*g4+1][0] = q[2]; bf[2*g4+1][1] = q[3];
                }
#pragma unroll
                for (int j = 0; j < 8; j++) mma16816(sacc[j], a, bf[j]);
            }
        }

        if (kb >= 2 * qb) {
            const int diag = kb * BNa - qb * BMa;
            const int ra = warp_m + lr, rb = ra + 8;
#pragma unroll
            for (int j = 0; j < 8; j++) {
                int colb = diag + 8 * j + lc2;
                if (colb     > ra) sacc[j][0] = -1e30f;
                if (colb + 1 > ra) sacc[j][1] = -1e30f;
                if (colb     > rb) sacc[j][2] = -1e30f;
                if (colb + 1 > rb) sacc[j][3] = -1e30f;
            }
        }

        float rmx0 = -1e30f, rmx1 = -1e30f;
#pragma unroll
        for (int j = 0; j < 8; j++) {
            rmx0 = fmaxf(rmx0, fmaxf(sacc[j][0], sacc[j][1]));
            rmx1 = fmaxf(rmx1, fmaxf(sacc[j][2], sacc[j][3]));
        }
        rmx0 = fmaxf(rmx0, __shfl_xor_sync(0xffffffffu, rmx0, 1));
        rmx0 = fmaxf(rmx0, __shfl_xor_sync(0xffffffffu, rmx0, 2));
        rmx1 = fmaxf(rmx1, __shfl_xor_sync(0xffffffffu, rmx1, 1));
        rmx1 = fmaxf(rmx1, __shfl_xor_sync(0xffffffffu, rmx1, 2));
        float mn0 = fmaxf(m0, rmx0), mn1 = fmaxf(m1, rmx1);
        float c0 = __expf(m0 - mn0), c1 = __expf(m1 - mn1);
        m0 = mn0; m1 = mn1;
        float ps0 = 0.0f, ps1 = 0.0f;
#pragma unroll
        for (int j = 0; j < 8; j++) {
            sacc[j][0] = __expf(sacc[j][0] - mn0); ps0 += sacc[j][0];
            sacc[j][1] = __expf(sacc[j][1] - mn0); ps0 += sacc[j][1];
            sacc[j][2] = __expf(sacc[j][2] - mn1); ps1 += sacc[j][2];
            sacc[j][3] = __expf(sacc[j][3] - mn1); ps1 += sacc[j][3];
        }
        l0 = l0 * c0 + ps0;
        l1 = l1 * c1 + ps1;
#pragma unroll
        for (int j = 0; j < 16; j++) {
            oacc[j][0] *= c0; oacc[j][1] *= c0;
            oacc[j][2] *= c1; oacc[j][3] *= c1;
        }

        const uint32_t sVhi = st + 32768, sVlo = st + 49152;
#pragma unroll
        for (int s = 0; s < 4; s++) {
            uint32_t phi[4], plo[4];
            hilo_pack(sacc[2*s][0],   sacc[2*s][1],   phi[0], plo[0]);
            hilo_pack(sacc[2*s][2],   sacc[2*s][3],   phi[1], plo[1]);
            hilo_pack(sacc[2*s+1][0], sacc[2*s+1][1], phi[2], plo[2]);
            hilo_pack(sacc[2*s+1][2], sacc[2*s+1][3], phi[3], plo[3]);

            uint32_t bv[16][2];
            const int mid = lane >> 3;
#pragma unroll
            for (int g = 0; g < 8; g++) {
                int r = s * 16 + 8 * (mid & 1) + (lane & 7);
                int c = 2 * g + (mid >> 1);
                uint32_t sw = (uint32_t)((c & 8) | ((c & 7) ^ (r & 7))) << 4;
                uint32_t q[4];
                ldsm_x4_t(q, sVhi + r * 256 + sw);
                bv[2*g][0] = q[0]; bv[2*g][1] = q[1];
                bv[2*g+1][0] = q[2]; bv[2*g+1][1] = q[3];
            }
#pragma unroll
            for (int j = 0; j < 16; j++) mma16816(oacc[j], phi, bv[j]);
#pragma unroll
            for (int j = 0; j < 16; j++) mma16816(oacc[j], plo, bv[j]);
#pragma unroll
            for (int g = 0; g < 8; g++) {
                int r = s * 16 + 8 * (mid & 1) + (lane & 7);
                int c = 2 * g + (mid >> 1);
                uint32_t sw = (uint32_t)((c & 8) | ((c & 7) ^ (r & 7))) << 4;
                uint32_t q[4];
                ldsm_x4_t(q, sVlo + r * 256 + sw);
                bv[2*g][0] = q[0]; bv[2*g][1] = q[1];
                bv[2*g+1][0] = q[2]; bv[2*g+1][1] = q[3];
            }
#pragma unroll
            for (int j = 0; j < 16; j++) mma16816(oacc[j], phi, bv[j]);
        }
    }

    l0 += __shfl_xor_sync(0xffffffffu, l0, 1);
    l0 += __shfl_xor_sync(0xffffffffu, l0, 2);
    l1 += __shfl_xor_sync(0xffffffffu, l1, 1);
    l1 += __shfl_xor_sync(0xffffffffu, l1, 2);
    const float il0 = 1.0f / l0, il1 = 1.0f / l1;

    // write fp16 ctx (row = b*SEQ + token, col = h*128 + d)
    const int ra = qb * BMa + warp_m + lr;
    size_t base0 = ((size_t)(b * SEQ_LEN) + ra) * D_MODEL + h * D_HEAD;
    size_t base1 = base0 + (size_t)8 * D_MODEL;
#pragma unroll
    for (int j = 0; j < 16; j++) {
        int d = 8 * j + lc2;
        __half2 v0 = __floats2half2_rn(oacc[j][0] * il0, oacc[j][1] * il0);
        __half2 v1 = __floats2half2_rn(oacc[j][2] * il1, oacc[j][3] * il1);
        *(uint32_t*)(CTX + base0 + d) = *(uint32_t*)&v0;
        *(uint32_t*)(CTX + base1 + d) = *(uint32_t*)&v1;
    }
}

// ---------------------------------------------------------------------------
// Launch
// ---------------------------------------------------------------------------
extern "C" void kernel_launch(void* const* d_in, const int* in_sizes, int n_in,
                              void* d_out, int out_size)
{
    const float* x     = (const float*)d_in[0];
    const float* q_w   = (const float*)d_in[1];
    const float* k_w   = (const float*)d_in[2];
    const float* v_w   = (const float*)d_in[3];
    const float* w_out = (const float*)d_in[4];
    float* out = (float*)d_out;

    __half *A, *Wqkv, *Wo;
    __half *Qhi, *Qlo, *Khi, *Klo, *Vhi, *Vlo;
    cudaGetSymbolAddress((void**)&A,    g_A);
    cudaGetSymbolAddress((void**)&Wqkv, g_Wqkv);
    cudaGetSymbolAddress((void**)&Wo,   g_Wo);
    cudaGetSymbolAddress((void**)&Qhi, g_Qhi);
    cudaGetSymbolAddress((void**)&Qlo, g_Qlo);
    cudaGetSymbolAddress((void**)&Khi, g_Khi);
    cudaGetSymbolAddress((void**)&Klo, g_Klo);
    cudaGetSymbolAddress((void**)&Vhi, g_Vhi);
    cudaGetSymbolAddress((void**)&Vlo, g_Vlo);

    cudaFuncSetAttribute(gemm_qkv, cudaFuncAttributeMaxDynamicSharedMemorySize, GEMM_SMEM);
    cudaFuncSetAttribute(gemm_out, cudaFuncAttributeMaxDynamicSharedMemorySize, GEMM_SMEM);
    cudaFuncSetAttribute(attn_mma, cudaFuncAttributeMaxDynamicSharedMemorySize, ATT_SMEM);

    // 1. weight transpose/convert + activation convert
    dim3 wgrid(D_MODEL / 32, D_MODEL / 32, 4);
    conv_wt_all<<<wgrid, 256>>>(q_w, k_w, v_w, w_out, Wqkv, Wo);
    conv_act<<<(MROWS * D_MODEL / 4) / 256, 256>>>(x, A);

    // 2. fused QKV projection (1-term fp16, K=2048)
    dim3 qkvgrid(NQKV / 128, MROWS / 128);        // (48, 32)
    gemm_qkv<<<qkvgrid, 128, GEMM_SMEM>>>(A, Wqkv,
                                          Qhi, Qlo, Khi, Klo, Vhi, Vlo);

    // 3. tensor-core causal attention -> fp16 ctx into A
    dim3 agrid(NUM_HEADS, SEQ_LEN / BMa, BATCH);  // (16,16,2), heavy qb first
    attn_mma<<<agrid, 256, ATT_SMEM>>>(Qhi, Qlo, Khi, Klo, Vhi, Vlo, A);

    // 4. output projection (1-term fp16)
    dim3 ogrid(D_MODEL / 128, MROWS / 128);       // (16, 32)
    gemm_out<<<ogrid, 128, GEMM_SMEM>>>(A, Wo, out);
}

// round 15
// speedup vs baseline: 21.7934x; 1.1144x over previous
#include <cuda_runtime.h>
#include <cuda_fp16.h>
#include <math_constants.h>
#include <cstdint>

#define D_MODEL   2048
#define NUM_HEADS 16
#define SEQ_LEN   2048
#define BATCH     2
#define D_HEAD    128
#define MROWS     (BATCH * SEQ_LEN)     // 4096
#define NQKV      (3 * D_MODEL)

// ---------------------------------------------------------------------------
// Scratch
// ---------------------------------------------------------------------------
__device__ __half g_A[(size_t)MROWS * D_MODEL];         // x / ctx, fp16
__device__ __half g_Wqkv[(size_t)NQKV * D_MODEL];       // Wq|Wk|Wv transposed [n][k]
__device__ __half g_Wo[(size_t)D_MODEL * D_MODEL];      // W_out transposed [n][k]
#define HSZ ((size_t)BATCH * NUM_HEADS * SEQ_LEN * D_HEAD)
__device__ __half g_Qhi[HSZ];
__device__ __half g_Qlo[HSZ];
__device__ __half g_Khi[HSZ];                            // K hi-only (lo dropped)
__device__ __half g_Vhi[HSZ];                            // V hi-only (lo dropped)

__device__ __forceinline__ uint32_t smem_to_u32(const void* p) {
    uint32_t a;
    asm("{ .reg .u64 t; cvta.to.shared.u64 t, %1; cvt.u32.u64 %0, t; }" : "=r"(a) : "l"(p));
    return a;
}
__device__ __forceinline__ void mma16816(
    float* c, const uint32_t* a, const uint32_t* b)
{
    asm volatile(
        "mma.sync.aligned.m16n8k16.row.col.f32.f16.f16.f32 "
        "{%0,%1,%2,%3}, {%4,%5,%6,%7}, {%8,%9}, {%0,%1,%2,%3};"
        : "+f"(c[0]), "+f"(c[1]), "+f"(c[2]), "+f"(c[3])
        : "r"(a[0]), "r"(a[1]), "r"(a[2]), "r"(a[3]), "r"(b[0]), "r"(b[1]));
}
__device__ __forceinline__ void ldsm_x4(uint32_t* r, uint32_t addr)
{
    asm volatile("ldmatrix.sync.aligned.m8n8.x4.shared.b16 {%0,%1,%2,%3}, [%4];"
                 : "=r"(r[0]), "=r"(r[1]), "=r"(r[2]), "=r"(r[3]) : "r"(addr));
}
__device__ __forceinline__ void ldsm_x4_t(uint32_t* r, uint32_t addr)
{
    asm volatile("ldmatrix.sync.aligned.m8n8.x4.trans.shared.b16 {%0,%1,%2,%3}, [%4];"
                 : "=r"(r[0]), "=r"(r[1]), "=r"(r[2]), "=r"(r[3]) : "r"(addr));
}
__device__ __forceinline__ void cp_async16(uint32_t dst, const void* src)
{
    asm volatile("cp.async.cg.shared.global [%0], [%1], 16;" :: "r"(dst), "l"(src));
}
__device__ __forceinline__ void hilo_pack(float x0, float x1, uint32_t& h, uint32_t& l)
{
    __half h0 = __float2half_rn(x0), h1 = __float2half_rn(x1);
    __half l0 = __float2half_rn(x0 - __half2float(h0));
    __half l1 = __float2half_rn(x1 - __half2float(h1));
    __half2 H = __halves2half2(h0, h1);
    __half2 L = __halves2half2(l0, l1);
    h = *(uint32_t*)&H; l = *(uint32_t*)&L;
}

// ---------------------------------------------------------------------------
// Conversions
// ---------------------------------------------------------------------------
__global__ __launch_bounds__(256) void conv_act(
    const float* __restrict__ src, __half* __restrict__ dst)
{
    int t = blockIdx.x * blockDim.x + threadIdx.x;
    float4 v = *(const float4*)(src + (size_t)t * 4);
    __half2 a = __floats2half2_rn(v.x, v.y);
    __half2 b = __floats2half2_rn(v.z, v.w);
    *(uint32_t*)(dst + (size_t)t * 4)     = *(uint32_t*)&a;
    *(uint32_t*)(dst + (size_t)t * 4 + 2) = *(uint32_t*)&b;
}

__global__ __launch_bounds__(256) void conv_wt_all(
    const float* __restrict__ Wq, const float* __restrict__ Wk,
    const float* __restrict__ Wv, const float* __restrict__ Wo,
    __half* __restrict__ Wqkv, __half* __restrict__ Wout)
{
    __shared__ float tile[32][33];
    const int z = blockIdx.z;
    const float* W = (z == 0) ? Wq : (z == 1) ? Wk : (z == 2) ? Wv : Wo;
    __half* dst = (z < 3) ? (Wqkv + (size_t)z * D_MODEL * D_MODEL) : Wout;

    int tx = threadIdx.x & 31, ty = threadIdx.x >> 5;
    int n0 = blockIdx.x * 32, k0 = blockIdx.y * 32;
#pragma unroll
    for (int j = 0; j < 4; j++)
        tile[ty + 8*j][tx] = W[(size_t)(k0 + ty + 8*j) * D_MODEL + n0 + tx];
    __syncthreads();
#pragma unroll
    for (int j = 0; j < 4; j++) {
        int n = n0 + ty + 8*j;
        dst[(size_t)n * D_MODEL + k0 + tx] = __float2half_rn(tile[tx][ty + 8*j]);
    }
}

// ---------------------------------------------------------------------------
// Pipelined mma.sync fp16 GEMM core. K=2048.
// CTA 128x128, BK=64, 4 warps 64x64, 3-stage cp.async.
// ---------------------------------------------------------------------------
#define BKg 64
#define NCH1 (D_MODEL / BKg)            // 32
#define STAGE_BYTES 32768
#define GEMM_SMEM (3 * STAGE_BYTES)

struct GemmAcc { float a[4][8][4]; };

__device__ __forceinline__ void gemm_mainloop(
    const __half* __restrict__ A, const __half* __restrict__ B,
    int row0, int col0, GemmAcc& acc)
{
    extern __shared__ char gsm[];
    const uint32_t smem_base = smem_to_u32(gsm);
    const int tid  = threadIdx.x;
    const int wid  = tid >> 5;
    const int lane = tid & 31;
    const int warp_m = (wid & 1) * 64;
    const int warp_n = (wid >> 1) * 64;

#pragma unroll
    for (int mt = 0; mt < 4; mt++)
#pragma unroll
        for (int nt = 0; nt < 8; nt++)
#pragma unroll
            for (int i = 0; i < 4; i++) acc.a[mt][nt][i] = 0.0f;

    const __half* Abase = A + (size_t)row0 * D_MODEL;
    const __half* Bbase = B + (size_t)col0 * D_MODEL;

    auto issue_stage = [&](int kc, int s) {
        const uint32_t stA = smem_base + s * STAGE_BYTES;
        const uint32_t stB = stA + 16384;
        const __half* gA = Abase + (size_t)kc * BKg;
        const __half* gB = Bbase + (size_t)kc * BKg;
#pragma unroll
        for (int i = 0; i < 8; i++) {
            int id = tid + i * 128;
            int r = id >> 3, c = id & 7;
            uint32_t soff = r * 128 + ((c ^ (r & 7)) << 4);
            cp_async16(stA + soff, gA + (size_t)r * D_MODEL + c * 8);
            cp_async16(stB + soff, gB + (size_t)r * D_MODEL + c * 8);
        }
        asm volatile("cp.async.commit_group;" ::: "memory");
    };

    issue_stage(0, 0);
    issue_stage(1, 1);

    const int l16   = lane & 15;
    const int aCsel = lane >> 4;
    const int bRow  = (lane & 7) + ((lane & 16) >> 1);
    const int bCsel = (lane >> 3) & 1;

    for (int kc = 0; kc < NCH1; kc++) {
        if (kc + 2 < NCH1) { asm volatile("cp.async.wait_group 1;" ::: "memory"); }
        else               { asm volatile("cp.async.wait_group 0;" ::: "memory"); }
        __syncthreads();
        if (kc + 2 < NCH1) issue_stage(kc + 2, (kc + 2) % 3);

        const int s = kc % 3;
        const uint32_t stA = smem_base + s * STAGE_BYTES;
        const uint32_t stB = stA + 16384;

#pragma unroll
        for (int ks = 0; ks < 4; ks++) {
            uint32_t afrag[4][4], bfrag[8][2];
#pragma unroll
            for (int mt = 0; mt < 4; mt++) {
                int r = warp_m + mt * 16 + l16;
                int c = 2 * ks + aCsel;
                ldsm_x4(afrag[mt], stA + r * 128 + ((c ^ (r & 7)) << 4));
            }
#pragma unroll
            for (int ntp = 0; ntp < 4; ntp++) {
                int n = warp_n + ntp * 16 + bRow;
                int c = 2 * ks + bCsel;
                uint32_t q[4];
                ldsm_x4(q, stB + n * 128 + ((c ^ (n & 7)) << 4));
                bfrag[2*ntp][0] = q[0]; bfrag[2*ntp][1] = q[1];
                bfrag[2*ntp+1][0] = q[2]; bfrag[2*ntp+1][1] = q[3];
            }
#pragma unroll
            for (int mt = 0; mt < 4; mt++)
#pragma unroll
                for (int nt = 0; nt < 8; nt++)
                    mma16816(acc.a[mt][nt], afrag[mt], bfrag[nt]);
        }
    }
}

// Fused QKV projection. Q -> hi/lo; K,V -> hi only.
__global__ __launch_bounds__(128) void gemm_qkv(
    const __half* __restrict__ A, const __half* __restrict__ Wqkv,
    __half* __restrict__ Qhi, __half* __restrict__ Qlo,
    __half* __restrict__ Khi, __half* __restrict__ Vhi)
{
    const int row0 = blockIdx.y * 128;
    const int col0 = blockIdx.x * 128;
    GemmAcc acc;
    gemm_mainloop(A, Wqkv, row0, col0, acc);

    const int wid  = threadIdx.x >> 5;
    const int lane = threadIdx.x & 31;
    const int warp_m = (wid & 1) * 64;
    const int warp_n = (wid >> 1) * 64;
    const int lr  = lane >> 2;
    const int lc2 = (lane & 3) * 2;

    const int proj = col0 >> 11;                // 0=Q 1=K 2=V
    const int hh   = (col0 & 2047) >> 7;

#pragma unroll
    for (int mt = 0; mt < 4; mt++) {
        int r = row0 + warp_m + mt * 16 + lr;
        int b = r >> 11, t = r & (SEQ_LEN - 1);
        size_t base0 = ((size_t)(b * NUM_HEADS + hh) * SEQ_LEN + t) * D_HEAD;
        size_t base1 = base0 + 8 * D_HEAD;
#pragma unroll
        for (int nt = 0; nt < 8; nt++) {
            int d = warp_n + nt * 8 + lc2;
            if (proj == 0) {
                const float scale = 0.08838834764831845f;
                uint32_t h0, l0, h1, l1;
                hilo_pack(acc.a[mt][nt][0] * scale, acc.a[mt][nt][1] * scale, h0, l0);
                hilo_pack(acc.a[mt][nt][2] * scale, acc.a[mt][nt][3] * scale, h1, l1);
                *(uint32_t*)(Qhi + base0 + d) = h0;
                *(uint32_t*)(Qlo + base0 + d) = l0;
                *(uint32_t*)(Qhi + base1 + d) = h1;
                *(uint32_t*)(Qlo + base1 + d) = l1;
            } else {
                __half* dst = (proj == 1) ? Khi : Vhi;
                __half2 v0 = __floats2half2_rn(acc.a[mt][nt][0], acc.a[mt][nt][1]);
                __half2 v1 = __floats2half2_rn(acc.a[mt][nt][2], acc.a[mt][nt][3]);
                *(uint32_t*)(dst + base0 + d) = *(uint32_t*)&v0;
                *(uint32_t*)(dst + base1 + d) = *(uint32_t*)&v1;
            }
        }
    }
}

// Output projection -> fp32 d_out.
__global__ __launch_bounds__(128) void gemm_out(
    const __half* __restrict__ A, const __half* __restrict__ B,
    float* __restrict__ C)
{
    const int row0 = blockIdx.y * 128;
    const int col0 = blockIdx.x * 128;
    GemmAcc acc;
    gemm_mainloop(A, B, row0, col0, acc);

    const int wid  = threadIdx.x >> 5;
    const int lane = threadIdx.x & 31;
    const int warp_m = (wid & 1) * 64;
    const int warp_n = (wid >> 1) * 64;
    const int lr  = lane >> 2;
    const int lc2 = (lane & 3) * 2;
#pragma unroll
    for (int mt = 0; mt < 4; mt++) {
        int r = row0 + warp_m + mt * 16 + lr;
#pragma unroll
        for (int nt = 0; nt < 8; nt++) {
            int c = col0 + warp_n + nt * 8 + lc2;
            *(float2*)(C + (size_t)r * D_MODEL + c)       = make_float2(acc.a[mt][nt][0], acc.a[mt][nt][1]);
            *(float2*)(C + (size_t)(r + 8) * D_MODEL + c) = make_float2(acc.a[mt][nt][2], acc.a[mt][nt][3]);
        }
    }
}

// ---------------------------------------------------------------------------
// Tensor-core causal flash attention.
// 4 mma passes: S = Qhi·Khi + Qlo·Khi ; O += Phi·Vhi + Plo·Vhi.
// smem: Qhi 32K | Qlo 32K | 2 stages x (Khi 16K + Vhi 16K) = 128KB total.
// ---------------------------------------------------------------------------
#define BMa 128
#define BNa 64
#define KV_STAGE 32768
#define ATT_SMEM (65536 + 2 * KV_STAGE)   // 131072

__global__ __launch_bounds__(256, 1) void attn_mma(
    const __half* __restrict__ Qhi, const __half* __restrict__ Qlo,
    const __half* __restrict__ Khi, const __half* __restrict__ Vhi,
    __half* __restrict__ CTX)
{
    extern __shared__ char smemraw[];
    const uint32_t sb = smem_to_u32(smemraw);
    const int tid = threadIdx.x, wid = tid >> 5, lane = tid & 31;
    const int h  = blockIdx.x;
    const int qb = gridDim.y - 1 - blockIdx.y;   // heavy blocks first
    const int b  = blockIdx.z;
    const int warp_m = wid * 16;

    const size_t head_off = (size_t)(b * NUM_HEADS + h) * SEQ_LEN * D_HEAD;
    const uint32_t sQhi = sb, sQlo = sb + 32768;

    {
        const __half* qhg = Qhi + head_off + (size_t)qb * BMa * D_HEAD;
        const __half* qlg = Qlo + head_off + (size_t)qb * BMa * D_HEAD;
#pragma unroll
        for (int i = 0; i < 8; i++) {
            int id = tid + i * 256;
            int r = id >> 4, c = id & 15;
            uint32_t sw = (uint32_t)((c & 8) | ((c & 7) ^ (r & 7))) << 4;
            cp_async16(sQhi + r * 256 + sw, qhg + r * 128 + c * 8);
            cp_async16(sQlo + r * 256 + sw, qlg + r * 128 + c * 8);
        }
        asm volatile("cp.async.commit_group;" ::: "memory");
    }

    const int nkb = 2 * qb + 2;
    auto issue_kv = [&](int kb, int s) {
        uint32_t st = sb + 65536 + s * KV_STAGE;
        const __half* kh = Khi + head_off + (size_t)kb * BNa * D_HEAD;
        const __half* vh = Vhi + head_off + (size_t)kb * BNa * D_HEAD;
#pragma unroll
        for (int i = 0; i < 4; i++) {
            int id = tid + i * 256;
            int r = id >> 4, c = id & 15;
            uint32_t sw = (uint32_t)((c & 8) | ((c & 7) ^ (r & 7))) << 4;
            uint32_t so = r * 256 + sw;
            int go = r * 128 + c * 8;
            cp_async16(st +         so, kh + go);
            cp_async16(st + 16384 + so, vh + go);
        }
        asm volatile("cp.async.commit_group;" ::: "memory");
    };
    issue_kv(0, 0);

    float oacc[16][4];
#pragma unroll
    for (int j = 0; j < 16; j++)
#pragma unroll
        for (int i = 0; i < 4; i++) oacc[j][i] = 0.0f;
    float m0 = -1e30f, m1 = -1e30f, l0 = 0.0f, l1 = 0.0f;
    const int lr = lane >> 2, lc2 = (lane & 3) * 2;

    for (int kb = 0; kb < nkb; kb++) {
        asm volatile("cp.async.wait_group 0;" ::: "memory");
        __syncthreads();
        if (kb + 1 < nkb) issue_kv(kb + 1, (kb + 1) & 1);

        const uint32_t st = sb + 65536 + (kb & 1) * KV_STAGE;
        float sacc[8][4];
#pragma unroll
        for (int j = 0; j < 8; j++)
#pragma unroll
            for (int i = 0; i < 4; i++) sacc[j][i] = 0.0f;

        // 2 score passes: (Qhi,Khi), (Qlo,Khi)
#pragma unroll
        for (int pass = 0; pass < 2; pass++) {
            const uint32_t sQ = (pass == 1) ? sQlo : sQhi;
#pragma unroll
            for (int ks = 0; ks < 8; ks++) {
                uint32_t a[4];
                {
                    int r = warp_m + (lane & 15);
                    int c = 2 * ks + (lane >> 4);
                    uint32_t sw = (uint32_t)((c & 8) | ((c & 7) ^ (r & 7))) << 4;
                    ldsm_x4(a, sQ + r * 256 + sw);
                }
                uint32_t bf[8][2];
#pragma unroll
                for (int g4 = 0; g4 < 4; g4++) {
                    int n = g4 * 16 + (lane & 7) + ((lane & 16) >> 1);
                    int c = 2 * ks + ((lane >> 3) & 1);
                    uint32_t sw = (uint32_t)((c & 8) | ((c & 7) ^ (n & 7))) << 4;
                    uint32_t q[4];
                    ldsm_x4(q, st + n * 256 + sw);
                    bf[2*g4][0] = q[0]; bf[2*g4][1] = q[1];
                    bf[2*g4+1][0] = q[2]; bf[2*g4+1][1] = q[3];
                }
#pragma unroll
                for (int j = 0; j < 8; j++) mma16816(sacc[j], a, bf[j]);
            }
        }

        if (kb >= 2 * qb) {
            const int diag = kb * BNa - qb * BMa;
            const int ra = warp_m + lr, rb = ra + 8;
#pragma unroll
            for (int j = 0; j < 8; j++) {
                int colb = diag + 8 * j + lc2;
                if (colb     > ra) sacc[j][0] = -1e30f;
                if (colb + 1 > ra) sacc[j][1] = -1e30f;
                if (colb     > rb) sacc[j][2] = -1e30f;
                if (colb + 1 > rb) sacc[j][3] = -1e30f;
            }
        }

        float rmx0 = -1e30f, rmx1 = -1e30f;
#pragma unroll
        for (int j = 0; j < 8; j++) {
            rmx0 = fmaxf(rmx0, fmaxf(sacc[j][0], sacc[j][1]));
            rmx1 = fmaxf(rmx1, fmaxf(sacc[j][2], sacc[j][3]));
        }
        rmx0 = fmaxf(rmx0, __shfl_xor_sync(0xffffffffu, rmx0, 1));
        rmx0 = fmaxf(rmx0, __shfl_xor_sync(0xffffffffu, rmx0, 2));
        rmx1 = fmaxf(rmx1, __shfl_xor_sync(0xffffffffu, rmx1, 1));
        rmx1 = fmaxf(rmx1, __shfl_xor_sync(0xffffffffu, rmx1, 2));
        float mn0 = fmaxf(m0, rmx0), mn1 = fmaxf(m1, rmx1);
        float c0 = __expf(m0 - mn0), c1 = __expf(m1 - mn1);
        m0 = mn0; m1 = mn1;
        float ps0 = 0.0f, ps1 = 0.0f;
#pragma unroll
        for (int j = 0; j < 8; j++) {
            sacc[j][0] = __expf(sacc[j][0] - mn0); ps0 += sacc[j][0];
            sacc[j][1] = __expf(sacc[j][1] - mn0); ps0 += sacc[j][1];
            sacc[j][2] = __expf(sacc[j][2] - mn1); ps1 += sacc[j][2];
            sacc[j][3] = __expf(sacc[j][3] - mn1); ps1 += sacc[j][3];
        }
        l0 = l0 * c0 + ps0;
        l1 = l1 * c1 + ps1;
#pragma unroll
        for (int j = 0; j < 16; j++) {
            oacc[j][0] *= c0; oacc[j][1] *= c0;
            oacc[j][2] *= c1; oacc[j][3] *= c1;
        }

        // PV: O += Phi*Vhi + Plo*Vhi
        const uint32_t sV = st + 16384;
#pragma unroll
        for (int s = 0; s < 4; s++) {
            uint32_t phi[4], plo[4];
            hilo_pack(sacc[2*s][0],   sacc[2*s][1],   phi[0], plo[0]);
            hilo_pack(sacc[2*s][2],   sacc[2*s][3],   phi[1], plo[1]);
            hilo_pack(sacc[2*s+1][0], sacc[2*s+1][1], phi[2], plo[2]);
            hilo_pack(sacc[2*s+1][2], sacc[2*s+1][3], phi[3], plo[3]);

            uint32_t bv[16][2];
            const int mid = lane >> 3;
#pragma unroll
            for (int g = 0; g < 8; g++) {
                int r = s * 16 + 8 * (mid & 1) + (lane & 7);
                int c = 2 * g + (mid >> 1);
                uint32_t sw = (uint32_t)((c & 8) | ((c & 7) ^ (r & 7))) << 4;
                uint32_t q[4];
                ldsm_x4_t(q, sV + r * 256 + sw);
                bv[2*g][0] = q[0]; bv[2*g][1] = q[1];
                bv[2*g+1][0] = q[2]; bv[2*g+1][1] = q[3];
            }
#pragma unroll
            for (int j = 0; j < 16; j++) mma16816(oacc[j], phi, bv[j]);
#pragma unroll
            for (int j = 0; j < 16; j++) mma16816(oacc[j], plo, bv[j]);
        }
    }

    l0 += __shfl_xor_sync(0xffffffffu, l0, 1);
    l0 += __shfl_xor_sync(0xffffffffu, l0, 2);
    l1 += __shfl_xor_sync(0xffffffffu, l1, 1);
    l1 += __shfl_xor_sync(0xffffffffu, l1, 2);
    const float il0 = 1.0f / l0, il1 = 1.0f / l1;

    const int ra = qb * BMa + warp_m + lr;
    size_t base0 = ((size_t)(b * SEQ_LEN) + ra) * D_MODEL + h * D_HEAD;
    size_t base1 = base0 + (size_t)8 * D_MODEL;
#pragma unroll
    for (int j = 0; j < 16; j++) {
        int d = 8 * j + lc2;
        __half2 v0 = __floats2half2_rn(oacc[j][0] * il0, oacc[j][1] * il0);
        __half2 v1 = __floats2half2_rn(oacc[j][2] * il1, oacc[j][3] * il1);
        *(uint32_t*)(CTX + base0 + d) = *(uint32_t*)&v0;
        *(uint32_t*)(CTX + base1 + d) = *(uint32_t*)&v1;
    }
}

// ---------------------------------------------------------------------------
// Launch
// ---------------------------------------------------------------------------
extern "C" void kernel_launch(void* const* d_in, const int* in_sizes, int n_in,
                              void* d_out, int out_size)
{
    const float* x     = (const float*)d_in[0];
    const float* q_w   = (const float*)d_in[1];
    const float* k_w   = (const float*)d_in[2];
    const float* v_w   = (const float*)d_in[3];
    const float* w_out = (const float*)d_in[4];
    float* out = (float*)d_out;

    __half *A, *Wqkv, *Wo;
    __half *Qhi, *Qlo, *Khi, *Vhi;
    cudaGetSymbolAddress((void**)&A,    g_A);
    cudaGetSymbolAddress((void**)&Wqkv, g_Wqkv);
    cudaGetSymbolAddress((void**)&Wo,   g_Wo);
    cudaGetSymbolAddress((void**)&Qhi, g_Qhi);
    cudaGetSymbolAddress((void**)&Qlo, g_Qlo);
    cudaGetSymbolAddress((void**)&Khi, g_Khi);
    cudaGetSymbolAddress((void**)&Vhi, g_Vhi);

    cudaFuncSetAttribute(gemm_qkv, cudaFuncAttributeMaxDynamicSharedMemorySize, GEMM_SMEM);
    cudaFuncSetAttribute(gemm_out, cudaFuncAttributeMaxDynamicSharedMemorySize, GEMM_SMEM);
    cudaFuncSetAttribute(attn_mma, cudaFuncAttributeMaxDynamicSharedMemorySize, ATT_SMEM);

    // 1. weight transpose/convert + activation convert
    dim3 wgrid(D_MODEL / 32, D_MODEL / 32, 4);
    conv_wt_all<<<wgrid, 256>>>(q_w, k_w, v_w, w_out, Wqkv, Wo);
    conv_act<<<(MROWS * D_MODEL / 4) / 256, 256>>>(x, A);

    // 2. fused QKV projection
    dim3 qkvgrid(NQKV / 128, MROWS / 128);        // (48, 32)
    gemm_qkv<<<qkvgrid, 128, GEMM_SMEM>>>(A, Wqkv, Qhi, Qlo, Khi, Vhi);

    // 3. tensor-core causal attention (4 mma passes) -> fp16 ctx into A
    dim3 agrid(NUM_HEADS, SEQ_LEN / BMa, BATCH);  // (16,16,2), heavy qb first
    attn_mma<<<agrid, 256, ATT_SMEM>>>(Qhi, Qlo, Khi, Vhi, A);

    // 4. output projection
    dim3 ogrid(D_MODEL / 128, MROWS / 128);       // (16, 32)
    gemm_out<<<ogrid, 128, GEMM_SMEM>>>(A, Wo, out);
}

// round 16
// speedup vs baseline: 25.6414x; 1.1766x over previous
#include <cuda_runtime.h>
#include <cuda_fp16.h>
#include <math_constants.h>
#include <cstdint>

#define D_MODEL   2048
#define NUM_HEADS 16
#define SEQ_LEN   2048
#define BATCH     2
#define D_HEAD    128
#define MROWS     (BATCH * SEQ_LEN)     // 4096
#define NQKV      (3 * D_MODEL)

// ---------------------------------------------------------------------------
// Scratch
// ---------------------------------------------------------------------------
__device__ __half g_A[(size_t)MROWS * D_MODEL];         // x / ctx, fp16
__device__ __half g_Wqkv[(size_t)NQKV * D_MODEL];       // Wq|Wk|Wv transposed [n][k]
__device__ __half g_Wo[(size_t)D_MODEL * D_MODEL];      // W_out transposed [n][k]
#define HSZ ((size_t)BATCH * NUM_HEADS * SEQ_LEN * D_HEAD)
__device__ __half g_Qh[HSZ];                             // Q hi-only (scaled)
__device__ __half g_Kh[HSZ];                             // K hi-only
__device__ __half g_Vh[HSZ];                             // V hi-only

__device__ __forceinline__ uint32_t smem_to_u32(const void* p) {
    uint32_t a;
    asm("{ .reg .u64 t; cvta.to.shared.u64 t, %1; cvt.u32.u64 %0, t; }" : "=r"(a) : "l"(p));
    return a;
}
__device__ __forceinline__ void mma16816(
    float* c, const uint32_t* a, const uint32_t* b)
{
    asm volatile(
        "mma.sync.aligned.m16n8k16.row.col.f32.f16.f16.f32 "
        "{%0,%1,%2,%3}, {%4,%5,%6,%7}, {%8,%9}, {%0,%1,%2,%3};"
        : "+f"(c[0]), "+f"(c[1]), "+f"(c[2]), "+f"(c[3])
        : "r"(a[0]), "r"(a[1]), "r"(a[2]), "r"(a[3]), "r"(b[0]), "r"(b[1]));
}
__device__ __forceinline__ void ldsm_x4(uint32_t* r, uint32_t addr)
{
    asm volatile("ldmatrix.sync.aligned.m8n8.x4.shared.b16 {%0,%1,%2,%3}, [%4];"
                 : "=r"(r[0]), "=r"(r[1]), "=r"(r[2]), "=r"(r[3]) : "r"(addr));
}
__device__ __forceinline__ void ldsm_x4_t(uint32_t* r, uint32_t addr)
{
    asm volatile("ldmatrix.sync.aligned.m8n8.x4.trans.shared.b16 {%0,%1,%2,%3}, [%4];"
                 : "=r"(r[0]), "=r"(r[1]), "=r"(r[2]), "=r"(r[3]) : "r"(addr));
}
__device__ __forceinline__ void cp_async16(uint32_t dst, const void* src)
{
    asm volatile("cp.async.cg.shared.global [%0], [%1], 16;" :: "r"(dst), "l"(src));
}

// ---------------------------------------------------------------------------
// Conversions
// ---------------------------------------------------------------------------
__global__ __launch_bounds__(256) void conv_act(
    const float* __restrict__ src, __half* __restrict__ dst)
{
    int t = blockIdx.x * blockDim.x + threadIdx.x;
    float4 v = *(const float4*)(src + (size_t)t * 4);
    __half2 a = __floats2half2_rn(v.x, v.y);
    __half2 b = __floats2half2_rn(v.z, v.w);
    *(uint32_t*)(dst + (size_t)t * 4)     = *(uint32_t*)&a;
    *(uint32_t*)(dst + (size_t)t * 4 + 2) = *(uint32_t*)&b;
}

__global__ __launch_bounds__(256) void conv_wt_all(
    const float* __restrict__ Wq, const float* __restrict__ Wk,
    const float* __restrict__ Wv, const float* __restrict__ Wo,
    __half* __restrict__ Wqkv, __half* __restrict__ Wout)
{
    __shared__ float tile[32][33];
    const int z = blockIdx.z;
    const float* W = (z == 0) ? Wq : (z == 1) ? Wk : (z == 2) ? Wv : Wo;
    __half* dst = (z < 3) ? (Wqkv + (size_t)z * D_MODEL * D_MODEL) : Wout;

    int tx = threadIdx.x & 31, ty = threadIdx.x >> 5;
    int n0 = blockIdx.x * 32, k0 = blockIdx.y * 32;
#pragma unroll
    for (int j = 0; j < 4; j++)
        tile[ty + 8*j][tx] = W[(size_t)(k0 + ty + 8*j) * D_MODEL + n0 + tx];
    __syncthreads();
#pragma unroll
    for (int j = 0; j < 4; j++) {
        int n = n0 + ty + 8*j;
        dst[(size_t)n * D_MODEL + k0 + tx] = __float2half_rn(tile[tx][ty + 8*j]);
    }
}

// ---------------------------------------------------------------------------
// Pipelined mma.sync fp16 GEMM core. K=2048.
// CTA 128x128, BK=64, 4 warps 64x64, 3-stage cp.async.
// ---------------------------------------------------------------------------
#define BKg 64
#define NCH1 (D_MODEL / BKg)            // 32
#define STAGE_BYTES 32768
#define GEMM_SMEM (3 * STAGE_BYTES)

struct GemmAcc { float a[4][8][4]; };

__device__ __forceinline__ void gemm_mainloop(
    const __half* __restrict__ A, const __half* __restrict__ B,
    int row0, int col0, GemmAcc& acc)
{
    extern __shared__ char gsm[];
    const uint32_t smem_base = smem_to_u32(gsm);
    const int tid  = threadIdx.x;
    const int wid  = tid >> 5;
    const int lane = tid & 31;
    const int warp_m = (wid & 1) * 64;
    const int warp_n = (wid >> 1) * 64;

#pragma unroll
    for (int mt = 0; mt < 4; mt++)
#pragma unroll
        for (int nt = 0; nt < 8; nt++)
#pragma unroll
            for (int i = 0; i < 4; i++) acc.a[mt][nt][i] = 0.0f;

    const __half* Abase = A + (size_t)row0 * D_MODEL;
    const __half* Bbase = B + (size_t)col0 * D_MODEL;

    auto issue_stage = [&](int kc, int s) {
        const uint32_t stA = smem_base + s * STAGE_BYTES;
        const uint32_t stB = stA + 16384;
        const __half* gA = Abase + (size_t)kc * BKg;
        const __half* gB = Bbase + (size_t)kc * BKg;
#pragma unroll
        for (int i = 0; i < 8; i++) {
            int id = tid + i * 128;
            int r = id >> 3, c = id & 7;
            uint32_t soff = r * 128 + ((c ^ (r & 7)) << 4);
            cp_async16(stA + soff, gA + (size_t)r * D_MODEL + c * 8);
            cp_async16(stB + soff, gB + (size_t)r * D_MODEL + c * 8);
        }
        asm volatile("cp.async.commit_group;" ::: "memory");
    };

    issue_stage(0, 0);
    issue_stage(1, 1);

    const int l16   = lane & 15;
    const int aCsel = lane >> 4;
    const int bRow  = (lane & 7) + ((lane & 16) >> 1);
    const int bCsel = (lane >> 3) & 1;

    for (int kc = 0; kc < NCH1; kc++) {
        if (kc + 2 < NCH1) { asm volatile("cp.async.wait_group 1;" ::: "memory"); }
        else               { asm volatile("cp.async.wait_group 0;" ::: "memory"); }
        __syncthreads();
        if (kc + 2 < NCH1) issue_stage(kc + 2, (kc + 2) % 3);

        const int s = kc % 3;
        const uint32_t stA = smem_base + s * STAGE_BYTES;
        const uint32_t stB = stA + 16384;

#pragma unroll
        for (int ks = 0; ks < 4; ks++) {
            uint32_t afrag[4][4], bfrag[8][2];
#pragma unroll
            for (int mt = 0; mt < 4; mt++) {
                int r = warp_m + mt * 16 + l16;
                int c = 2 * ks + aCsel;
                ldsm_x4(afrag[mt], stA + r * 128 + ((c ^ (r & 7)) << 4));
            }
#pragma unroll
            for (int ntp = 0; ntp < 4; ntp++) {
                int n = warp_n + ntp * 16 + bRow;
                int c = 2 * ks + bCsel;
                uint32_t q[4];
                ldsm_x4(q, stB + n * 128 + ((c ^ (n & 7)) << 4));
                bfrag[2*ntp][0] = q[0]; bfrag[2*ntp][1] = q[1];
                bfrag[2*ntp+1][0] = q[2]; bfrag[2*ntp+1][1] = q[3];
            }
#pragma unroll
            for (int mt = 0; mt < 4; mt++)
#pragma unroll
                for (int nt = 0; nt < 8; nt++)
                    mma16816(acc.a[mt][nt], afrag[mt], bfrag[nt]);
        }
    }
}

// Fused QKV projection. Q (scaled), K, V -> fp16 per-head layout.
__global__ __launch_bounds__(128) void gemm_qkv(
    const __half* __restrict__ A, const __half* __restrict__ Wqkv,
    __half* __restrict__ Qh, __half* __restrict__ Kh, __half* __restrict__ Vh)
{
    const int row0 = blockIdx.y * 128;
    const int col0 = blockIdx.x * 128;
    GemmAcc acc;
    gemm_mainloop(A, Wqkv, row0, col0, acc);

    const int wid  = threadIdx.x >> 5;
    const int lane = threadIdx.x & 31;
    const int warp_m = (wid & 1) * 64;
    const int warp_n = (wid >> 1) * 64;
    const int lr  = lane >> 2;
    const int lc2 = (lane & 3) * 2;

    const int proj = col0 >> 11;                // 0=Q 1=K 2=V
    const int hh   = (col0 & 2047) >> 7;
    __half* dst = (proj == 0) ? Qh : (proj == 1) ? Kh : Vh;
    const float scale = (proj == 0) ? 0.08838834764831845f : 1.0f;

#pragma unroll
    for (int mt = 0; mt < 4; mt++) {
        int r = row0 + warp_m + mt * 16 + lr;
        int b = r >> 11, t = r & (SEQ_LEN - 1);
        size_t base0 = ((size_t)(b * NUM_HEADS + hh) * SEQ_LEN + t) * D_HEAD;
        size_t base1 = base0 + 8 * D_HEAD;
#pragma unroll
        for (int nt = 0; nt < 8; nt++) {
            int d = warp_n + nt * 8 + lc2;
            __half2 v0 = __floats2half2_rn(acc.a[mt][nt][0] * scale, acc.a[mt][nt][1] * scale);
            __half2 v1 = __floats2half2_rn(acc.a[mt][nt][2] * scale, acc.a[mt][nt][3] * scale);
            *(uint32_t*)(dst + base0 + d) = *(uint32_t*)&v0;
            *(uint32_t*)(dst + base1 + d) = *(uint32_t*)&v1;
        }
    }
}

// Output projection -> fp32 d_out.
__global__ __launch_bounds__(128) void gemm_out(
    const __half* __restrict__ A, const __half* __restrict__ B,
    float* __restrict__ C)
{
    const int row0 = blockIdx.y * 128;
    const int col0 = blockIdx.x * 128;
    GemmAcc acc;
    gemm_mainloop(A, B, row0, col0, acc);

    const int wid  = threadIdx.x >> 5;
    const int lane = threadIdx.x & 31;
    const int warp_m = (wid & 1) * 64;
    const int warp_n = (wid >> 1) * 64;
    const int lr  = lane >> 2;
    const int lc2 = (lane & 3) * 2;
#pragma unroll
    for (int mt = 0; mt < 4; mt++) {
        int r = row0 + warp_m + mt * 16 + lr;
#pragma unroll
        for (int nt = 0; nt < 8; nt++) {
            int c = col0 + warp_n + nt * 8 + lc2;
            *(float2*)(C + (size_t)r * D_MODEL + c)       = make_float2(acc.a[mt][nt][0], acc.a[mt][nt][1]);
            *(float2*)(C + (size_t)(r + 8) * D_MODEL + c) = make_float2(acc.a[mt][nt][2], acc.a[mt][nt][3]);
        }
    }
}

// ---------------------------------------------------------------------------
// Tensor-core causal flash attention, pure fp16 (2 mma passes).
// smem: Q 32K | 2 stages x (K 16K + V 16K) = 96KB total.
// ---------------------------------------------------------------------------
#define BMa 128
#define BNa 64
#define KV_STAGE 32768
#define ATT_SMEM (32768 + 2 * KV_STAGE)   // 98304

__global__ __launch_bounds__(256, 1) void attn_mma(
    const __half* __restrict__ Qh, const __half* __restrict__ Kh,
    const __half* __restrict__ Vh, __half* __restrict__ CTX)
{
    extern __shared__ char smemraw[];
    const uint32_t sb = smem_to_u32(smemraw);
    const int tid = threadIdx.x, wid = tid >> 5, lane = tid & 31;
    const int h  = blockIdx.x;
    const int qb = gridDim.y - 1 - blockIdx.y;   // heavy blocks first
    const int b  = blockIdx.z;
    const int warp_m = wid * 16;

    const size_t head_off = (size_t)(b * NUM_HEADS + h) * SEQ_LEN * D_HEAD;
    const uint32_t sQ = sb;

    {
        const __half* qg = Qh + head_off + (size_t)qb * BMa * D_HEAD;
#pragma unroll
        for (int i = 0; i < 8; i++) {
            int id = tid + i * 256;
            int r = id >> 4, c = id & 15;
            uint32_t sw = (uint32_t)((c & 8) | ((c & 7) ^ (r & 7))) << 4;
            cp_async16(sQ + r * 256 + sw, qg + r * 128 + c * 8);
        }
        asm volatile("cp.async.commit_group;" ::: "memory");
    }

    const int nkb = 2 * qb + 2;
    auto issue_kv = [&](int kb, int s) {
        uint32_t st = sb + 32768 + s * KV_STAGE;
        const __half* kh = Kh + head_off + (size_t)kb * BNa * D_HEAD;
        const __half* vh = Vh + head_off + (size_t)kb * BNa * D_HEAD;
#pragma unroll
        for (int i = 0; i < 4; i++) {
            int id = tid + i * 256;
            int r = id >> 4, c = id & 15;
            uint32_t sw = (uint32_t)((c & 8) | ((c & 7) ^ (r & 7))) << 4;
            uint32_t so = r * 256 + sw;
            int go = r * 128 + c * 8;
            cp_async16(st +         so, kh + go);
            cp_async16(st + 16384 + so, vh + go);
        }
        asm volatile("cp.async.commit_group;" ::: "memory");
    };
    issue_kv(0, 0);

    float oacc[16][4];
#pragma unroll
    for (int j = 0; j < 16; j++)
#pragma unroll
        for (int i = 0; i < 4; i++) oacc[j][i] = 0.0f;
    float m0 = -1e30f, m1 = -1e30f, l0 = 0.0f, l1 = 0.0f;
    const int lr = lane >> 2, lc2 = (lane & 3) * 2;

    for (int kb = 0; kb < nkb; kb++) {
        asm volatile("cp.async.wait_group 0;" ::: "memory");
        __syncthreads();
        if (kb + 1 < nkb) issue_kv(kb + 1, (kb + 1) & 1);

        const uint32_t st = sb + 32768 + (kb & 1) * KV_STAGE;
        float sacc[8][4];
#pragma unroll
        for (int j = 0; j < 8; j++)
#pragma unroll
            for (int i = 0; i < 4; i++) sacc[j][i] = 0.0f;

        // score pass: S = Qh · Kh^T
#pragma unroll
        for (int ks = 0; ks < 8; ks++) {
            uint32_t a[4];
            {
                int r = warp_m + (lane & 15);
                int c = 2 * ks + (lane >> 4);
                uint32_t sw = (uint32_t)((c & 8) | ((c & 7) ^ (r & 7))) << 4;
                ldsm_x4(a, sQ + r * 256 + sw);
            }
            uint32_t bf[8][2];
#pragma unroll
            for (int g4 = 0; g4 < 4; g4++) {
                int n = g4 * 16 + (lane & 7) + ((lane & 16) >> 1);
                int c = 2 * ks + ((lane >> 3) & 1);
                uint32_t sw = (uint32_t)((c & 8) | ((c & 7) ^ (n & 7))) << 4;
                uint32_t q[4];
                ldsm_x4(q, st + n * 256 + sw);
                bf[2*g4][0] = q[0]; bf[2*g4][1] = q[1];
                bf[2*g4+1][0] = q[2]; bf[2*g4+1][1] = q[3];
            }
#pragma unroll
            for (int j = 0; j < 8; j++) mma16816(sacc[j], a, bf[j]);
        }

        if (kb >= 2 * qb) {
            const int diag = kb * BNa - qb * BMa;
            const int ra = warp_m + lr, rb = ra + 8;
#pragma unroll
            for (int j = 0; j < 8; j++) {
                int colb = diag + 8 * j + lc2;
                if (colb     > ra) sacc[j][0] = -1e30f;
                if (colb + 1 > ra) sacc[j][1] = -1e30f;
                if (colb     > rb) sacc[j][2] = -1e30f;
                if (colb + 1 > rb) sacc[j][3] = -1e30f;
            }
        }

        float rmx0 = -1e30f, rmx1 = -1e30f;
#pragma unroll
        for (int j = 0; j < 8; j++) {
            rmx0 = fmaxf(rmx0, fmaxf(sacc[j][0], sacc[j][1]));
            rmx1 = fmaxf(rmx1, fmaxf(sacc[j][2], sacc[j][3]));
        }
        rmx0 = fmaxf(rmx0, __shfl_xor_sync(0xffffffffu, rmx0, 1));
        rmx0 = fmaxf(rmx0, __shfl_xor_sync(0xffffffffu, rmx0, 2));
        rmx1 = fmaxf(rmx1, __shfl_xor_sync(0xffffffffu, rmx1, 1));
        rmx1 = fmaxf(rmx1, __shfl_xor_sync(0xffffffffu, rmx1, 2));
        float mn0 = fmaxf(m0, rmx0), mn1 = fmaxf(m1, rmx1);
        float c0 = __expf(m0 - mn0), c1 = __expf(m1 - mn1);
        m0 = mn0; m1 = mn1;
        float ps0 = 0.0f, ps1 = 0.0f;
#pragma unroll
        for (int j = 0; j < 8; j++) {
            sacc[j][0] = __expf(sacc[j][0] - mn0); ps0 += sacc[j][0];
            sacc[j][1] = __expf(sacc[j][1] - mn0); ps0 += sacc[j][1];
            sacc[j][2] = __expf(sacc[j][2] - mn1); ps1 += sacc[j][2];
            sacc[j][3] = __expf(sacc[j][3] - mn1); ps1 += sacc[j][3];
        }
        l0 = l0 * c0 + ps0;
        l1 = l1 * c1 + ps1;
#pragma unroll
        for (int j = 0; j < 16; j++) {
            oacc[j][0] *= c0; oacc[j][1] *= c0;
            oacc[j][2] *= c1; oacc[j][3] *= c1;
        }

        // PV: O += P · V (P in fp16)
        const uint32_t sV = st + 16384;
#pragma unroll
        for (int s = 0; s < 4; s++) {
            uint32_t pfrag[4];
            {
                __half2 p0 = __floats2half2_rn(sacc[2*s][0],   sacc[2*s][1]);
                __half2 p1 = __floats2half2_rn(sacc[2*s][2],   sacc[2*s][3]);
                __half2 p2 = __floats2half2_rn(sacc[2*s+1][0], sacc[2*s+1][1]);
                __half2 p3 = __floats2half2_rn(sacc[2*s+1][2], sacc[2*s+1][3]);
                pfrag[0] = *(uint32_t*)&p0; pfrag[1] = *(uint32_t*)&p1;
                pfrag[2] = *(uint32_t*)&p2; pfrag[3] = *(uint32_t*)&p3;
            }
            uint32_t bv[16][2];
            const int mid = lane >> 3;
#pragma unroll
            for (int g = 0; g < 8; g++) {
                int r = s * 16 + 8 * (mid & 1) + (lane & 7);
                int c = 2 * g + (mid >> 1);
                uint32_t sw = (uint32_t)((c & 8) | ((c & 7) ^ (r & 7))) << 4;
                uint32_t q[4];
                ldsm_x4_t(q, sV + r * 256 + sw);
                bv[2*g][0] = q[0]; bv[2*g][1] = q[1];
                bv[2*g+1][0] = q[2]; bv[2*g+1][1] = q[3];
            }
#pragma unroll
            for (int j = 0; j < 16; j++) mma16816(oacc[j], pfrag, bv[j]);
        }
    }

    l0 += __shfl_xor_sync(0xffffffffu, l0, 1);
    l0 += __shfl_xor_sync(0xffffffffu, l0, 2);
    l1 += __shfl_xor_sync(0xffffffffu, l1, 1);
    l1 += __shfl_xor_sync(0xffffffffu, l1, 2);
    const float il0 = 1.0f / l0, il1 = 1.0f / l1;

    const int ra = qb * BMa + warp_m + lr;
    size_t base0 = ((size_t)(b * SEQ_LEN) + ra) * D_MODEL + h * D_HEAD;
    size_t base1 = base0 + (size_t)8 * D_MODEL;
#pragma unroll
    for (int j = 0; j < 16; j++) {
        int d = 8 * j + lc2;
        __half2 v0 = __floats2half2_rn(oacc[j][0] * il0, oacc[j][1] * il0);
        __half2 v1 = __floats2half2_rn(oacc[j][2] * il1, oacc[j][3] * il1);
        *(uint32_t*)(CTX + base0 + d) = *(uint32_t*)&v0;
        *(uint32_t*)(CTX + base1 + d) = *(uint32_t*)&v1;
    }
}

// ---------------------------------------------------------------------------
// Launch
// ---------------------------------------------------------------------------
extern "C" void kernel_launch(void* const* d_in, const int* in_sizes, int n_in,
                              void* d_out, int out_size)
{
    const float* x     = (const float*)d_in[0];
    const float* q_w   = (const float*)d_in[1];
    const float* k_w   = (const float*)d_in[2];
    const float* v_w   = (const float*)d_in[3];
    const float* w_out = (const float*)d_in[4];
    float* out = (float*)d_out;

    __half *A, *Wqkv, *Wo, *Qh, *Kh, *Vh;
    cudaGetSymbolAddress((void**)&A,    g_A);
    cudaGetSymbolAddress((void**)&Wqkv, g_Wqkv);
    cudaGetSymbolAddress((void**)&Wo,   g_Wo);
    cudaGetSymbolAddress((void**)&Qh,   g_Qh);
    cudaGetSymbolAddress((void**)&Kh,   g_Kh);
    cudaGetSymbolAddress((void**)&Vh,   g_Vh);

    cudaFuncSetAttribute(gemm_qkv, cudaFuncAttributeMaxDynamicSharedMemorySize, GEMM_SMEM);
    cudaFuncSetAttribute(gemm_out, cudaFuncAttributeMaxDynamicSharedMemorySize, GEMM_SMEM);
    cudaFuncSetAttribute(attn_mma, cudaFuncAttributeMaxDynamicSharedMemorySize, ATT_SMEM);

    // 1. weight transpose/convert + activation convert
    dim3 wgrid(D_MODEL / 32, D_MODEL / 32, 4);
    conv_wt_all<<<wgrid, 256>>>(q_w, k_w, v_w, w_out, Wqkv, Wo);
    conv_act<<<(MROWS * D_MODEL / 4) / 256, 256>>>(x, A);

    // 2. fused QKV projection
    dim3 qkvgrid(NQKV / 128, MROWS / 128);        // (48, 32)
    gemm_qkv<<<qkvgrid, 128, GEMM_SMEM>>>(A, Wqkv, Qh, Kh, Vh);

    // 3. pure-fp16 tensor-core causal attention -> fp16 ctx into A
    dim3 agrid(NUM_HEADS, SEQ_LEN / BMa, BATCH);  // (16,16,2), heavy qb first
    attn_mma<<<agrid, 256, ATT_SMEM>>>(Qh, Kh, Vh, A);

    // 4. output projection
    dim3 ogrid(D_MODEL / 128, MROWS / 128);       // (16, 32)
    gemm_out<<<ogrid, 128, GEMM_SMEM>>>(A, Wo, out);
}